// round 1
// baseline (speedup 1.0000x reference)
#include <cuda_runtime.h>
#include <math.h>

#define B_   2
#define C_   128
#define H_   96
#define W_   320
#define HW_  30720
#define CQ_  32
#define D_   32
#define NPIX_ (B_*HW_)        // 61440
#define XEL_  (B_*C_*HW_)     // 7864320
#define NCEL_ (B_*D_*HW_)     // 1966080

// ---------------- scratch (no cudaMalloc allowed) ----------------
__device__ float  g_q[NCEL_];
__device__ float  g_k[NCEL_];
__device__ float  g_sim[NCEL_];
__device__ float  g_cost[NCEL_];
__device__ float  g_fused[XEL_];
__device__ float  g_wT[C_*C_*9];     // rc_w transposed: [ic][tap][oc]
__device__ float  g_faproj[33];      // fa_w(cost half) projected through ce_w (+bias term)
__device__ double g_part[2*512*2];   // two-stage reduction partials
__device__ float  g_stats[8];        // [mu_t0,inv_t0,mu_t1,inv_t1, mu_c0,inv_c0,mu_c1,inv_c1]
__device__ float  g_ymean[B_*C_];
__device__ float  g_yscale[B_*C_];

// ---------------- tiny weight preprocessing ----------------
__global__ void k_prep(const float* __restrict__ fa_w,
                       const float* __restrict__ ce_w,
                       const float* __restrict__ ce_b) {
    int t = threadIdx.x;
    if (t < 32) {
        float s = 0.f;
        for (int o = 0; o < C_; o++) s += fa_w[C_ + o] * ce_w[o * D_ + t];
        g_faproj[t] = s;
    } else if (t == 32) {
        float s = 0.f;
        for (int o = 0; o < C_; o++) s += fa_w[C_ + o] * ce_b[o];
        g_faproj[32] = s;
    }
}

__global__ void k_transW(const float* __restrict__ rc_w) {
    int i = blockIdx.x * 256 + threadIdx.x;
    if (i < C_ * C_ * 9) {
        int oc = i & 127;
        int tmp = i >> 7;
        int tap = tmp % 9;
        int ic  = tmp / 9;
        g_wT[i] = rc_w[(oc * C_ + ic) * 9 + tap];
    }
}

// ---------------- q / k projections (32x128 matvec per pixel) ----------------
__global__ void __launch_bounds__(256) k_qk(const float* __restrict__ t_feat,
                                            const float* __restrict__ s_feat,
                                            const float* __restrict__ q_w,
                                            const float* __restrict__ q_b,
                                            const float* __restrict__ k_w,
                                            const float* __restrict__ k_b) {
    __shared__ __align__(16) float wsh[CQ_ * C_];
    __shared__ float bsh[CQ_];
    int which = blockIdx.y;
    const float* feat = which ? s_feat : t_feat;
    const float* wm   = which ? k_w : q_w;
    const float* bv   = which ? k_b : q_b;
    float* dst        = which ? g_k : g_q;

    for (int i = threadIdx.x; i < CQ_ * C_; i += 256) wsh[i] = wm[i];
    if (threadIdx.x < CQ_) bsh[threadIdx.x] = bv[threadIdx.x];
    __syncthreads();

    int idx = blockIdx.x * 256 + threadIdx.x;
    int b = idx / HW_;
    int pix = idx % HW_;
    const float* fp = feat + (size_t)b * C_ * HW_ + pix;

    float acc[CQ_];
#pragma unroll
    for (int o = 0; o < CQ_; o++) acc[o] = 0.f;

    const float4* w4 = reinterpret_cast<const float4*>(wsh);
    for (int cc = 0; cc < C_ / 4; cc++) {
        float v0 = fp[(size_t)(4 * cc + 0) * HW_];
        float v1 = fp[(size_t)(4 * cc + 1) * HW_];
        float v2 = fp[(size_t)(4 * cc + 2) * HW_];
        float v3 = fp[(size_t)(4 * cc + 3) * HW_];
#pragma unroll
        for (int o = 0; o < CQ_; o++) {
            float4 w = w4[o * (C_ / 4) + cc];
            acc[o] += w.x * v0 + w.y * v1 + w.z * v2 + w.w * v3;
        }
    }
    float* dp = dst + (size_t)b * CQ_ * HW_ + pix;
#pragma unroll
    for (int o = 0; o < CQ_; o++) dp[(size_t)o * HW_] = acc[o] + bsh[o];
}

// ---------------- per-batch mean/var (deterministic two-stage) ----------------
__global__ void k_stats_part(const float* __restrict__ src, int perBatch) {
    __shared__ double sh1[256], sh2[256];
    int b = blockIdx.y;
    const float* p = src + (size_t)b * perBatch;
    double s1 = 0.0, s2 = 0.0;
    for (int i = blockIdx.x * 256 + threadIdx.x; i < perBatch; i += 512 * 256) {
        double v = p[i];
        s1 += v; s2 += v * v;
    }
    sh1[threadIdx.x] = s1; sh2[threadIdx.x] = s2;
    __syncthreads();
    for (int s = 128; s > 0; s >>= 1) {
        if (threadIdx.x < s) { sh1[threadIdx.x] += sh1[threadIdx.x + s]; sh2[threadIdx.x] += sh2[threadIdx.x + s]; }
        __syncthreads();
    }
    if (threadIdx.x == 0) {
        g_part[(b * 512 + blockIdx.x) * 2 + 0] = sh1[0];
        g_part[(b * 512 + blockIdx.x) * 2 + 1] = sh2[0];
    }
}

__global__ void k_stats_final(int outBase, double N, double eps) {
    __shared__ double sh1[512], sh2[512];
    int b = blockIdx.x;
    sh1[threadIdx.x] = g_part[(b * 512 + threadIdx.x) * 2 + 0];
    sh2[threadIdx.x] = g_part[(b * 512 + threadIdx.x) * 2 + 1];
    __syncthreads();
    for (int s = 256; s > 0; s >>= 1) {
        if (threadIdx.x < s) { sh1[threadIdx.x] += sh1[threadIdx.x + s]; sh2[threadIdx.x] += sh2[threadIdx.x + s]; }
        __syncthreads();
    }
    if (threadIdx.x == 0) {
        double mu  = sh1[0] / N;
        double var = sh2[0] / N - mu * mu;
        g_stats[outBase + b * 2 + 0] = (float)mu;
        g_stats[outBase + b * 2 + 1] = (float)(1.0 / sqrt(var + eps));
    }
}

// ---------------- warp volume + cosine similarity ----------------
__global__ void __launch_bounds__(W_) k_sim(const float* __restrict__ disp,
                                            const float* __restrict__ directs) {
    __shared__ float ksh[CQ_][W_];
    int h = blockIdx.x, b = blockIdx.y;
    int w = threadIdx.x;

    for (int i = threadIdx.x; i < CQ_ * W_; i += W_) {
        int c = i / W_, ww = i % W_;
        ksh[c][ww] = g_k[((size_t)(b * CQ_ + c)) * HW_ + h * W_ + ww];
    }
    __syncthreads();

    float qv[CQ_];
    float n2 = 0.f;
    const float* qp = g_q + (size_t)b * CQ_ * HW_ + h * W_ + w;
#pragma unroll
    for (int c = 0; c < CQ_; c++) { float v = qp[(size_t)c * HW_]; qv[c] = v; n2 += v * v; }
    float inv = 1.f / fmaxf(sqrtf(n2), 1e-12f);
#pragma unroll
    for (int c = 0; c < CQ_; c++) qv[c] *= inv;

    float dir = directs[b];
    float* sp = g_sim + (size_t)b * D_ * HW_ + h * W_ + w;
    for (int d = 0; d < D_; d++) {
        float pos = (float)w + disp[d] * dir * (float)(W_ - 1);
        pos = fminf(fmaxf(pos, 0.f), (float)(W_ - 1));
        int x0 = (int)floorf(pos);
        x0 = min(max(x0, 0), W_ - 1);
        int x1 = min(x0 + 1, W_ - 1);
        float t = pos - (float)x0;
        float dot = 0.f, kn2 = 0.f;
#pragma unroll
        for (int c = 0; c < CQ_; c++) {
            float g = ksh[c][x0] * (1.f - t) + ksh[c][x1] * t;
            dot += qv[c] * g;
            kn2 += g * g;
        }
        sp[(size_t)d * HW_] = dot / fmaxf(sqrtf(kn2), 1e-12f);
    }
}

// ---------------- 3x3x3 cost filtering (zero pad) ----------------
__global__ void __launch_bounds__(W_) k_cost3d(const float* __restrict__ cf_w,
                                               const float* __restrict__ cf_b) {
    __shared__ float wsh[27];
    if (threadIdx.x < 27) wsh[threadIdx.x] = cf_w[threadIdx.x];
    __syncthreads();
    int h = blockIdx.x, d = blockIdx.y, b = blockIdx.z, w = threadIdx.x;
    float s = 0.f;
#pragma unroll
    for (int kd = 0; kd < 3; kd++) {
        int dd = d + kd - 1; if (dd < 0 || dd >= D_) continue;
#pragma unroll
        for (int kh = 0; kh < 3; kh++) {
            int hh = h + kh - 1; if (hh < 0 || hh >= H_) continue;
            const float* row = g_sim + ((size_t)(b * D_ + dd) * H_ + hh) * W_;
#pragma unroll
            for (int kw = 0; kw < 3; kw++) {
                int wi = w + kw - 1; if (wi < 0 || wi >= W_) continue;
                s += wsh[kd * 9 + kh * 3 + kw] * row[wi];
            }
        }
    }
    g_cost[((size_t)(b * D_ + d) * H_ + h) * W_ + w] = s + cf_b[0];
}

// ---------------- softmax over D -> writes norm_cost into d_out ----------------
__global__ void __launch_bounds__(256) k_softmax(float* __restrict__ out) {
    int idx = blockIdx.x * 256 + threadIdx.x;
    int b = idx / HW_, pix = idx % HW_;
    const float* cp = g_cost + (size_t)b * D_ * HW_ + pix;
    float v[D_];
    float m = -1e30f;
#pragma unroll
    for (int d = 0; d < D_; d++) { v[d] = cp[(size_t)d * HW_]; m = fmaxf(m, v[d]); }
    float s = 0.f;
#pragma unroll
    for (int d = 0; d < D_; d++) { v[d] = expf(v[d] - m); s += v[d]; }
    float invs = 1.f / s;
    float* op = out + XEL_ + (size_t)b * D_ * HW_ + pix;
#pragma unroll
    for (int d = 0; d < D_; d++) op[(size_t)d * HW_] = v[d] * invs;
}

// ---------------- groupnorms + cost embed + gated fusion ----------------
__global__ void __launch_bounds__(256) k_fuse(const float* __restrict__ out_base,
                                              const float* __restrict__ t_feat,
                                              const float* __restrict__ nt_w,
                                              const float* __restrict__ nt_b,
                                              const float* __restrict__ nc_w,
                                              const float* __restrict__ nc_b,
                                              const float* __restrict__ ce_w,
                                              const float* __restrict__ ce_b,
                                              const float* __restrict__ fa_w,
                                              const float* __restrict__ fa_b) {
    __shared__ float ces[C_ * D_];
    __shared__ float fas[C_], ntw[C_], ntb[C_], ceb[C_];
    __shared__ float ncw[D_], ncb[D_], proj[33];
    for (int i = threadIdx.x; i < C_ * D_; i += 256) ces[i] = ce_w[i];
    if (threadIdx.x < C_) {
        fas[threadIdx.x] = fa_w[threadIdx.x];
        ntw[threadIdx.x] = nt_w[threadIdx.x];
        ntb[threadIdx.x] = nt_b[threadIdx.x];
        ceb[threadIdx.x] = ce_b[threadIdx.x];
    }
    if (threadIdx.x < D_) { ncw[threadIdx.x] = nc_w[threadIdx.x]; ncb[threadIdx.x] = nc_b[threadIdx.x]; }
    if (threadIdx.x < 33) proj[threadIdx.x] = g_faproj[threadIdx.x];
    __syncthreads();

    int idx = blockIdx.x * 256 + threadIdx.x;
    int b = idx / HW_, pix = idx % HW_;
    float mu_t = g_stats[b * 2 + 0], inv_t = g_stats[b * 2 + 1];
    float mu_c = g_stats[4 + b * 2 + 0], inv_c = g_stats[4 + b * 2 + 1];

    const float* ncp = out_base + XEL_ + (size_t)b * D_ * HW_ + pix;
    float cn[D_];
    float alin = fa_b[0] + proj[32];
#pragma unroll
    for (int d = 0; d < D_; d++) {
        float v = (ncp[(size_t)d * HW_] - mu_c) * inv_c * ncw[d] + ncb[d];
        cn[d] = v;
        alin += proj[d] * v;
    }
    const float* tp = t_feat + (size_t)b * C_ * HW_ + pix;
    for (int c = 0; c < C_; c++) {
        float tv = (tp[(size_t)c * HW_] - mu_t) * inv_t * ntw[c] + ntb[c];
        alin += fas[c] * tv;
    }
    float alpha = 1.f / (1.f + expf(-alin));
    float om = 1.f - alpha;

    float* fp = g_fused + (size_t)b * C_ * HW_ + pix;
    for (int o = 0; o < C_; o++) {
        float cf = ceb[o];
        const float* cw = ces + o * D_;
#pragma unroll
        for (int d = 0; d < D_; d++) cf += cw[d] * cn[d];
        float tv = (tp[(size_t)o * HW_] - mu_t) * inv_t * ntw[o] + ntb[o];
        fp[(size_t)o * HW_] = alpha * tv + om * cf;
    }
}

// ---------------- reflect-pad 3x3 conv 128->128 (register tiled) ----------------
__global__ void __launch_bounds__(128) k_conv(const float* __restrict__ rc_b,
                                              float* __restrict__ out) {
    __shared__ float sh_in[8][3][68];
    __shared__ __align__(16) float sh_w[8][9][64];
    int wt = blockIdx.x;                  // 0..4  (64-wide pixel tile)
    int h  = blockIdx.y;                  // 0..95
    int z  = blockIdx.z;                  // 0..3
    int b   = z >> 1;
    int ocb = (z & 1) * 64;
    int tid = threadIdx.x;
    int pg = tid & 7, og = tid >> 3;
    int p0 = pg * 8, oc0 = og * 4;
    int w0 = wt * 64;

    float acc[4][8];
#pragma unroll
    for (int k = 0; k < 4; k++)
#pragma unroll
        for (int p = 0; p < 8; p++) acc[k][p] = 0.f;

    for (int icc = 0; icc < 16; icc++) {
        // stage input: 8 ic x 3 rows x 66 cols, reflect-padded
        for (int i = tid; i < 8 * 3 * 66; i += 128) {
            int ic = i / 198;
            int r  = (i / 66) % 3;
            int col = i % 66;
            int wi = w0 - 1 + col;
            wi = (wi < 0) ? -wi : ((wi >= W_) ? 2 * W_ - 2 - wi : wi);
            int hi = h - 1 + r;
            hi = (hi < 0) ? -hi : ((hi >= H_) ? 2 * H_ - 2 - hi : hi);
            sh_in[ic][r][col] = g_fused[((size_t)(b * C_ + icc * 8 + ic) * H_ + hi) * W_ + wi];
        }
        // stage weights: 8 ic x 9 taps x 64 oc (coalesced from transposed layout)
        for (int i = tid; i < 8 * 9 * 64; i += 128) {
            int ic  = i / 576;
            int rem = i % 576;
            sh_w[ic][rem / 64][rem % 64] =
                g_wT[((size_t)(icc * 8 + ic) * 9 + (rem / 64)) * C_ + ocb + (rem % 64)];
        }
        __syncthreads();

#pragma unroll
        for (int ic = 0; ic < 8; ic++) {
#pragma unroll
            for (int dy = 0; dy < 3; dy++) {
                float in_reg[10];
#pragma unroll
                for (int j = 0; j < 10; j++) in_reg[j] = sh_in[ic][dy][p0 + j];
#pragma unroll
                for (int dx = 0; dx < 3; dx++) {
                    float4 wv = *reinterpret_cast<const float4*>(&sh_w[ic][dy * 3 + dx][oc0]);
#pragma unroll
                    for (int p = 0; p < 8; p++) {
                        float iv = in_reg[p + dx];
                        acc[0][p] += wv.x * iv;
                        acc[1][p] += wv.y * iv;
                        acc[2][p] += wv.z * iv;
                        acc[3][p] += wv.w * iv;
                    }
                }
            }
        }
        __syncthreads();
    }

#pragma unroll
    for (int k = 0; k < 4; k++) {
        int oc = ocb + oc0 + k;
        float bias = rc_b[oc];
        float* op = out + ((size_t)(b * C_ + oc) * H_ + h) * W_ + w0 + p0;
#pragma unroll
        for (int p = 0; p < 8; p++) op[p] = acc[k][p] + bias;
    }
}

// ---------------- squeeze-excite ----------------
__global__ void k_sepool(const float* __restrict__ out) {
    __shared__ double sh[256];
    int bc = blockIdx.x;
    const float* p = out + (size_t)bc * HW_;
    double s = 0.0;
    for (int i = threadIdx.x; i < HW_; i += 256) s += p[i];
    sh[threadIdx.x] = s;
    __syncthreads();
    for (int st = 128; st > 0; st >>= 1) {
        if (threadIdx.x < st) sh[threadIdx.x] += sh[threadIdx.x + st];
        __syncthreads();
    }
    if (threadIdx.x == 0) g_ymean[bc] = (float)(sh[0] / (double)HW_);
}

__global__ void k_se(const float* __restrict__ se_w1, const float* __restrict__ se_w2) {
    __shared__ float y1[B_][8];
    int tid = threadIdx.x;
    if (tid < B_ * 8) {
        int b = tid / 8, j = tid % 8;
        float s = 0.f;
        for (int c = 0; c < C_; c++) s += g_ymean[b * C_ + c] * se_w1[j * C_ + c];
        y1[b][j] = fmaxf(s, 0.f);
    }
    __syncthreads();
    if (tid < B_ * C_) {
        int b = tid / C_, c = tid % C_;
        float s = 0.f;
#pragma unroll
        for (int j = 0; j < 8; j++) s += y1[b][j] * se_w2[c * 8 + j];
        g_yscale[tid] = 1.f / (1.f + expf(-s));
    }
}

__global__ void __launch_bounds__(256) k_elu(float* __restrict__ out) {
    int idx = blockIdx.x * 256 + threadIdx.x;
    float v = out[idx] * g_yscale[idx / HW_];
    out[idx] = v > 0.f ? v : expm1f(v);
}

// ---------------- launch ----------------
extern "C" void kernel_launch(void* const* d_in, const int* in_sizes, int n_in,
                              void* d_out, int out_size) {
    const float* t_feat  = (const float*)d_in[0];
    const float* s_feat  = (const float*)d_in[1];
    const float* directs = (const float*)d_in[2];
    const float* disp    = (const float*)d_in[3];
    const float* q_w     = (const float*)d_in[4];
    const float* q_b     = (const float*)d_in[5];
    const float* k_w     = (const float*)d_in[6];
    const float* k_b     = (const float*)d_in[7];
    const float* cf_w    = (const float*)d_in[8];
    const float* cf_b    = (const float*)d_in[9];
    const float* nt_w    = (const float*)d_in[10];
    const float* nt_b    = (const float*)d_in[11];
    const float* nc_w    = (const float*)d_in[12];
    const float* nc_b    = (const float*)d_in[13];
    const float* ce_w    = (const float*)d_in[14];
    const float* ce_b    = (const float*)d_in[15];
    const float* fa_w    = (const float*)d_in[16];
    const float* fa_b    = (const float*)d_in[17];
    const float* rc_w    = (const float*)d_in[18];
    const float* rc_b    = (const float*)d_in[19];
    const float* se_w1   = (const float*)d_in[20];
    const float* se_w2   = (const float*)d_in[21];
    float* out = (float*)d_out;

    k_prep<<<1, 64>>>(fa_w, ce_w, ce_b);
    k_transW<<<576, 256>>>(rc_w);
    k_qk<<<dim3(NPIX_ / 256, 2), 256>>>(t_feat, s_feat, q_w, q_b, k_w, k_b);
    k_stats_part<<<dim3(512, B_), 256>>>(t_feat, C_ * HW_);
    k_stats_final<<<B_, 512>>>(0, (double)(C_ * HW_), 1e-5);
    k_sim<<<dim3(H_, B_), W_>>>(disp, directs);
    k_cost3d<<<dim3(H_, D_, B_), W_>>>(cf_w, cf_b);
    k_softmax<<<NPIX_ / 256, 256>>>(out);
    k_stats_part<<<dim3(512, B_), 256>>>(out + XEL_, D_ * HW_);
    k_stats_final<<<B_, 512>>>(4, (double)(D_ * HW_), 1e-5);
    k_fuse<<<NPIX_ / 256, 256>>>(out, t_feat, nt_w, nt_b, nc_w, nc_b, ce_w, ce_b, fa_w, fa_b);
    k_conv<<<dim3(W_ / 64, H_, 2 * B_), 128>>>(rc_b, out);
    k_sepool<<<B_ * C_, 256>>>(out);
    k_se<<<1, 256>>>(se_w1, se_w2);
    k_elu<<<XEL_ / 256, 256>>>(out);
}

// round 2
// speedup vs baseline: 1.0710x; 1.0710x over previous
#include <cuda_runtime.h>
#include <math.h>

#define B_   2
#define C_   128
#define H_   96
#define W_   320
#define HW_  30720
#define CQ_  32
#define D_   32
#define NPIX_ (B_*HW_)        // 61440
#define XEL_  (B_*C_*HW_)     // 7864320
#define NCEL_ (B_*D_*HW_)     // 1966080

typedef unsigned long long u64;

#define FMA2(d,a,b,c) asm("fma.rn.f32x2 %0, %1, %2, %3;" : "=l"(d) : "l"(a), "l"(b), "l"(c))
#define PACK2(d,lo,hi) asm("mov.b64 %0, {%1, %2};" : "=l"(d) : "r"(__float_as_uint(lo)), "r"(__float_as_uint(hi)))
#define UNPK2(lo,hi,s) do { unsigned _a,_b; asm("mov.b64 {%0, %1}, %2;" : "=r"(_a), "=r"(_b) : "l"(s)); lo=__uint_as_float(_a); hi=__uint_as_float(_b); } while(0)

// ---------------- scratch ----------------
__device__ float  g_q[NCEL_];
__device__ float  g_k[NCEL_];
__device__ float  g_sim[NCEL_];
__device__ float  g_cost[NCEL_];
__device__ float  g_fused[XEL_];
__device__ float  g_wT[C_*C_*9];     // rc_w transposed: [ic][tap][oc]
__device__ float  g_faproj[40];      // [0..31] proj_d, [32] proj.ce_b, [33] sum fa*ntb, [34] sum fa*ntw
__device__ float  g_partf[2*512*2];
__device__ float  g_stats[8];
__device__ float  g_ymean[B_*C_];
__device__ float  g_yscale[B_*C_];

// ---------------- tiny weight preprocessing ----------------
__global__ void k_prep(const float* __restrict__ fa_w,
                       const float* __restrict__ ce_w,
                       const float* __restrict__ ce_b,
                       const float* __restrict__ nt_w,
                       const float* __restrict__ nt_b) {
    int t = threadIdx.x;
    if (t < 32) {
        float s = 0.f;
        for (int o = 0; o < C_; o++) s += fa_w[C_ + o] * ce_w[o * D_ + t];
        g_faproj[t] = s;
    } else if (t == 32) {
        float s = 0.f;
        for (int o = 0; o < C_; o++) s += fa_w[C_ + o] * ce_b[o];
        g_faproj[32] = s;
    } else if (t == 33) {
        float s = 0.f;
        for (int c = 0; c < C_; c++) s += fa_w[c] * nt_b[c];
        g_faproj[33] = s;
    } else if (t == 34) {
        float s = 0.f;
        for (int c = 0; c < C_; c++) s += fa_w[c] * nt_w[c];
        g_faproj[34] = s;
    }
}

__global__ void k_transW(const float* __restrict__ rc_w) {
    int i = blockIdx.x * 256 + threadIdx.x;
    if (i < C_ * C_ * 9) {
        int oc = i & 127;
        int tmp = i >> 7;
        int tap = tmp % 9;
        int ic  = tmp / 9;
        g_wT[i] = rc_w[(oc * C_ + ic) * 9 + tap];
    }
}

// ---------------- q / k projections (packed f32x2, output pairs) ----------------
__global__ void __launch_bounds__(256) k_qk(const float* __restrict__ t_feat,
                                            const float* __restrict__ s_feat,
                                            const float* __restrict__ q_w,
                                            const float* __restrict__ q_b,
                                            const float* __restrict__ k_w,
                                            const float* __restrict__ k_b) {
    __shared__ u64 wp[C_][16];   // [c][oc_pair]  16KB
    __shared__ float bsh[CQ_];
    int which = blockIdx.y;
    const float* feat = which ? s_feat : t_feat;
    const float* wm   = which ? k_w : q_w;
    const float* bv   = which ? k_b : q_b;
    float* dst        = which ? g_k : g_q;

    for (int i = threadIdx.x; i < C_ * 16; i += 256) {
        int c = i >> 4, op = i & 15;
        float wa = wm[(2 * op) * C_ + c];
        float wb = wm[(2 * op + 1) * C_ + c];
        u64 t; PACK2(t, wa, wb);
        wp[c][op] = t;
    }
    if (threadIdx.x < CQ_) bsh[threadIdx.x] = bv[threadIdx.x];
    __syncthreads();

    int idx = blockIdx.x * 256 + threadIdx.x;
    int b = idx / HW_;
    int pix = idx % HW_;
    const float* fp = feat + (size_t)b * C_ * HW_ + pix;

    u64 acc[16];
#pragma unroll
    for (int o = 0; o < 16; o++) acc[o] = 0ULL;

#pragma unroll 4
    for (int c = 0; c < C_; c++) {
        float v = fp[(size_t)c * HW_];
        u64 v2; PACK2(v2, v, v);
        const u64* wr = wp[c];
#pragma unroll
        for (int op = 0; op < 16; op++) FMA2(acc[op], wr[op], v2, acc[op]);
    }
    float* dp = dst + (size_t)b * CQ_ * HW_ + pix;
#pragma unroll
    for (int op = 0; op < 16; op++) {
        float lo, hi; UNPK2(lo, hi, acc[op]);
        dp[(size_t)(2 * op) * HW_]     = lo + bsh[2 * op];
        dp[(size_t)(2 * op + 1) * HW_] = hi + bsh[2 * op + 1];
    }
}

// ---------------- per-batch mean/var (float partials, double final) ----------------
__global__ void __launch_bounds__(256) k_stats_part(const float* __restrict__ src, int perBatch4) {
    __shared__ float sh1[256], sh2[256];
    int b = blockIdx.y;
    const float4* p = reinterpret_cast<const float4*>(src) + (size_t)b * perBatch4;
    float s1 = 0.f, s2 = 0.f;
    for (int i = blockIdx.x * 256 + threadIdx.x; i < perBatch4; i += 512 * 256) {
        float4 v = p[i];
        s1 += (v.x + v.y) + (v.z + v.w);
        s2 += (v.x * v.x + v.y * v.y) + (v.z * v.z + v.w * v.w);
    }
    sh1[threadIdx.x] = s1; sh2[threadIdx.x] = s2;
    __syncthreads();
    for (int s = 128; s > 0; s >>= 1) {
        if (threadIdx.x < s) { sh1[threadIdx.x] += sh1[threadIdx.x + s]; sh2[threadIdx.x] += sh2[threadIdx.x + s]; }
        __syncthreads();
    }
    if (threadIdx.x == 0) {
        g_partf[(b * 512 + blockIdx.x) * 2 + 0] = sh1[0];
        g_partf[(b * 512 + blockIdx.x) * 2 + 1] = sh2[0];
    }
}

__global__ void k_stats_final(int outBase, double N, double eps) {
    __shared__ double sh1[512], sh2[512];
    int b = blockIdx.x;
    sh1[threadIdx.x] = (double)g_partf[(b * 512 + threadIdx.x) * 2 + 0];
    sh2[threadIdx.x] = (double)g_partf[(b * 512 + threadIdx.x) * 2 + 1];
    __syncthreads();
    for (int s = 256; s > 0; s >>= 1) {
        if (threadIdx.x < s) { sh1[threadIdx.x] += sh1[threadIdx.x + s]; sh2[threadIdx.x] += sh2[threadIdx.x + s]; }
        __syncthreads();
    }
    if (threadIdx.x == 0) {
        double mu  = sh1[0] / N;
        double var = sh2[0] / N - mu * mu;
        g_stats[outBase + b * 2 + 0] = (float)mu;
        g_stats[outBase + b * 2 + 1] = (float)(1.0 / sqrt(var + eps));
    }
}

// ---------------- warp volume + cosine similarity ----------------
__global__ void __launch_bounds__(W_) k_sim(const float* __restrict__ disp,
                                            const float* __restrict__ directs) {
    __shared__ float ksh[CQ_][W_];
    int h = blockIdx.x, b = blockIdx.y;
    int w = threadIdx.x;

    for (int i = threadIdx.x; i < CQ_ * W_; i += W_) {
        int c = i / W_, ww = i % W_;
        ksh[c][ww] = g_k[((size_t)(b * CQ_ + c)) * HW_ + h * W_ + ww];
    }
    __syncthreads();

    float qv[CQ_];
    float n2 = 0.f;
    const float* qp = g_q + (size_t)b * CQ_ * HW_ + h * W_ + w;
#pragma unroll
    for (int c = 0; c < CQ_; c++) { float v = qp[(size_t)c * HW_]; qv[c] = v; n2 += v * v; }
    float inv = 1.f / fmaxf(sqrtf(n2), 1e-12f);
#pragma unroll
    for (int c = 0; c < CQ_; c++) qv[c] *= inv;

    float dir = directs[b];
    float* sp = g_sim + (size_t)b * D_ * HW_ + h * W_ + w;
    for (int d = 0; d < D_; d++) {
        float pos = (float)w + disp[d] * dir * (float)(W_ - 1);
        pos = fminf(fmaxf(pos, 0.f), (float)(W_ - 1));
        int x0 = (int)floorf(pos);
        x0 = min(max(x0, 0), W_ - 1);
        int x1 = min(x0 + 1, W_ - 1);
        float t = pos - (float)x0;
        float dot = 0.f, kn2 = 0.f;
#pragma unroll
        for (int c = 0; c < CQ_; c++) {
            float g = ksh[c][x0] * (1.f - t) + ksh[c][x1] * t;
            dot += qv[c] * g;
            kn2 += g * g;
        }
        sp[(size_t)d * HW_] = dot / fmaxf(sqrtf(kn2), 1e-12f);
    }
}

// ---------------- 3x3x3 cost filtering (zero pad) ----------------
__global__ void __launch_bounds__(W_) k_cost3d(const float* __restrict__ cf_w,
                                               const float* __restrict__ cf_b) {
    __shared__ float wsh[27];
    if (threadIdx.x < 27) wsh[threadIdx.x] = cf_w[threadIdx.x];
    __syncthreads();
    int h = blockIdx.x, d = blockIdx.y, b = blockIdx.z, w = threadIdx.x;
    float s = 0.f;
#pragma unroll
    for (int kd = 0; kd < 3; kd++) {
        int dd = d + kd - 1; if (dd < 0 || dd >= D_) continue;
#pragma unroll
        for (int kh = 0; kh < 3; kh++) {
            int hh = h + kh - 1; if (hh < 0 || hh >= H_) continue;
            const float* row = g_sim + ((size_t)(b * D_ + dd) * H_ + hh) * W_;
#pragma unroll
            for (int kw = 0; kw < 3; kw++) {
                int wi = w + kw - 1; if (wi < 0 || wi >= W_) continue;
                s += wsh[kd * 9 + kh * 3 + kw] * row[wi];
            }
        }
    }
    g_cost[((size_t)(b * D_ + d) * H_ + h) * W_ + w] = s + cf_b[0];
}

// ---------------- softmax over D ----------------
__global__ void __launch_bounds__(256) k_softmax(float* __restrict__ out) {
    int idx = blockIdx.x * 256 + threadIdx.x;
    int b = idx / HW_, pix = idx % HW_;
    const float* cp = g_cost + (size_t)b * D_ * HW_ + pix;
    float v[D_];
    float m = -1e30f;
#pragma unroll
    for (int d = 0; d < D_; d++) { v[d] = cp[(size_t)d * HW_]; m = fmaxf(m, v[d]); }
    float s = 0.f;
#pragma unroll
    for (int d = 0; d < D_; d++) { v[d] = expf(v[d] - m); s += v[d]; }
    float invs = 1.f / s;
    float* op = out + XEL_ + (size_t)b * D_ * HW_ + pix;
#pragma unroll
    for (int d = 0; d < D_; d++) op[(size_t)d * HW_] = v[d] * invs;
}

// ---------------- groupnorms + cost embed + gated fusion (packed) ----------------
__global__ void __launch_bounds__(256) k_fuse(const float* __restrict__ out_base,
                                              const float* __restrict__ t_feat,
                                              const float* __restrict__ nt_w,
                                              const float* __restrict__ nt_b,
                                              const float* __restrict__ nc_w,
                                              const float* __restrict__ nc_b,
                                              const float* __restrict__ ce_w,
                                              const float* __restrict__ ce_b,
                                              const float* __restrict__ fa_w,
                                              const float* __restrict__ fa_b) {
    __shared__ u64 cep[D_][64];   // 16KB: [d][oc_pair] of ce_w pairs
    __shared__ u64 cebp[64];
    __shared__ float fw[C_], ntw[C_], ntb[C_];
    __shared__ float ncw[D_], ncb[D_], proj[40];

    for (int i = threadIdx.x; i < D_ * 64; i += 256) {
        int d = i >> 6, op = i & 63;
        u64 t; PACK2(t, ce_w[(2 * op) * D_ + d], ce_w[(2 * op + 1) * D_ + d]);
        cep[d][op] = t;
    }
    if (threadIdx.x < 64) {
        u64 t; PACK2(t, ce_b[2 * threadIdx.x], ce_b[2 * threadIdx.x + 1]);
        cebp[threadIdx.x] = t;
    }
    if (threadIdx.x < C_) {
        float f = fa_w[threadIdx.x];
        float w = nt_w[threadIdx.x];
        fw[threadIdx.x]  = f * w;
        ntw[threadIdx.x] = w;
        ntb[threadIdx.x] = nt_b[threadIdx.x];
    }
    if (threadIdx.x < D_) { ncw[threadIdx.x] = nc_w[threadIdx.x]; ncb[threadIdx.x] = nc_b[threadIdx.x]; }
    if (threadIdx.x >= 128 && threadIdx.x < 128 + 40) proj[threadIdx.x - 128] = g_faproj[threadIdx.x - 128];
    __syncthreads();

    int idx = blockIdx.x * 256 + threadIdx.x;
    int b = idx / HW_, pix = idx % HW_;
    float mu_t = g_stats[b * 2 + 0], inv_t = g_stats[b * 2 + 1];
    float mu_c = g_stats[4 + b * 2 + 0], inv_c = g_stats[4 + b * 2 + 1];

    const float* ncp = out_base + XEL_ + (size_t)b * D_ * HW_ + pix;
    u64 cnp[D_];
    float alin = fa_b[0] + proj[32] + proj[33];
#pragma unroll
    for (int d = 0; d < D_; d++) {
        float v = (ncp[(size_t)d * HW_] - mu_c) * inv_c * ncw[d] + ncb[d];
        PACK2(cnp[d], v, v);
        alin += proj[d] * v;
    }
    // alpha t-part: K + inv_t*(sum fw[c]*t[c] - mu_t*sum fw)
    const float* tp = t_feat + (size_t)b * C_ * HW_ + pix;
    float dotft = 0.f;
#pragma unroll 4
    for (int c = 0; c < C_; c++) dotft += fw[c] * tp[(size_t)c * HW_];
    alin += inv_t * (dotft - mu_t * proj[34]);

    float alpha = 1.f / (1.f + expf(-alin));
    float om = 1.f - alpha;

    float* fp = g_fused + (size_t)b * C_ * HW_ + pix;
#pragma unroll 2
    for (int op = 0; op < 64; op++) {
        u64 a2 = cebp[op];
#pragma unroll
        for (int d = 0; d < D_; d++) FMA2(a2, cep[d][op], cnp[d], a2);
        float cf0, cf1; UNPK2(cf0, cf1, a2);
        int o0 = 2 * op, o1 = 2 * op + 1;
        float tv0 = (tp[(size_t)o0 * HW_] - mu_t) * inv_t * ntw[o0] + ntb[o0];
        float tv1 = (tp[(size_t)o1 * HW_] - mu_t) * inv_t * ntw[o1] + ntb[o1];
        fp[(size_t)o0 * HW_] = alpha * tv0 + om * cf0;
        fp[(size_t)o1 * HW_] = alpha * tv1 + om * cf1;
    }
}

// ---------------- reflect-pad 3x3 conv 128->128 (f32x2 packed) ----------------
__global__ void __launch_bounds__(128) k_conv(const float* __restrict__ rc_b,
                                              float* __restrict__ out) {
    __shared__ float sh_in[8][3][68];
    __shared__ __align__(16) float sh_w[8][9][64];
    int wt = blockIdx.x;                  // 0..4  (64-wide pixel tile)
    int h  = blockIdx.y;                  // 0..95
    int z  = blockIdx.z;                  // 0..3
    int b   = z >> 1;
    int ocb = (z & 1) * 64;
    int tid = threadIdx.x;
    int pg = tid & 7, og = tid >> 3;
    int p0 = pg * 8, oc0 = og * 4;
    int w0 = wt * 64;

    u64 acc[4][4];                        // [oc][pixel-pair]
#pragma unroll
    for (int k = 0; k < 4; k++)
#pragma unroll
        for (int p = 0; p < 4; p++) acc[k][p] = 0ULL;

    for (int icc = 0; icc < 16; icc++) {
        for (int i = tid; i < 8 * 3 * 66; i += 128) {
            int ic = i / 198;
            int r  = (i / 66) % 3;
            int col = i % 66;
            int wi = w0 - 1 + col;
            wi = (wi < 0) ? -wi : ((wi >= W_) ? 2 * W_ - 2 - wi : wi);
            int hi = h - 1 + r;
            hi = (hi < 0) ? -hi : ((hi >= H_) ? 2 * H_ - 2 - hi : hi);
            sh_in[ic][r][col] = g_fused[((size_t)(b * C_ + icc * 8 + ic) * H_ + hi) * W_ + wi];
        }
        for (int i = tid; i < 8 * 9 * 64; i += 128) {
            int ic  = i / 576;
            int rem = i % 576;
            sh_w[ic][rem / 64][rem % 64] =
                g_wT[((size_t)(icc * 8 + ic) * 9 + (rem / 64)) * C_ + ocb + (rem % 64)];
        }
        __syncthreads();

#pragma unroll
        for (int ic = 0; ic < 8; ic++) {
#pragma unroll
            for (int dy = 0; dy < 3; dy++) {
                float in_reg[10];
#pragma unroll
                for (int j = 0; j < 10; j++) in_reg[j] = sh_in[ic][dy][p0 + j];
                u64 pk[9];
#pragma unroll
                for (int j = 0; j < 9; j++) PACK2(pk[j], in_reg[j], in_reg[j + 1]);
#pragma unroll
                for (int dx = 0; dx < 3; dx++) {
                    float4 wv = *reinterpret_cast<const float4*>(&sh_w[ic][dy * 3 + dx][oc0]);
                    u64 wp0, wp1, wp2, wp3;
                    PACK2(wp0, wv.x, wv.x);
                    PACK2(wp1, wv.y, wv.y);
                    PACK2(wp2, wv.z, wv.z);
                    PACK2(wp3, wv.w, wv.w);
#pragma unroll
                    for (int p = 0; p < 4; p++) {
                        u64 iv = pk[2 * p + dx];
                        FMA2(acc[0][p], wp0, iv, acc[0][p]);
                        FMA2(acc[1][p], wp1, iv, acc[1][p]);
                        FMA2(acc[2][p], wp2, iv, acc[2][p]);
                        FMA2(acc[3][p], wp3, iv, acc[3][p]);
                    }
                }
            }
        }
        __syncthreads();
    }

#pragma unroll
    for (int k = 0; k < 4; k++) {
        int oc = ocb + oc0 + k;
        float bias = rc_b[oc];
        float* op = out + ((size_t)(b * C_ + oc) * H_ + h) * W_ + w0 + p0;
#pragma unroll
        for (int p = 0; p < 4; p++) {
            float lo, hi; UNPK2(lo, hi, acc[k][p]);
            op[2 * p]     = lo + bias;
            op[2 * p + 1] = hi + bias;
        }
    }
}

// ---------------- squeeze-excite ----------------
__global__ void k_sepool(const float* __restrict__ out) {
    __shared__ float sh[256];
    int bc = blockIdx.x;
    const float4* p = reinterpret_cast<const float4*>(out + (size_t)bc * HW_);
    float s = 0.f;
    for (int i = threadIdx.x; i < HW_ / 4; i += 256) {
        float4 v = p[i];
        s += (v.x + v.y) + (v.z + v.w);
    }
    sh[threadIdx.x] = s;
    __syncthreads();
    for (int st = 128; st > 0; st >>= 1) {
        if (threadIdx.x < st) sh[threadIdx.x] += sh[threadIdx.x + st];
        __syncthreads();
    }
    if (threadIdx.x == 0) g_ymean[bc] = sh[0] / (float)HW_;
}

__global__ void k_se(const float* __restrict__ se_w1, const float* __restrict__ se_w2) {
    __shared__ float y1[B_][8];
    int tid = threadIdx.x;
    if (tid < B_ * 8) {
        int b = tid / 8, j = tid % 8;
        float s = 0.f;
        for (int c = 0; c < C_; c++) s += g_ymean[b * C_ + c] * se_w1[j * C_ + c];
        y1[b][j] = fmaxf(s, 0.f);
    }
    __syncthreads();
    if (tid < B_ * C_) {
        int b = tid / C_, c = tid % C_;
        float s = 0.f;
#pragma unroll
        for (int j = 0; j < 8; j++) s += y1[b][j] * se_w2[c * 8 + j];
        g_yscale[tid] = 1.f / (1.f + expf(-s));
    }
}

__global__ void __launch_bounds__(256) k_elu(float* __restrict__ out) {
    int idx = blockIdx.x * 256 + threadIdx.x;
    float v = out[idx] * g_yscale[idx / HW_];
    out[idx] = v > 0.f ? v : expm1f(v);
}

// ---------------- launch ----------------
extern "C" void kernel_launch(void* const* d_in, const int* in_sizes, int n_in,
                              void* d_out, int out_size) {
    const float* t_feat  = (const float*)d_in[0];
    const float* s_feat  = (const float*)d_in[1];
    const float* directs = (const float*)d_in[2];
    const float* disp    = (const float*)d_in[3];
    const float* q_w     = (const float*)d_in[4];
    const float* q_b     = (const float*)d_in[5];
    const float* k_w     = (const float*)d_in[6];
    const float* k_b     = (const float*)d_in[7];
    const float* cf_w    = (const float*)d_in[8];
    const float* cf_b    = (const float*)d_in[9];
    const float* nt_w    = (const float*)d_in[10];
    const float* nt_b    = (const float*)d_in[11];
    const float* nc_w    = (const float*)d_in[12];
    const float* nc_b    = (const float*)d_in[13];
    const float* ce_w    = (const float*)d_in[14];
    const float* ce_b    = (const float*)d_in[15];
    const float* fa_w    = (const float*)d_in[16];
    const float* fa_b    = (const float*)d_in[17];
    const float* rc_w    = (const float*)d_in[18];
    const float* rc_b    = (const float*)d_in[19];
    const float* se_w1   = (const float*)d_in[20];
    const float* se_w2   = (const float*)d_in[21];
    float* out = (float*)d_out;

    k_prep<<<1, 64>>>(fa_w, ce_w, ce_b, nt_w, nt_b);
    k_transW<<<576, 256>>>(rc_w);
    k_qk<<<dim3(NPIX_ / 256, 2), 256>>>(t_feat, s_feat, q_w, q_b, k_w, k_b);
    k_stats_part<<<dim3(512, B_), 256>>>(t_feat, C_ * HW_ / 4);
    k_stats_final<<<B_, 512>>>(0, (double)(C_ * HW_), 1e-5);
    k_sim<<<dim3(H_, B_), W_>>>(disp, directs);
    k_cost3d<<<dim3(H_, D_, B_), W_>>>(cf_w, cf_b);
    k_softmax<<<NPIX_ / 256, 256>>>(out);
    k_stats_part<<<dim3(512, B_), 256>>>(out + XEL_, D_ * HW_ / 4);
    k_stats_final<<<B_, 512>>>(4, (double)(D_ * HW_), 1e-5);
    k_fuse<<<NPIX_ / 256, 256>>>(out, t_feat, nt_w, nt_b, nc_w, nc_b, ce_w, ce_b, fa_w, fa_b);
    k_conv<<<dim3(W_ / 64, H_, 2 * B_), 128>>>(rc_b, out);
    k_sepool<<<B_ * C_, 256>>>(out);
    k_se<<<1, 256>>>(se_w1, se_w2);
    k_elu<<<XEL_ / 256, 256>>>(out);
}

// round 4
// speedup vs baseline: 2.4578x; 2.2948x over previous
#include <cuda_runtime.h>
#include <cuda_bf16.h>
#include <math.h>
#include <stdint.h>

#define B_   2
#define C_   128
#define H_   96
#define W_   320
#define HW_  30720
#define CQ_  32
#define D_   32
#define NPIX_ (B_*HW_)        // 61440
#define XEL_  (B_*C_*HW_)     // 7864320
#define NCEL_ (B_*D_*HW_)     // 1966080
#define PH_  98
#define PW_  322

typedef unsigned long long u64;

#define FMA2(d,a,b,c) asm("fma.rn.f32x2 %0, %1, %2, %3;" : "=l"(d) : "l"(a), "l"(b), "l"(c))
#define PACK2(d,lo,hi) asm("mov.b64 %0, {%1, %2};" : "=l"(d) : "r"(__float_as_uint(lo)), "r"(__float_as_uint(hi)))
#define UNPK2(lo,hi,s) do { unsigned _a,_b; asm("mov.b64 {%0, %1}, %2;" : "=r"(_a), "=r"(_b) : "l"(s)); lo=__uint_as_float(_a); hi=__uint_as_float(_b); } while(0)

// ---------------- scratch ----------------
__device__ float  g_q[NCEL_];
__device__ float  g_k[NCEL_];
__device__ float  g_sim[NCEL_];
__device__ float  g_cost[NCEL_];
__device__ __align__(16) __nv_bfloat16 g_phi[(size_t)B_*PH_*PW_*C_];
__device__ __align__(16) __nv_bfloat16 g_plo[(size_t)B_*PH_*PW_*C_];
__device__ __align__(16) unsigned short g_wBs[18][2][8192];  // pre-swizzled smem images [it][hi/lo]
__device__ float  g_faproj[40];
__device__ float  g_partf[2*512*2];
__device__ float  g_stats[8];
__device__ float  g_ymean[B_*C_];
__device__ float  g_yscale[B_*C_];

// ---------------- low-level helpers ----------------
__device__ __forceinline__ uint32_t smem_u32(const void* p) {
    uint32_t a;
    asm("{ .reg .u64 t; cvta.to.shared.u64 t, %1; cvt.u32.u64 %0, t; }" : "=r"(a) : "l"(p));
    return a;
}
#define CP16(sm, gp) asm volatile("cp.async.cg.shared.global [%0], [%1], 16;" :: "r"(sm), "l"(gp) : "memory")
#define CP_COMMIT()  asm volatile("cp.async.commit_group;" ::: "memory")
#define CP_WAIT(n)   asm volatile("cp.async.wait_group %0;" :: "n"(n) : "memory")

__device__ __forceinline__ void ldsm_x4(uint32_t* r, uint32_t addr) {
    asm volatile("ldmatrix.sync.aligned.m8n8.x4.shared.b16 {%0,%1,%2,%3}, [%4];"
        : "=r"(r[0]), "=r"(r[1]), "=r"(r[2]), "=r"(r[3]) : "r"(addr));
}
__device__ __forceinline__ void mma16816(float* d, const uint32_t* a, uint32_t b0, uint32_t b1) {
    asm volatile("mma.sync.aligned.m16n8k16.row.col.f32.bf16.bf16.f32 "
        "{%0,%1,%2,%3}, {%4,%5,%6,%7}, {%8,%9}, {%0,%1,%2,%3};"
        : "+f"(d[0]), "+f"(d[1]), "+f"(d[2]), "+f"(d[3])
        : "r"(a[0]), "r"(a[1]), "r"(a[2]), "r"(a[3]), "r"(b0), "r"(b1));
}

// ---------------- tiny weight preprocessing ----------------
__global__ void k_prep(const float* __restrict__ fa_w,
                       const float* __restrict__ ce_w,
                       const float* __restrict__ ce_b,
                       const float* __restrict__ nt_w,
                       const float* __restrict__ nt_b) {
    int t = threadIdx.x;
    if (t < 32) {
        float s = 0.f;
        for (int o = 0; o < C_; o++) s += fa_w[C_ + o] * ce_w[o * D_ + t];
        g_faproj[t] = s;
    } else if (t == 32) {
        float s = 0.f;
        for (int o = 0; o < C_; o++) s += fa_w[C_ + o] * ce_b[o];
        g_faproj[32] = s;
    } else if (t == 33) {
        float s = 0.f;
        for (int c = 0; c < C_; c++) s += fa_w[c] * nt_b[c];
        g_faproj[33] = s;
    } else if (t == 34) {
        float s = 0.f;
        for (int c = 0; c < C_; c++) s += fa_w[c] * nt_w[c];
        g_faproj[34] = s;
    }
}

// weights -> smem-image: [it = chunk*9+tap][part][oc 0..127][icl 0..63] bf16,
// 16B-chunk swizzled by (oc&7); row stride 64 bf16 = 128B
__global__ void k_prepW(const float* __restrict__ rc_w) {
    int it = blockIdx.x;      // chunk*9 + tap
    int part = blockIdx.y;    // 0=hi 1=lo
    int tap = it % 9, chunk = it / 9;
    for (int idx = threadIdx.x; idx < 8192; idx += 256) {
        int oc = idx >> 6, icl = idx & 63;
        int ic = chunk * 64 + icl;
        float w = rc_w[(oc * C_ + ic) * 9 + tap];
        __nv_bfloat16 hi = __float2bfloat16(w);
        __nv_bfloat16 lo = __float2bfloat16(w - __bfloat162float(hi));
        unsigned short v = part ? __bfloat16_as_ushort(lo) : __bfloat16_as_ushort(hi);
        int pos = oc * 64 + (((icl >> 3) ^ (oc & 7)) << 3) + (icl & 7);
        g_wBs[it][part][pos] = v;
    }
}

// ---------------- q / k projections (packed f32x2) ----------------
__global__ void __launch_bounds__(256) k_qk(const float* __restrict__ t_feat,
                                            const float* __restrict__ s_feat,
                                            const float* __restrict__ q_w,
                                            const float* __restrict__ q_b,
                                            const float* __restrict__ k_w,
                                            const float* __restrict__ k_b) {
    __shared__ u64 wp[C_][16];
    __shared__ float bsh[CQ_];
    int which = blockIdx.y;
    const float* feat = which ? s_feat : t_feat;
    const float* wm   = which ? k_w : q_w;
    const float* bv   = which ? k_b : q_b;
    float* dst        = which ? g_k : g_q;

    for (int i = threadIdx.x; i < C_ * 16; i += 256) {
        int c = i >> 4, op = i & 15;
        u64 t; PACK2(t, wm[(2 * op) * C_ + c], wm[(2 * op + 1) * C_ + c]);
        wp[c][op] = t;
    }
    if (threadIdx.x < CQ_) bsh[threadIdx.x] = bv[threadIdx.x];
    __syncthreads();

    int idx = blockIdx.x * 256 + threadIdx.x;
    int b = idx / HW_;
    int pix = idx % HW_;
    const float* fp = feat + (size_t)b * C_ * HW_ + pix;

    u64 acc[16];
#pragma unroll
    for (int o = 0; o < 16; o++) acc[o] = 0ULL;

#pragma unroll 4
    for (int c = 0; c < C_; c++) {
        float v = fp[(size_t)c * HW_];
        u64 v2; PACK2(v2, v, v);
        const u64* wr = wp[c];
#pragma unroll
        for (int op = 0; op < 16; op++) FMA2(acc[op], wr[op], v2, acc[op]);
    }
    float* dp = dst + (size_t)b * CQ_ * HW_ + pix;
#pragma unroll
    for (int op = 0; op < 16; op++) {
        float lo, hi; UNPK2(lo, hi, acc[op]);
        dp[(size_t)(2 * op) * HW_]     = lo + bsh[2 * op];
        dp[(size_t)(2 * op + 1) * HW_] = hi + bsh[2 * op + 1];
    }
}

// ---------------- per-batch mean/var ----------------
__global__ void __launch_bounds__(256) k_stats_part(const float* __restrict__ src, int perBatch4) {
    __shared__ float sh1[256], sh2[256];
    int b = blockIdx.y;
    const float4* p = reinterpret_cast<const float4*>(src) + (size_t)b * perBatch4;
    float s1 = 0.f, s2 = 0.f;
    for (int i = blockIdx.x * 256 + threadIdx.x; i < perBatch4; i += 512 * 256) {
        float4 v = p[i];
        s1 += (v.x + v.y) + (v.z + v.w);
        s2 += (v.x * v.x + v.y * v.y) + (v.z * v.z + v.w * v.w);
    }
    sh1[threadIdx.x] = s1; sh2[threadIdx.x] = s2;
    __syncthreads();
    for (int s = 128; s > 0; s >>= 1) {
        if (threadIdx.x < s) { sh1[threadIdx.x] += sh1[threadIdx.x + s]; sh2[threadIdx.x] += sh2[threadIdx.x + s]; }
        __syncthreads();
    }
    if (threadIdx.x == 0) {
        g_partf[(b * 512 + blockIdx.x) * 2 + 0] = sh1[0];
        g_partf[(b * 512 + blockIdx.x) * 2 + 1] = sh2[0];
    }
}

__global__ void k_stats_final(int outBase, double N, double eps) {
    __shared__ double sh1[512], sh2[512];
    int b = blockIdx.x;
    sh1[threadIdx.x] = (double)g_partf[(b * 512 + threadIdx.x) * 2 + 0];
    sh2[threadIdx.x] = (double)g_partf[(b * 512 + threadIdx.x) * 2 + 1];
    __syncthreads();
    for (int s = 256; s > 0; s >>= 1) {
        if (threadIdx.x < s) { sh1[threadIdx.x] += sh1[threadIdx.x + s]; sh2[threadIdx.x] += sh2[threadIdx.x + s]; }
        __syncthreads();
    }
    if (threadIdx.x == 0) {
        double mu  = sh1[0] / N;
        double var = sh2[0] / N - mu * mu;
        g_stats[outBase + b * 2 + 0] = (float)mu;
        g_stats[outBase + b * 2 + 1] = (float)(1.0 / sqrt(var + eps));
    }
}

// ---------------- warp volume + cosine similarity ----------------
__global__ void __launch_bounds__(W_) k_sim(const float* __restrict__ disp,
                                            const float* __restrict__ directs) {
    __shared__ float ksh[CQ_][W_];
    int h = blockIdx.x, b = blockIdx.y;
    int w = threadIdx.x;

    for (int i = threadIdx.x; i < CQ_ * W_; i += W_) {
        int c = i / W_, ww = i % W_;
        ksh[c][ww] = g_k[((size_t)(b * CQ_ + c)) * HW_ + h * W_ + ww];
    }
    __syncthreads();

    float qv[CQ_];
    float n2 = 0.f;
    const float* qp = g_q + (size_t)b * CQ_ * HW_ + h * W_ + w;
#pragma unroll
    for (int c = 0; c < CQ_; c++) { float v = qp[(size_t)c * HW_]; qv[c] = v; n2 += v * v; }
    float inv = 1.f / fmaxf(sqrtf(n2), 1e-12f);
#pragma unroll
    for (int c = 0; c < CQ_; c++) qv[c] *= inv;

    float dir = directs[b];
    float* sp = g_sim + (size_t)b * D_ * HW_ + h * W_ + w;
    for (int d = 0; d < D_; d++) {
        float pos = (float)w + disp[d] * dir * (float)(W_ - 1);
        pos = fminf(fmaxf(pos, 0.f), (float)(W_ - 1));
        int x0 = (int)floorf(pos);
        x0 = min(max(x0, 0), W_ - 1);
        int x1 = min(x0 + 1, W_ - 1);
        float t = pos - (float)x0;
        float dot = 0.f, kn2 = 0.f;
#pragma unroll
        for (int c = 0; c < CQ_; c++) {
            float g = ksh[c][x0] * (1.f - t) + ksh[c][x1] * t;
            dot += qv[c] * g;
            kn2 += g * g;
        }
        sp[(size_t)d * HW_] = dot / fmaxf(sqrtf(kn2), 1e-12f);
    }
}

// ---------------- 3x3x3 cost filtering (zero pad) ----------------
__global__ void __launch_bounds__(W_) k_cost3d(const float* __restrict__ cf_w,
                                               const float* __restrict__ cf_b) {
    __shared__ float wsh[27];
    if (threadIdx.x < 27) wsh[threadIdx.x] = cf_w[threadIdx.x];
    __syncthreads();
    int h = blockIdx.x, d = blockIdx.y, b = blockIdx.z, w = threadIdx.x;
    float s = 0.f;
#pragma unroll
    for (int kd = 0; kd < 3; kd++) {
        int dd = d + kd - 1; if (dd < 0 || dd >= D_) continue;
#pragma unroll
        for (int kh = 0; kh < 3; kh++) {
            int hh = h + kh - 1; if (hh < 0 || hh >= H_) continue;
            const float* row = g_sim + ((size_t)(b * D_ + dd) * H_ + hh) * W_;
#pragma unroll
            for (int kw = 0; kw < 3; kw++) {
                int wi = w + kw - 1; if (wi < 0 || wi >= W_) continue;
                s += wsh[kd * 9 + kh * 3 + kw] * row[wi];
            }
        }
    }
    g_cost[((size_t)(b * D_ + d) * H_ + h) * W_ + w] = s + cf_b[0];
}

// ---------------- softmax over D ----------------
__global__ void __launch_bounds__(256) k_softmax(float* __restrict__ out) {
    int idx = blockIdx.x * 256 + threadIdx.x;
    int b = idx / HW_, pix = idx % HW_;
    const float* cp = g_cost + (size_t)b * D_ * HW_ + pix;
    float v[D_];
    float m = -1e30f;
#pragma unroll
    for (int d = 0; d < D_; d++) { v[d] = cp[(size_t)d * HW_]; m = fmaxf(m, v[d]); }
    float s = 0.f;
#pragma unroll
    for (int d = 0; d < D_; d++) { v[d] = expf(v[d] - m); s += v[d]; }
    float invs = 1.f / s;
    float* op = out + XEL_ + (size_t)b * D_ * HW_ + pix;
#pragma unroll
    for (int d = 0; d < D_; d++) op[(size_t)d * HW_] = v[d] * invs;
}

// ---------------- groupnorms + cost embed + gated fusion -> padded NHWC bf16 hi/lo ----------------
__global__ void __launch_bounds__(256) k_fuse(const float* __restrict__ out_base,
                                              const float* __restrict__ t_feat,
                                              const float* __restrict__ nt_w,
                                              const float* __restrict__ nt_b,
                                              const float* __restrict__ nc_w,
                                              const float* __restrict__ nc_b,
                                              const float* __restrict__ ce_w,
                                              const float* __restrict__ ce_b,
                                              const float* __restrict__ fa_w,
                                              const float* __restrict__ fa_b) {
    __shared__ u64 cep[D_][64];
    __shared__ u64 cebp[64];
    __shared__ float fw[C_], ntw[C_], ntb[C_];
    __shared__ float ncw[D_], ncb[D_], proj[40];

    for (int i = threadIdx.x; i < D_ * 64; i += 256) {
        int d = i >> 6, op = i & 63;
        u64 t; PACK2(t, ce_w[(2 * op) * D_ + d], ce_w[(2 * op + 1) * D_ + d]);
        cep[d][op] = t;
    }
    if (threadIdx.x < 64) {
        u64 t; PACK2(t, ce_b[2 * threadIdx.x], ce_b[2 * threadIdx.x + 1]);
        cebp[threadIdx.x] = t;
    }
    if (threadIdx.x < C_) {
        float f = fa_w[threadIdx.x];
        float w = nt_w[threadIdx.x];
        fw[threadIdx.x]  = f * w;
        ntw[threadIdx.x] = w;
        ntb[threadIdx.x] = nt_b[threadIdx.x];
    }
    if (threadIdx.x < D_) { ncw[threadIdx.x] = nc_w[threadIdx.x]; ncb[threadIdx.x] = nc_b[threadIdx.x]; }
    if (threadIdx.x >= 128 && threadIdx.x < 128 + 40) proj[threadIdx.x - 128] = g_faproj[threadIdx.x - 128];
    __syncthreads();

    int idx = blockIdx.x * 256 + threadIdx.x;
    int b = idx / HW_, pix = idx % HW_;
    int h = pix / W_, w = pix % W_;
    float mu_t = g_stats[b * 2 + 0], inv_t = g_stats[b * 2 + 1];
    float mu_c = g_stats[4 + b * 2 + 0], inv_c = g_stats[4 + b * 2 + 1];

    const float* ncp = out_base + XEL_ + (size_t)b * D_ * HW_ + pix;
    u64 cnp[D_];
    float alin = fa_b[0] + proj[32] + proj[33];
#pragma unroll
    for (int d = 0; d < D_; d++) {
        float v = (ncp[(size_t)d * HW_] - mu_c) * inv_c * ncw[d] + ncb[d];
        PACK2(cnp[d], v, v);
        alin += proj[d] * v;
    }
    const float* tp = t_feat + (size_t)b * C_ * HW_ + pix;
    float dotft = 0.f;
#pragma unroll 4
    for (int c = 0; c < C_; c++) dotft += fw[c] * tp[(size_t)c * HW_];
    alin += inv_t * (dotft - mu_t * proj[34]);

    float alpha = 1.f / (1.f + expf(-alin));
    float om = 1.f - alpha;

    size_t pbase = ((size_t)(b * PH_ + h + 1) * PW_ + (w + 1)) * C_;
    unsigned hq[4], lq[4];
#pragma unroll 2
    for (int op = 0; op < 64; op++) {
        u64 a2 = cebp[op];
#pragma unroll
        for (int d = 0; d < D_; d++) FMA2(a2, cep[d][op], cnp[d], a2);
        float cf0, cf1; UNPK2(cf0, cf1, a2);
        int o0 = 2 * op, o1 = 2 * op + 1;
        float tv0 = (tp[(size_t)o0 * HW_] - mu_t) * inv_t * ntw[o0] + ntb[o0];
        float tv1 = (tp[(size_t)o1 * HW_] - mu_t) * inv_t * ntw[o1] + ntb[o1];
        float f0 = alpha * tv0 + om * cf0;
        float f1 = alpha * tv1 + om * cf1;
        __nv_bfloat16 h0 = __float2bfloat16(f0);
        __nv_bfloat16 h1 = __float2bfloat16(f1);
        __nv_bfloat16 l0 = __float2bfloat16(f0 - __bfloat162float(h0));
        __nv_bfloat16 l1 = __float2bfloat16(f1 - __bfloat162float(h1));
        int grp = op & 3;
        hq[grp] = (unsigned)__bfloat16_as_ushort(h0) | ((unsigned)__bfloat16_as_ushort(h1) << 16);
        lq[grp] = (unsigned)__bfloat16_as_ushort(l0) | ((unsigned)__bfloat16_as_ushort(l1) << 16);
        if (grp == 3) {
            int oc8 = 2 * (op - 3);
            *reinterpret_cast<uint4*>(&g_phi[pbase + oc8]) = make_uint4(hq[0], hq[1], hq[2], hq[3]);
            *reinterpret_cast<uint4*>(&g_plo[pbase + oc8]) = make_uint4(lq[0], lq[1], lq[2], lq[3]);
        }
    }
}

// ---------------- reflect border fill ----------------
__global__ void k_border() {
    int i = blockIdx.x;
    int b = blockIdx.y;
    int hp, wp;
    if (i < PW_)            { hp = 0;           wp = i; }
    else if (i < 2 * PW_)   { hp = PH_ - 1;     wp = i - PW_; }
    else if (i < 2 * PW_ + H_) { hp = i - 2 * PW_ + 1; wp = 0; }
    else                    { hp = i - 2 * PW_ - H_ + 1; wp = PW_ - 1; }
    int rh = hp - 1, rw = wp - 1;
    rh = (rh < 0) ? -rh : ((rh >= H_) ? 2 * H_ - 2 - rh : rh);
    rw = (rw < 0) ? -rw : ((rw >= W_) ? 2 * W_ - 2 - rw : rw);
    size_t dst = ((size_t)(b * PH_ + hp) * PW_ + wp) * C_ + threadIdx.x;
    size_t src = ((size_t)(b * PH_ + rh + 1) * PW_ + (rw + 1)) * C_ + threadIdx.x;
    g_phi[dst] = g_phi[src];
    g_plo[dst] = g_plo[src];
}

// ---------------- mma.sync implicit-GEMM conv ----------------
// smem: A patch hi [180 rows x 128B] @0, lo @23040; B double-buffered @46080:
//       + buf*32768 + part*16384   (each 16KB [128 oc][64 ic] bf16, swizzled)
#define A_HI  0
#define A_LO  23040
#define B_OFF 46080
#define CONV_SMEM 111616

__global__ void __launch_bounds__(256) k_conv_mma(const float* __restrict__ rc_b,
                                                  float* __restrict__ out) {
    extern __shared__ __align__(128) char smem[];
    uint32_t sb = smem_u32(smem);
    int tid = threadIdx.x, lane = tid & 31, wid = tid >> 5;
    int warp_m = wid & 3, warp_n = wid >> 2;

    int bx = blockIdx.x % 20;
    int by = (blockIdx.x / 20) % 12;
    int b  = blockIdx.x / 240;
    int h0 = by * 8, w0 = bx * 16;
    size_t pbase = ((size_t)(b * PH_ + h0) * PW_ + w0) * C_;

    // A ldmatrix lane geometry
    int m_loc = lane & 15, khalf_a = lane >> 4;
    int rA[2], cA[2];
#pragma unroll
    for (int mt = 0; mt < 2; mt++) {
        int m_abs = warp_m * 32 + mt * 16 + m_loc;
        rA[mt] = m_abs >> 4;
        cA[mt] = m_abs & 15;
    }
    // B ldmatrix lane geometry
    int subB = lane >> 3;
    int nl = (lane & 7) + ((subB & 2) << 2);
    int khalf_b = subB & 1;
    uint32_t bRow[4]; int bSw[4];
#pragma unroll
    for (int nb4 = 0; nb4 < 4; nb4++) {
        int oc = warp_n * 64 + nb4 * 16 + nl;
        bRow[nb4] = (uint32_t)oc * 128;
        bSw[nb4]  = oc & 7;
    }

    float acc[2][8][4];
#pragma unroll
    for (int mt = 0; mt < 2; mt++)
#pragma unroll
        for (int n = 0; n < 8; n++)
#pragma unroll
            for (int e = 0; e < 4; e++) acc[mt][n][e] = 0.f;

    // prefetch B(it=0)
    {
        const uint4* s0 = reinterpret_cast<const uint4*>(g_wBs[0][0]);
        const uint4* s1 = reinterpret_cast<const uint4*>(g_wBs[0][1]);
#pragma unroll
        for (int j = 0; j < 4; j++) {
            int idx = tid + j * 256;
            CP16(sb + B_OFF + idx * 16, s0 + idx);
            CP16(sb + B_OFF + 16384 + idx * 16, s1 + idx);
        }
        CP_COMMIT();
    }

    for (int it = 0; it < 18; it++) {
        int chunk = it / 9, tap = it % 9, buf = it & 1;
        int dy = tap / 3, dx = tap % 3;
        __syncthreads();   // previous compute done (frees buf^1 and patch)

        if (it + 1 < 18) {
            const uint4* s0 = reinterpret_cast<const uint4*>(g_wBs[it + 1][0]);
            const uint4* s1 = reinterpret_cast<const uint4*>(g_wBs[it + 1][1]);
            uint32_t d0 = sb + B_OFF + (buf ^ 1) * 32768;
#pragma unroll
            for (int j = 0; j < 4; j++) {
                int idx = tid + j * 256;
                CP16(d0 + idx * 16, s0 + idx);
                CP16(d0 + 16384 + idx * 16, s1 + idx);
            }
        }
        CP_COMMIT();

        if (tap == 0) {
            // stage A patch for this chunk: 180 rows x 64 ic (hi+lo)
            for (int i = tid; i < 1440; i += 256) {
                int row = i >> 3, ch = i & 7;
                int pr = row / 18, pc = row % 18;
                size_t g = pbase + ((size_t)pr * PW_ + pc) * C_ + chunk * 64 + ch * 8;
                uint32_t so = (uint32_t)row * 128 + ((ch ^ (row & 7)) << 4);
                *reinterpret_cast<uint4*>(smem + A_HI + so) = *reinterpret_cast<const uint4*>(&g_phi[g]);
                *reinterpret_cast<uint4*>(smem + A_LO + so) = *reinterpret_cast<const uint4*>(&g_plo[g]);
            }
        }
        CP_WAIT(1);
        __syncthreads();   // B(it) + patch visible

        uint32_t bbase = sb + B_OFF + buf * 32768;
        int rowA[2], swA[2];
#pragma unroll
        for (int mt = 0; mt < 2; mt++) {
            rowA[mt] = (rA[mt] + dy) * 18 + cA[mt] + dx;
            swA[mt]  = rowA[mt] & 7;
        }

#pragma unroll
        for (int k16 = 0; k16 < 4; k16++) {
            int chA = k16 * 2 + khalf_a;
            int chB = k16 * 2 + khalf_b;
            uint32_t ah[2][4], al[2][4];
#pragma unroll
            for (int mt = 0; mt < 2; mt++) {
                uint32_t off = (uint32_t)rowA[mt] * 128 + ((chA ^ swA[mt]) << 4);
                ldsm_x4(ah[mt], sb + A_HI + off);
                ldsm_x4(al[mt], sb + A_LO + off);
            }
            uint32_t bh[4][4], bl[4][4];
#pragma unroll
            for (int nb4 = 0; nb4 < 4; nb4++) {
                uint32_t off = bRow[nb4] + ((chB ^ bSw[nb4]) << 4);
                ldsm_x4(bh[nb4], bbase + off);
                ldsm_x4(bl[nb4], bbase + 16384 + off);
            }
#pragma unroll
            for (int mt = 0; mt < 2; mt++) {
#pragma unroll
                for (int nb4 = 0; nb4 < 4; nb4++) {
#pragma unroll
                    for (int half = 0; half < 2; half++) {
                        int n = nb4 * 2 + half;
                        uint32_t b0h = bh[nb4][half * 2], b1h = bh[nb4][half * 2 + 1];
                        mma16816(acc[mt][n], ah[mt], b0h, b1h);
                        mma16816(acc[mt][n], al[mt], b0h, b1h);
                        mma16816(acc[mt][n], ah[mt], bl[nb4][half * 2], bl[nb4][half * 2 + 1]);
                    }
                }
            }
        }
    }

    // ---------------- epilogue: transpose via smem (stride 132), coalesced stores ----------------
    float* sf = reinterpret_cast<float*>(smem);
    int rbase = lane >> 2, cpair = (lane & 3) * 2;
#pragma unroll
    for (int p = 0; p < 2; p++) {
        __syncthreads();
        if (warp_n == p) {
#pragma unroll
            for (int mt = 0; mt < 2; mt++)
#pragma unroll
                for (int nbl = 0; nbl < 8; nbl++)
#pragma unroll
                    for (int e = 0; e < 4; e++) {
                        int m   = warp_m * 32 + mt * 16 + rbase + ((e >> 1) << 3);
                        int ocl = nbl * 8 + cpair + (e & 1);
                        sf[ocl * 132 + m] = acc[mt][nbl][e];
                    }
        }
        __syncthreads();
#pragma unroll
        for (int j = 0; j < 8; j++) {
            int idx = tid + j * 256;
            int ocl = idx >> 5, q = idx & 31;
            int r = q >> 2, cc = (q & 3) * 4;
            float4 v = *reinterpret_cast<const float4*>(&sf[ocl * 132 + r * 16 + cc]);
            int oc = p * 64 + ocl;
            float bias = rc_b[oc];
            v.x += bias; v.y += bias; v.z += bias; v.w += bias;
            *reinterpret_cast<float4*>(&out[(size_t)(b * C_ + oc) * HW_ + (h0 + r) * W_ + w0 + cc]) = v;
        }
    }
}

// ---------------- squeeze-excite ----------------
__global__ void k_sepool(const float* __restrict__ out) {
    __shared__ float sh[256];
    int bc = blockIdx.x;
    const float4* p = reinterpret_cast<const float4*>(out + (size_t)bc * HW_);
    float s = 0.f;
    for (int i = threadIdx.x; i < HW_ / 4; i += 256) {
        float4 v = p[i];
        s += (v.x + v.y) + (v.z + v.w);
    }
    sh[threadIdx.x] = s;
    __syncthreads();
    for (int st = 128; st > 0; st >>= 1) {
        if (threadIdx.x < st) sh[threadIdx.x] += sh[threadIdx.x + st];
        __syncthreads();
    }
    if (threadIdx.x == 0) g_ymean[bc] = sh[0] / (float)HW_;
}

__global__ void k_se(const float* __restrict__ se_w1, const float* __restrict__ se_w2) {
    __shared__ float y1[B_][8];
    int tid = threadIdx.x;
    if (tid < B_ * 8) {
        int b = tid / 8, j = tid % 8;
        float s = 0.f;
        for (int c = 0; c < C_; c++) s += g_ymean[b * C_ + c] * se_w1[j * C_ + c];
        y1[b][j] = fmaxf(s, 0.f);
    }
    __syncthreads();
    if (tid < B_ * C_) {
        int b = tid / C_, c = tid % C_;
        float s = 0.f;
#pragma unroll
        for (int j = 0; j < 8; j++) s += y1[b][j] * se_w2[c * 8 + j];
        g_yscale[tid] = 1.f / (1.f + expf(-s));
    }
}

__global__ void __launch_bounds__(256) k_elu(float* __restrict__ out) {
    int idx = blockIdx.x * 256 + threadIdx.x;
    float v = out[idx] * g_yscale[idx / HW_];
    out[idx] = v > 0.f ? v : expm1f(v);
}

// ---------------- launch ----------------
extern "C" void kernel_launch(void* const* d_in, const int* in_sizes, int n_in,
                              void* d_out, int out_size) {
    const float* t_feat  = (const float*)d_in[0];
    const float* s_feat  = (const float*)d_in[1];
    const float* directs = (const float*)d_in[2];
    const float* disp    = (const float*)d_in[3];
    const float* q_w     = (const float*)d_in[4];
    const float* q_b     = (const float*)d_in[5];
    const float* k_w     = (const float*)d_in[6];
    const float* k_b     = (const float*)d_in[7];
    const float* cf_w    = (const float*)d_in[8];
    const float* cf_b    = (const float*)d_in[9];
    const float* nt_w    = (const float*)d_in[10];
    const float* nt_b    = (const float*)d_in[11];
    const float* nc_w    = (const float*)d_in[12];
    const float* nc_b    = (const float*)d_in[13];
    const float* ce_w    = (const float*)d_in[14];
    const float* ce_b    = (const float*)d_in[15];
    const float* fa_w    = (const float*)d_in[16];
    const float* fa_b    = (const float*)d_in[17];
    const float* rc_w    = (const float*)d_in[18];
    const float* rc_b    = (const float*)d_in[19];
    const float* se_w1   = (const float*)d_in[20];
    const float* se_w2   = (const float*)d_in[21];
    float* out = (float*)d_out;

    cudaFuncSetAttribute(k_conv_mma, cudaFuncAttributeMaxDynamicSharedMemorySize, CONV_SMEM);

    k_prep<<<1, 64>>>(fa_w, ce_w, ce_b, nt_w, nt_b);
    k_prepW<<<dim3(18, 2), 256>>>(rc_w);
    k_qk<<<dim3(NPIX_ / 256, 2), 256>>>(t_feat, s_feat, q_w, q_b, k_w, k_b);
    k_stats_part<<<dim3(512, B_), 256>>>(t_feat, C_ * HW_ / 4);
    k_stats_final<<<B_, 512>>>(0, (double)(C_ * HW_), 1e-5);
    k_sim<<<dim3(H_, B_), W_>>>(disp, directs);
    k_cost3d<<<dim3(H_, D_, B_), W_>>>(cf_w, cf_b);
    k_softmax<<<NPIX_ / 256, 256>>>(out);
    k_stats_part<<<dim3(512, B_), 256>>>(out + XEL_, D_ * HW_ / 4);
    k_stats_final<<<B_, 512>>>(4, (double)(D_ * HW_), 1e-5);
    k_fuse<<<NPIX_ / 256, 256>>>(out, t_feat, nt_w, nt_b, nc_w, nc_b, ce_w, ce_b, fa_w, fa_b);
    k_border<<<dim3(2 * PW_ + 2 * H_, B_), C_>>>();
    k_conv_mma<<<480, 256, CONV_SMEM>>>(rc_b, out);
    k_sepool<<<B_ * C_, 256>>>(out);
    k_se<<<1, 256>>>(se_w1, se_w2);
    k_elu<<<XEL_ / 256, 256>>>(out);
}

// round 5
// speedup vs baseline: 2.7770x; 1.1299x over previous
#include <cuda_runtime.h>
#include <cuda_fp16.h>
#include <math.h>
#include <stdint.h>

#define B_   2
#define C_   128
#define H_   96
#define W_   320
#define HW_  30720
#define CQ_  32
#define D_   32
#define NPIX_ (B_*HW_)        // 61440
#define XEL_  (B_*C_*HW_)     // 7864320
#define NCEL_ (B_*D_*HW_)     // 1966080
#define PH_  98
#define PW_  322

typedef unsigned long long u64;

#define FMA2(d,a,b,c) asm("fma.rn.f32x2 %0, %1, %2, %3;" : "=l"(d) : "l"(a), "l"(b), "l"(c))
#define PACK2(d,lo,hi) asm("mov.b64 %0, {%1, %2};" : "=l"(d) : "r"(__float_as_uint(lo)), "r"(__float_as_uint(hi)))
#define UNPK2(lo,hi,s) do { unsigned _a,_b; asm("mov.b64 {%0, %1}, %2;" : "=r"(_a), "=r"(_b) : "l"(s)); lo=__uint_as_float(_a); hi=__uint_as_float(_b); } while(0)

// ---------------- scratch ----------------
__device__ float  g_q[NCEL_];
__device__ float  g_k[NCEL_];
__device__ float  g_sim[NCEL_];
__device__ __align__(16) __half g_phi[(size_t)B_*PH_*PW_*C_];
__device__ __align__(16) __half g_plo[(size_t)B_*PH_*PW_*C_];
__device__ __align__(16) unsigned short g_wH[18][8192];   // pre-swizzled fp16 weight smem-images
__device__ float  g_faproj[40];
__device__ float  g_partf[2*512*2];
__device__ float  g_stats[8];
__device__ float  g_cpart[480*128];    // per-CTA conv channel sums (post-bias)
__device__ float  g_yscale[B_*C_];

// ---------------- low-level helpers ----------------
__device__ __forceinline__ uint32_t smem_u32(const void* p) {
    uint32_t a;
    asm("{ .reg .u64 t; cvta.to.shared.u64 t, %1; cvt.u32.u64 %0, t; }" : "=r"(a) : "l"(p));
    return a;
}
#define CP16(sm, gp) asm volatile("cp.async.cg.shared.global [%0], [%1], 16;" :: "r"(sm), "l"(gp) : "memory")
#define CP_COMMIT()  asm volatile("cp.async.commit_group;" ::: "memory")
#define CP_WAIT(n)   asm volatile("cp.async.wait_group %0;" :: "n"(n) : "memory")

__device__ __forceinline__ void ldsm_x4(uint32_t* r, uint32_t addr) {
    asm volatile("ldmatrix.sync.aligned.m8n8.x4.shared.b16 {%0,%1,%2,%3}, [%4];"
        : "=r"(r[0]), "=r"(r[1]), "=r"(r[2]), "=r"(r[3]) : "r"(addr));
}
__device__ __forceinline__ void mma16816h(float* d, const uint32_t* a, uint32_t b0, uint32_t b1) {
    asm volatile("mma.sync.aligned.m16n8k16.row.col.f32.f16.f16.f32 "
        "{%0,%1,%2,%3}, {%4,%5,%6,%7}, {%8,%9}, {%0,%1,%2,%3};"
        : "+f"(d[0]), "+f"(d[1]), "+f"(d[2]), "+f"(d[3])
        : "r"(a[0]), "r"(a[1]), "r"(a[2]), "r"(a[3]), "r"(b0), "r"(b1));
}

// ---------------- tiny weight preprocessing ----------------
__global__ void k_prep(const float* __restrict__ fa_w,
                       const float* __restrict__ ce_w,
                       const float* __restrict__ ce_b,
                       const float* __restrict__ nt_w,
                       const float* __restrict__ nt_b) {
    int t = threadIdx.x;
    if (t < 32) {
        float s = 0.f;
        for (int o = 0; o < C_; o++) s += fa_w[C_ + o] * ce_w[o * D_ + t];
        g_faproj[t] = s;
    } else if (t == 32) {
        float s = 0.f;
        for (int o = 0; o < C_; o++) s += fa_w[C_ + o] * ce_b[o];
        g_faproj[32] = s;
    } else if (t == 33) {
        float s = 0.f;
        for (int c = 0; c < C_; c++) s += fa_w[c] * nt_b[c];
        g_faproj[33] = s;
    } else if (t == 34) {
        float s = 0.f;
        for (int c = 0; c < C_; c++) s += fa_w[c] * nt_w[c];
        g_faproj[34] = s;
    }
}

// weights -> fp16 smem-image: [it = chunk*9+tap][oc 0..127][icl 0..63],
// 16B-chunk swizzled by (oc&7); row stride 64 halfs = 128B
__global__ void k_prepW(const float* __restrict__ rc_w) {
    int it = blockIdx.x;      // chunk*9 + tap
    int tap = it % 9, chunk = it / 9;
    for (int idx = threadIdx.x; idx < 8192; idx += 256) {
        int oc = idx >> 6, icl = idx & 63;
        int ic = chunk * 64 + icl;
        float w = rc_w[(oc * C_ + ic) * 9 + tap];
        int pos = oc * 64 + (((icl >> 3) ^ (oc & 7)) << 3) + (icl & 7);
        g_wH[it][pos] = __half_as_ushort(__float2half_rn(w));
    }
}

// ---------------- q / k projections (packed f32x2) ----------------
__global__ void __launch_bounds__(256) k_qk(const float* __restrict__ t_feat,
                                            const float* __restrict__ s_feat,
                                            const float* __restrict__ q_w,
                                            const float* __restrict__ q_b,
                                            const float* __restrict__ k_w,
                                            const float* __restrict__ k_b) {
    __shared__ u64 wp[C_][16];
    __shared__ float bsh[CQ_];
    int which = blockIdx.y;
    const float* feat = which ? s_feat : t_feat;
    const float* wm   = which ? k_w : q_w;
    const float* bv   = which ? k_b : q_b;
    float* dst        = which ? g_k : g_q;

    for (int i = threadIdx.x; i < C_ * 16; i += 256) {
        int c = i >> 4, op = i & 15;
        u64 t; PACK2(t, wm[(2 * op) * C_ + c], wm[(2 * op + 1) * C_ + c]);
        wp[c][op] = t;
    }
    if (threadIdx.x < CQ_) bsh[threadIdx.x] = bv[threadIdx.x];
    __syncthreads();

    int idx = blockIdx.x * 256 + threadIdx.x;
    int b = idx / HW_;
    int pix = idx % HW_;
    const float* fp = feat + (size_t)b * C_ * HW_ + pix;

    u64 acc[16];
#pragma unroll
    for (int o = 0; o < 16; o++) acc[o] = 0ULL;

#pragma unroll 4
    for (int c = 0; c < C_; c++) {
        float v = fp[(size_t)c * HW_];
        u64 v2; PACK2(v2, v, v);
        const u64* wr = wp[c];
#pragma unroll
        for (int op = 0; op < 16; op++) FMA2(acc[op], wr[op], v2, acc[op]);
    }
    float* dp = dst + (size_t)b * CQ_ * HW_ + pix;
#pragma unroll
    for (int op = 0; op < 16; op++) {
        float lo, hi; UNPK2(lo, hi, acc[op]);
        dp[(size_t)(2 * op) * HW_]     = lo + bsh[2 * op];
        dp[(size_t)(2 * op + 1) * HW_] = hi + bsh[2 * op + 1];
    }
}

// ---------------- per-batch mean/var ----------------
__global__ void __launch_bounds__(256) k_stats_part(const float* __restrict__ src, int perBatch4) {
    __shared__ float sh1[256], sh2[256];
    int b = blockIdx.y;
    const float4* p = reinterpret_cast<const float4*>(src) + (size_t)b * perBatch4;
    float s1 = 0.f, s2 = 0.f;
    for (int i = blockIdx.x * 256 + threadIdx.x; i < perBatch4; i += 512 * 256) {
        float4 v = p[i];
        s1 += (v.x + v.y) + (v.z + v.w);
        s2 += (v.x * v.x + v.y * v.y) + (v.z * v.z + v.w * v.w);
    }
    sh1[threadIdx.x] = s1; sh2[threadIdx.x] = s2;
    __syncthreads();
    for (int s = 128; s > 0; s >>= 1) {
        if (threadIdx.x < s) { sh1[threadIdx.x] += sh1[threadIdx.x + s]; sh2[threadIdx.x] += sh2[threadIdx.x + s]; }
        __syncthreads();
    }
    if (threadIdx.x == 0) {
        g_partf[(b * 512 + blockIdx.x) * 2 + 0] = sh1[0];
        g_partf[(b * 512 + blockIdx.x) * 2 + 1] = sh2[0];
    }
}

__global__ void k_stats_final(int outBase, double N, double eps) {
    __shared__ double sh1[512], sh2[512];
    int b = blockIdx.x;
    sh1[threadIdx.x] = (double)g_partf[(b * 512 + threadIdx.x) * 2 + 0];
    sh2[threadIdx.x] = (double)g_partf[(b * 512 + threadIdx.x) * 2 + 1];
    __syncthreads();
    for (int s = 256; s > 0; s >>= 1) {
        if (threadIdx.x < s) { sh1[threadIdx.x] += sh1[threadIdx.x + s]; sh2[threadIdx.x] += sh2[threadIdx.x + s]; }
        __syncthreads();
    }
    if (threadIdx.x == 0) {
        double mu  = sh1[0] / N;
        double var = sh2[0] / N - mu * mu;
        g_stats[outBase + b * 2 + 0] = (float)mu;
        g_stats[outBase + b * 2 + 1] = (float)(1.0 / sqrt(var + eps));
    }
}

// ---------------- warp volume + cosine similarity ----------------
__global__ void __launch_bounds__(W_) k_sim(const float* __restrict__ disp,
                                            const float* __restrict__ directs) {
    __shared__ float ksh[CQ_][W_];
    int h = blockIdx.x, b = blockIdx.y;
    int w = threadIdx.x;

    for (int i = threadIdx.x; i < CQ_ * W_; i += W_) {
        int c = i / W_, ww = i % W_;
        ksh[c][ww] = g_k[((size_t)(b * CQ_ + c)) * HW_ + h * W_ + ww];
    }
    __syncthreads();

    float qv[CQ_];
    float n2 = 0.f;
    const float* qp = g_q + (size_t)b * CQ_ * HW_ + h * W_ + w;
#pragma unroll
    for (int c = 0; c < CQ_; c++) { float v = qp[(size_t)c * HW_]; qv[c] = v; n2 += v * v; }
    float inv = 1.f / fmaxf(sqrtf(n2), 1e-12f);
#pragma unroll
    for (int c = 0; c < CQ_; c++) qv[c] *= inv;

    float dir = directs[b];
    float* sp = g_sim + (size_t)b * D_ * HW_ + h * W_ + w;
    for (int d = 0; d < D_; d++) {
        float pos = (float)w + disp[d] * dir * (float)(W_ - 1);
        pos = fminf(fmaxf(pos, 0.f), (float)(W_ - 1));
        int x0 = (int)floorf(pos);
        x0 = min(max(x0, 0), W_ - 1);
        int x1 = min(x0 + 1, W_ - 1);
        float t = pos - (float)x0;
        float dot = 0.f, kn2 = 0.f;
#pragma unroll
        for (int c = 0; c < CQ_; c++) {
            float g = ksh[c][x0] * (1.f - t) + ksh[c][x1] * t;
            dot += qv[c] * g;
            kn2 += g * g;
        }
        sp[(size_t)d * HW_] = dot / fmaxf(sqrtf(kn2), 1e-12f);
    }
}

// ---------------- fused 3x3x3 cost filtering + softmax over D ----------------
// softmax is shift-invariant => cf_b drops out entirely.
__global__ void __launch_bounds__(W_) k_costsoft(const float* __restrict__ cf_w,
                                                 float* __restrict__ out) {
    __shared__ float wsh[27];
    __shared__ float sh[2][3][PW_];
    int h = blockIdx.x, b = blockIdx.y, w = threadIdx.x;
    if (threadIdx.x < 27) wsh[threadIdx.x] = cf_w[threadIdx.x];
    if (threadIdx.x < 12) {
        int bu = threadIdx.x / 6, r = (threadIdx.x % 6) / 2, e = threadIdx.x & 1;
        sh[bu][r][e * (PW_ - 1)] = 0.f;
    }

    float c[D_];
#pragma unroll
    for (int d = 0; d < D_; d++) c[d] = 0.f;

#pragma unroll
    for (int dd = 0; dd < D_; dd++) {
        int bu = dd & 1;
#pragma unroll
        for (int r = 0; r < 3; r++) {
            int hh = h + r - 1;
            float v = 0.f;
            if (hh >= 0 && hh < H_) v = g_sim[((size_t)(b * D_ + dd) * H_ + hh) * W_ + w];
            sh[bu][r][w + 1] = v;
        }
        __syncthreads();
        float s0 = 0.f, s1 = 0.f, s2 = 0.f;
#pragma unroll
        for (int r = 0; r < 3; r++) {
            float v0 = sh[bu][r][w], v1 = sh[bu][r][w + 1], v2 = sh[bu][r][w + 2];
            s0 += wsh[r * 3 + 0] * v0 + wsh[r * 3 + 1] * v1 + wsh[r * 3 + 2] * v2;
            s1 += wsh[9 + r * 3 + 0] * v0 + wsh[9 + r * 3 + 1] * v1 + wsh[9 + r * 3 + 2] * v2;
            s2 += wsh[18 + r * 3 + 0] * v0 + wsh[18 + r * 3 + 1] * v1 + wsh[18 + r * 3 + 2] * v2;
        }
        if (dd + 1 < D_) c[dd + 1] += s0;
        c[dd] += s1;
        if (dd >= 1) c[dd - 1] += s2;
    }

    float m = -1e30f;
#pragma unroll
    for (int d = 0; d < D_; d++) m = fmaxf(m, c[d]);
    float sum = 0.f;
#pragma unroll
    for (int d = 0; d < D_; d++) { c[d] = expf(c[d] - m); sum += c[d]; }
    float invs = 1.f / sum;
    float* op = out + XEL_ + (size_t)b * D_ * HW_ + h * W_ + w;
#pragma unroll
    for (int d = 0; d < D_; d++) op[(size_t)d * HW_] = c[d] * invs;
}

// ---------------- groupnorms + cost embed + gated fusion -> padded NHWC fp16 hi/lo ----------------
__global__ void __launch_bounds__(256) k_fuse(const float* __restrict__ out_base,
                                              const float* __restrict__ t_feat,
                                              const float* __restrict__ nt_w,
                                              const float* __restrict__ nt_b,
                                              const float* __restrict__ nc_w,
                                              const float* __restrict__ nc_b,
                                              const float* __restrict__ ce_w,
                                              const float* __restrict__ ce_b,
                                              const float* __restrict__ fa_w,
                                              const float* __restrict__ fa_b) {
    __shared__ u64 cep[D_][64];
    __shared__ u64 cebp[64];
    __shared__ float fw[C_], ntw[C_], ntb[C_];
    __shared__ float ncw[D_], ncb[D_], proj[40];

    for (int i = threadIdx.x; i < D_ * 64; i += 256) {
        int d = i >> 6, op = i & 63;
        u64 t; PACK2(t, ce_w[(2 * op) * D_ + d], ce_w[(2 * op + 1) * D_ + d]);
        cep[d][op] = t;
    }
    if (threadIdx.x < 64) {
        u64 t; PACK2(t, ce_b[2 * threadIdx.x], ce_b[2 * threadIdx.x + 1]);
        cebp[threadIdx.x] = t;
    }
    if (threadIdx.x < C_) {
        float f = fa_w[threadIdx.x];
        float w = nt_w[threadIdx.x];
        fw[threadIdx.x]  = f * w;
        ntw[threadIdx.x] = w;
        ntb[threadIdx.x] = nt_b[threadIdx.x];
    }
    if (threadIdx.x < D_) { ncw[threadIdx.x] = nc_w[threadIdx.x]; ncb[threadIdx.x] = nc_b[threadIdx.x]; }
    if (threadIdx.x >= 128 && threadIdx.x < 128 + 40) proj[threadIdx.x - 128] = g_faproj[threadIdx.x - 128];
    __syncthreads();

    int idx = blockIdx.x * 256 + threadIdx.x;
    int b = idx / HW_, pix = idx % HW_;
    int h = pix / W_, w = pix % W_;
    float mu_t = g_stats[b * 2 + 0], inv_t = g_stats[b * 2 + 1];
    float mu_c = g_stats[4 + b * 2 + 0], inv_c = g_stats[4 + b * 2 + 1];

    const float* ncp = out_base + XEL_ + (size_t)b * D_ * HW_ + pix;
    u64 cnp[D_];
    float alin = fa_b[0] + proj[32] + proj[33];
#pragma unroll
    for (int d = 0; d < D_; d++) {
        float v = (ncp[(size_t)d * HW_] - mu_c) * inv_c * ncw[d] + ncb[d];
        PACK2(cnp[d], v, v);
        alin += proj[d] * v;
    }
    const float* tp = t_feat + (size_t)b * C_ * HW_ + pix;
    float dotft = 0.f;
#pragma unroll 4
    for (int c = 0; c < C_; c++) dotft += fw[c] * tp[(size_t)c * HW_];
    alin += inv_t * (dotft - mu_t * proj[34]);

    float alpha = 1.f / (1.f + expf(-alin));
    float om = 1.f - alpha;

    size_t pbase = ((size_t)(b * PH_ + h + 1) * PW_ + (w + 1)) * C_;
    unsigned hq[4], lq[4];
#pragma unroll 2
    for (int op = 0; op < 64; op++) {
        u64 a2 = cebp[op];
#pragma unroll
        for (int d = 0; d < D_; d++) FMA2(a2, cep[d][op], cnp[d], a2);
        float cf0, cf1; UNPK2(cf0, cf1, a2);
        int o0 = 2 * op, o1 = 2 * op + 1;
        float tv0 = (tp[(size_t)o0 * HW_] - mu_t) * inv_t * ntw[o0] + ntb[o0];
        float tv1 = (tp[(size_t)o1 * HW_] - mu_t) * inv_t * ntw[o1] + ntb[o1];
        float f0 = alpha * tv0 + om * cf0;
        float f1 = alpha * tv1 + om * cf1;
        __half h0 = __float2half_rn(f0);
        __half h1 = __float2half_rn(f1);
        __half l0 = __float2half_rn(f0 - __half2float(h0));
        __half l1 = __float2half_rn(f1 - __half2float(h1));
        int grp = op & 3;
        hq[grp] = (unsigned)__half_as_ushort(h0) | ((unsigned)__half_as_ushort(h1) << 16);
        lq[grp] = (unsigned)__half_as_ushort(l0) | ((unsigned)__half_as_ushort(l1) << 16);
        if (grp == 3) {
            int oc8 = 2 * (op - 3);
            *reinterpret_cast<uint4*>(&g_phi[pbase + oc8]) = make_uint4(hq[0], hq[1], hq[2], hq[3]);
            *reinterpret_cast<uint4*>(&g_plo[pbase + oc8]) = make_uint4(lq[0], lq[1], lq[2], lq[3]);
        }
    }
}

// ---------------- reflect border fill ----------------
__global__ void k_border() {
    int i = blockIdx.x;
    int b = blockIdx.y;
    int hp, wp;
    if (i < PW_)            { hp = 0;           wp = i; }
    else if (i < 2 * PW_)   { hp = PH_ - 1;     wp = i - PW_; }
    else if (i < 2 * PW_ + H_) { hp = i - 2 * PW_ + 1; wp = 0; }
    else                    { hp = i - 2 * PW_ - H_ + 1; wp = PW_ - 1; }
    int rh = hp - 1, rw = wp - 1;
    rh = (rh < 0) ? -rh : ((rh >= H_) ? 2 * H_ - 2 - rh : rh);
    rw = (rw < 0) ? -rw : ((rw >= W_) ? 2 * W_ - 2 - rw : rw);
    size_t dst = ((size_t)(b * PH_ + hp) * PW_ + wp) * C_ + threadIdx.x;
    size_t src = ((size_t)(b * PH_ + rh + 1) * PW_ + (rw + 1)) * C_ + threadIdx.x;
    g_phi[dst] = g_phi[src];
    g_plo[dst] = g_plo[src];
}

// ---------------- mma.sync implicit-GEMM conv (fp16 2-term) ----------------
// smem: A hi [180 x 128B] @0, A lo @23040; B double-buffered @46080 (16KB each)
#define A_HI  0
#define A_LO  23040
#define B_OFF 46080
#define CONV_SMEM 78848

__global__ void __launch_bounds__(256, 2) k_conv_mma(const float* __restrict__ rc_b,
                                                     float* __restrict__ out) {
    extern __shared__ __align__(128) char smem[];
    uint32_t sb = smem_u32(smem);
    int tid = threadIdx.x, lane = tid & 31, wid = tid >> 5;
    int warp_m = wid & 3, warp_n = wid >> 2;

    int bx = blockIdx.x % 20;
    int by = (blockIdx.x / 20) % 12;
    int b  = blockIdx.x / 240;
    int h0 = by * 8, w0 = bx * 16;
    size_t pbase = ((size_t)(b * PH_ + h0) * PW_ + w0) * C_;

    int m_loc = lane & 15, khalf_a = lane >> 4;
    int rA[2], cA[2];
#pragma unroll
    for (int mt = 0; mt < 2; mt++) {
        int m_abs = warp_m * 32 + mt * 16 + m_loc;
        rA[mt] = m_abs >> 4;
        cA[mt] = m_abs & 15;
    }
    int subB = lane >> 3;
    int nl = (lane & 7) + ((subB & 2) << 2);
    int khalf_b = subB & 1;
    uint32_t bRow[4]; int bSw[4];
#pragma unroll
    for (int nb4 = 0; nb4 < 4; nb4++) {
        int oc = warp_n * 64 + nb4 * 16 + nl;
        bRow[nb4] = (uint32_t)oc * 128;
        bSw[nb4]  = oc & 7;
    }

    float acc[2][8][4];
#pragma unroll
    for (int mt = 0; mt < 2; mt++)
#pragma unroll
        for (int n = 0; n < 8; n++)
#pragma unroll
            for (int e = 0; e < 4; e++) acc[mt][n][e] = 0.f;

    // prefetch B(it=0): 16KB = 1024 lines, 4 per thread
    {
        const uint4* s0 = reinterpret_cast<const uint4*>(g_wH[0]);
#pragma unroll
        for (int j = 0; j < 4; j++) {
            int idx = tid + j * 256;
            CP16(sb + B_OFF + idx * 16, s0 + idx);
        }
        CP_COMMIT();
    }

    for (int it = 0; it < 18; it++) {
        int chunk = it / 9, tap = it % 9, buf = it & 1;
        int dy = tap / 3, dx = tap % 3;
        __syncthreads();

        if (it + 1 < 18) {
            const uint4* s0 = reinterpret_cast<const uint4*>(g_wH[it + 1]);
            uint32_t d0 = sb + B_OFF + (buf ^ 1) * 16384;
#pragma unroll
            for (int j = 0; j < 4; j++) {
                int idx = tid + j * 256;
                CP16(d0 + idx * 16, s0 + idx);
            }
        }
        CP_COMMIT();

        if (tap == 0) {
            for (int i = tid; i < 1440; i += 256) {
                int row = i >> 3, ch = i & 7;
                int pr = row / 18, pc = row % 18;
                size_t g = pbase + ((size_t)pr * PW_ + pc) * C_ + chunk * 64 + ch * 8;
                uint32_t so = (uint32_t)row * 128 + ((ch ^ (row & 7)) << 4);
                *reinterpret_cast<uint4*>(smem + A_HI + so) = *reinterpret_cast<const uint4*>(&g_phi[g]);
                *reinterpret_cast<uint4*>(smem + A_LO + so) = *reinterpret_cast<const uint4*>(&g_plo[g]);
            }
        }
        CP_WAIT(1);
        __syncthreads();

        uint32_t bbase = sb + B_OFF + buf * 16384;
        int rowA[2], swA[2];
#pragma unroll
        for (int mt = 0; mt < 2; mt++) {
            rowA[mt] = (rA[mt] + dy) * 18 + cA[mt] + dx;
            swA[mt]  = rowA[mt] & 7;
        }

#pragma unroll
        for (int k16 = 0; k16 < 4; k16++) {
            int chA = k16 * 2 + khalf_a;
            int chB = k16 * 2 + khalf_b;
            uint32_t ah[2][4], al[2][4];
#pragma unroll
            for (int mt = 0; mt < 2; mt++) {
                uint32_t off = (uint32_t)rowA[mt] * 128 + ((chA ^ swA[mt]) << 4);
                ldsm_x4(ah[mt], sb + A_HI + off);
                ldsm_x4(al[mt], sb + A_LO + off);
            }
            uint32_t bh[4][4];
#pragma unroll
            for (int nb4 = 0; nb4 < 4; nb4++) {
                uint32_t off = bRow[nb4] + ((chB ^ bSw[nb4]) << 4);
                ldsm_x4(bh[nb4], bbase + off);
            }
#pragma unroll
            for (int mt = 0; mt < 2; mt++) {
#pragma unroll
                for (int nb4 = 0; nb4 < 4; nb4++) {
#pragma unroll
                    for (int half = 0; half < 2; half++) {
                        int n = nb4 * 2 + half;
                        uint32_t b0h = bh[nb4][half * 2], b1h = bh[nb4][half * 2 + 1];
                        mma16816h(acc[mt][n], ah[mt], b0h, b1h);
                        mma16816h(acc[mt][n], al[mt], b0h, b1h);
                    }
                }
            }
        }
    }

    // ---------------- epilogue: transpose, store, per-CTA channel sums ----------------
    float* sf = reinterpret_cast<float*>(smem);
    int rbase = lane >> 2, cpair = (lane & 3) * 2;
#pragma unroll
    for (int p = 0; p < 2; p++) {
        __syncthreads();
        if (warp_n == p) {
#pragma unroll
            for (int mt = 0; mt < 2; mt++)
#pragma unroll
                for (int nbl = 0; nbl < 8; nbl++)
#pragma unroll
                    for (int e = 0; e < 4; e++) {
                        int m   = warp_m * 32 + mt * 16 + rbase + ((e >> 1) << 3);
                        int ocl = nbl * 8 + cpair + (e & 1);
                        sf[ocl * 132 + m] = acc[mt][nbl][e];
                    }
        }
        __syncthreads();
#pragma unroll
        for (int j = 0; j < 8; j++) {
            int idx = tid + j * 256;
            int ocl = idx >> 5, q = idx & 31;
            int r = q >> 2, cc = (q & 3) * 4;
            float4 v = *reinterpret_cast<const float4*>(&sf[ocl * 132 + r * 16 + cc]);
            int oc = p * 64 + ocl;
            float bias = rc_b[oc];
            v.x += bias; v.y += bias; v.z += bias; v.w += bias;
            *reinterpret_cast<float4*>(&out[(size_t)(b * C_ + oc) * HW_ + (h0 + r) * W_ + w0 + cc]) = v;
            // channel partial sum (deterministic per-CTA; warp covers all 32 q of this ocl)
            float s = (v.x + v.y) + (v.z + v.w);
#pragma unroll
            for (int o = 16; o > 0; o >>= 1) s += __shfl_xor_sync(0xFFFFFFFFu, s, o);
            if (lane == 0) g_cpart[(size_t)blockIdx.x * 128 + oc] = s;
        }
    }
}

// ---------------- squeeze-excite (reduce conv partials + 2-layer MLP) ----------------
__global__ void __launch_bounds__(1024) k_se2(const float* __restrict__ se_w1,
                                              const float* __restrict__ se_w2) {
    __shared__ float part[4][256];
    __shared__ float mean_s[256];
    __shared__ float y1s[16];
    int tid = threadIdx.x;
    int q = tid >> 8, bc = tid & 255;
    int b = bc >> 7, c = bc & 127;
    float s = 0.f;
    for (int t = q * 60; t < q * 60 + 60; t++)
        s += g_cpart[(size_t)(b * 240 + t) * 128 + c];
    part[q][bc] = s;
    __syncthreads();
    if (tid < 256) {
        float m = part[0][tid] + part[1][tid] + part[2][tid] + part[3][tid];
        mean_s[tid] = m / (float)HW_;
    }
    __syncthreads();
    if (tid < 16) {
        int bb = tid / 8, j = tid % 8;
        float s2 = 0.f;
        for (int cc = 0; cc < C_; cc++) s2 += mean_s[bb * 128 + cc] * se_w1[j * C_ + cc];
        y1s[tid] = fmaxf(s2, 0.f);
    }
    __syncthreads();
    if (tid < 256) {
        int bb = tid >> 7, cc = tid & 127;
        float s3 = 0.f;
#pragma unroll
        for (int j = 0; j < 8; j++) s3 += y1s[bb * 8 + j] * se_w2[cc * 8 + j];
        g_yscale[tid] = 1.f / (1.f + expf(-s3));
    }
}

__global__ void __launch_bounds__(256) k_elu(float* __restrict__ out) {
    int idx = blockIdx.x * 256 + threadIdx.x;
    float v = out[idx] * g_yscale[idx / HW_];
    out[idx] = v > 0.f ? v : expm1f(v);
}

// ---------------- launch ----------------
extern "C" void kernel_launch(void* const* d_in, const int* in_sizes, int n_in,
                              void* d_out, int out_size) {
    const float* t_feat  = (const float*)d_in[0];
    const float* s_feat  = (const float*)d_in[1];
    const float* directs = (const float*)d_in[2];
    const float* disp    = (const float*)d_in[3];
    const float* q_w     = (const float*)d_in[4];
    const float* q_b     = (const float*)d_in[5];
    const float* k_w     = (const float*)d_in[6];
    const float* k_b     = (const float*)d_in[7];
    const float* cf_w    = (const float*)d_in[8];
    const float* nt_w    = (const float*)d_in[10];
    const float* nt_b    = (const float*)d_in[11];
    const float* nc_w    = (const float*)d_in[12];
    const float* nc_b    = (const float*)d_in[13];
    const float* ce_w    = (const float*)d_in[14];
    const float* ce_b    = (const float*)d_in[15];
    const float* fa_w    = (const float*)d_in[16];
    const float* fa_b    = (const float*)d_in[17];
    const float* rc_w    = (const float*)d_in[18];
    const float* rc_b    = (const float*)d_in[19];
    const float* se_w1   = (const float*)d_in[20];
    const float* se_w2   = (const float*)d_in[21];
    float* out = (float*)d_out;

    cudaFuncSetAttribute(k_conv_mma, cudaFuncAttributeMaxDynamicSharedMemorySize, CONV_SMEM);

    k_prep<<<1, 64>>>(fa_w, ce_w, ce_b, nt_w, nt_b);
    k_prepW<<<18, 256>>>(rc_w);
    k_qk<<<dim3(NPIX_ / 256, 2), 256>>>(t_feat, s_feat, q_w, q_b, k_w, k_b);
    k_stats_part<<<dim3(512, B_), 256>>>(t_feat, C_ * HW_ / 4);
    k_stats_final<<<B_, 512>>>(0, (double)(C_ * HW_), 1e-5);
    k_sim<<<dim3(H_, B_), W_>>>(disp, directs);
    k_costsoft<<<dim3(H_, B_), W_>>>(cf_w, out);
    k_stats_part<<<dim3(512, B_), 256>>>(out + XEL_, D_ * HW_ / 4);
    k_stats_final<<<B_, 512>>>(4, (double)(D_ * HW_), 1e-5);
    k_fuse<<<NPIX_ / 256, 256>>>(out, t_feat, nt_w, nt_b, nc_w, nc_b, ce_w, ce_b, fa_w, fa_b);
    k_border<<<dim3(2 * PW_ + 2 * H_, B_), C_>>>();
    k_conv_mma<<<480, 256, CONV_SMEM>>>(rc_b, out);
    k_se2<<<1, 1024>>>(se_w1, se_w2);
    k_elu<<<XEL_ / 256, 256>>>(out);
}

// round 6
// speedup vs baseline: 3.2856x; 1.1832x over previous
#include <cuda_runtime.h>
#include <cuda_fp16.h>
#include <math.h>
#include <stdint.h>

#define B_   2
#define C_   128
#define H_   96
#define W_   320
#define HW_  30720
#define CQ_  32
#define D_   32
#define NPIX_ (B_*HW_)        // 61440
#define XEL_  (B_*C_*HW_)     // 7864320
#define NCEL_ (B_*D_*HW_)     // 1966080
#define PH_  98
#define PW_  322

typedef unsigned long long u64;

#define FMA2(d,a,b,c) asm("fma.rn.f32x2 %0, %1, %2, %3;" : "=l"(d) : "l"(a), "l"(b), "l"(c))
#define PACK2(d,lo,hi) asm("mov.b64 %0, {%1, %2};" : "=l"(d) : "r"(__float_as_uint(lo)), "r"(__float_as_uint(hi)))
#define UNPK2(lo,hi,s) do { unsigned _a,_b; asm("mov.b64 {%0, %1}, %2;" : "=r"(_a), "=r"(_b) : "l"(s)); lo=__uint_as_float(_a); hi=__uint_as_float(_b); } while(0)

// ---------------- scratch ----------------
__device__ float  g_q[NCEL_];
__device__ float  g_k[NCEL_];
__device__ float  g_sim[NCEL_];
__device__ __align__(16) __half g_phi[(size_t)B_*PH_*PW_*C_];
__device__ __align__(16) unsigned short g_wH[18][8192];   // pre-swizzled fp16 weight smem-images
__device__ float  g_faproj[40];
__device__ float  g_partf[2*512*2];
__device__ float  g_stats[8];
__device__ float  g_cpart[480*128];    // per-CTA conv channel sums (post-bias)
__device__ float  g_yscale[B_*C_];

// ---------------- low-level helpers ----------------
__device__ __forceinline__ uint32_t smem_u32(const void* p) {
    uint32_t a;
    asm("{ .reg .u64 t; cvta.to.shared.u64 t, %1; cvt.u32.u64 %0, t; }" : "=r"(a) : "l"(p));
    return a;
}
#define CP16(sm, gp) asm volatile("cp.async.cg.shared.global [%0], [%1], 16;" :: "r"(sm), "l"(gp) : "memory")
#define CP_COMMIT()  asm volatile("cp.async.commit_group;" ::: "memory")
#define CP_WAIT(n)   asm volatile("cp.async.wait_group %0;" :: "n"(n) : "memory")

__device__ __forceinline__ void ldsm_x4(uint32_t* r, uint32_t addr) {
    asm volatile("ldmatrix.sync.aligned.m8n8.x4.shared.b16 {%0,%1,%2,%3}, [%4];"
        : "=r"(r[0]), "=r"(r[1]), "=r"(r[2]), "=r"(r[3]) : "r"(addr));
}
__device__ __forceinline__ void mma16816h(float* d, const uint32_t* a, uint32_t b0, uint32_t b1) {
    asm volatile("mma.sync.aligned.m16n8k16.row.col.f32.f16.f16.f32 "
        "{%0,%1,%2,%3}, {%4,%5,%6,%7}, {%8,%9}, {%0,%1,%2,%3};"
        : "+f"(d[0]), "+f"(d[1]), "+f"(d[2]), "+f"(d[3])
        : "r"(a[0]), "r"(a[1]), "r"(a[2]), "r"(a[3]), "r"(b0), "r"(b1));
}

// ---------------- tiny weight preprocessing ----------------
__global__ void k_prep(const float* __restrict__ fa_w,
                       const float* __restrict__ ce_w,
                       const float* __restrict__ ce_b,
                       const float* __restrict__ nt_w,
                       const float* __restrict__ nt_b) {
    int t = threadIdx.x;
    if (t < 32) {
        float s = 0.f;
        for (int o = 0; o < C_; o++) s += fa_w[C_ + o] * ce_w[o * D_ + t];
        g_faproj[t] = s;
    } else if (t == 32) {
        float s = 0.f;
        for (int o = 0; o < C_; o++) s += fa_w[C_ + o] * ce_b[o];
        g_faproj[32] = s;
    } else if (t == 33) {
        float s = 0.f;
        for (int c = 0; c < C_; c++) s += fa_w[c] * nt_b[c];
        g_faproj[33] = s;
    } else if (t == 34) {
        float s = 0.f;
        for (int c = 0; c < C_; c++) s += fa_w[c] * nt_w[c];
        g_faproj[34] = s;
    }
}

// weights -> fp16 smem-image: [it = chunk*9+tap][oc 0..127][icl 0..63],
// 16B-chunk swizzled by (oc&7); row stride 64 halfs = 128B
__global__ void k_prepW(const float* __restrict__ rc_w) {
    int it = blockIdx.x;      // chunk*9 + tap
    int tap = it % 9, chunk = it / 9;
    for (int idx = threadIdx.x; idx < 8192; idx += 256) {
        int oc = idx >> 6, icl = idx & 63;
        int ic = chunk * 64 + icl;
        float w = rc_w[(oc * C_ + ic) * 9 + tap];
        int pos = oc * 64 + (((icl >> 3) ^ (oc & 7)) << 3) + (icl & 7);
        g_wH[it][pos] = __half_as_ushort(__float2half_rn(w));
    }
}

// ---------------- q / k projections (packed f32x2) ----------------
__global__ void __launch_bounds__(256) k_qk(const float* __restrict__ t_feat,
                                            const float* __restrict__ s_feat,
                                            const float* __restrict__ q_w,
                                            const float* __restrict__ q_b,
                                            const float* __restrict__ k_w,
                                            const float* __restrict__ k_b) {
    __shared__ u64 wp[C_][16];
    __shared__ float bsh[CQ_];
    int which = blockIdx.y;
    const float* feat = which ? s_feat : t_feat;
    const float* wm   = which ? k_w : q_w;
    const float* bv   = which ? k_b : q_b;
    float* dst        = which ? g_k : g_q;

    for (int i = threadIdx.x; i < C_ * 16; i += 256) {
        int c = i >> 4, op = i & 15;
        u64 t; PACK2(t, wm[(2 * op) * C_ + c], wm[(2 * op + 1) * C_ + c]);
        wp[c][op] = t;
    }
    if (threadIdx.x < CQ_) bsh[threadIdx.x] = bv[threadIdx.x];
    __syncthreads();

    int idx = blockIdx.x * 256 + threadIdx.x;
    int b = idx / HW_;
    int pix = idx % HW_;
    const float* fp = feat + (size_t)b * C_ * HW_ + pix;

    u64 acc[16];
#pragma unroll
    for (int o = 0; o < 16; o++) acc[o] = 0ULL;

#pragma unroll 4
    for (int c = 0; c < C_; c++) {
        float v = fp[(size_t)c * HW_];
        u64 v2; PACK2(v2, v, v);
        const u64* wr = wp[c];
#pragma unroll
        for (int op = 0; op < 16; op++) FMA2(acc[op], wr[op], v2, acc[op]);
    }
    float* dp = dst + (size_t)b * CQ_ * HW_ + pix;
#pragma unroll
    for (int op = 0; op < 16; op++) {
        float lo, hi; UNPK2(lo, hi, acc[op]);
        dp[(size_t)(2 * op) * HW_]     = lo + bsh[2 * op];
        dp[(size_t)(2 * op + 1) * HW_] = hi + bsh[2 * op + 1];
    }
}

// ---------------- per-batch mean/var ----------------
__global__ void __launch_bounds__(256) k_stats_part(const float* __restrict__ src, int perBatch4) {
    __shared__ float sh1[256], sh2[256];
    int b = blockIdx.y;
    const float4* p = reinterpret_cast<const float4*>(src) + (size_t)b * perBatch4;
    float s1 = 0.f, s2 = 0.f;
    for (int i = blockIdx.x * 256 + threadIdx.x; i < perBatch4; i += 512 * 256) {
        float4 v = p[i];
        s1 += (v.x + v.y) + (v.z + v.w);
        s2 += (v.x * v.x + v.y * v.y) + (v.z * v.z + v.w * v.w);
    }
    sh1[threadIdx.x] = s1; sh2[threadIdx.x] = s2;
    __syncthreads();
    for (int s = 128; s > 0; s >>= 1) {
        if (threadIdx.x < s) { sh1[threadIdx.x] += sh1[threadIdx.x + s]; sh2[threadIdx.x] += sh2[threadIdx.x + s]; }
        __syncthreads();
    }
    if (threadIdx.x == 0) {
        g_partf[(b * 512 + blockIdx.x) * 2 + 0] = sh1[0];
        g_partf[(b * 512 + blockIdx.x) * 2 + 1] = sh2[0];
    }
}

__global__ void k_stats_final(int outBase, double N, double eps) {
    __shared__ double sh1[512], sh2[512];
    int b = blockIdx.x;
    sh1[threadIdx.x] = (double)g_partf[(b * 512 + threadIdx.x) * 2 + 0];
    sh2[threadIdx.x] = (double)g_partf[(b * 512 + threadIdx.x) * 2 + 1];
    __syncthreads();
    for (int s = 256; s > 0; s >>= 1) {
        if (threadIdx.x < s) { sh1[threadIdx.x] += sh1[threadIdx.x + s]; sh2[threadIdx.x] += sh2[threadIdx.x + s]; }
        __syncthreads();
    }
    if (threadIdx.x == 0) {
        double mu  = sh1[0] / N;
        double var = sh2[0] / N - mu * mu;
        g_stats[outBase + b * 2 + 0] = (float)mu;
        g_stats[outBase + b * 2 + 1] = (float)(1.0 / sqrt(var + eps));
    }
}

// ---------------- warp volume + cosine similarity ----------------
__global__ void __launch_bounds__(W_) k_sim(const float* __restrict__ disp,
                                            const float* __restrict__ directs) {
    __shared__ float ksh[CQ_][W_];
    int h = blockIdx.x, b = blockIdx.y;
    int w = threadIdx.x;

    for (int i = threadIdx.x; i < CQ_ * W_; i += W_) {
        int c = i / W_, ww = i % W_;
        ksh[c][ww] = g_k[((size_t)(b * CQ_ + c)) * HW_ + h * W_ + ww];
    }
    __syncthreads();

    float qv[CQ_];
    float n2 = 0.f;
    const float* qp = g_q + (size_t)b * CQ_ * HW_ + h * W_ + w;
#pragma unroll
    for (int c = 0; c < CQ_; c++) { float v = qp[(size_t)c * HW_]; qv[c] = v; n2 += v * v; }
    float inv = 1.f / fmaxf(sqrtf(n2), 1e-12f);
#pragma unroll
    for (int c = 0; c < CQ_; c++) qv[c] *= inv;

    float dir = directs[b];
    float* sp = g_sim + (size_t)b * D_ * HW_ + h * W_ + w;
    for (int d = 0; d < D_; d++) {
        float pos = (float)w + disp[d] * dir * (float)(W_ - 1);
        pos = fminf(fmaxf(pos, 0.f), (float)(W_ - 1));
        int x0 = (int)floorf(pos);
        x0 = min(max(x0, 0), W_ - 1);
        int x1 = min(x0 + 1, W_ - 1);
        float t = pos - (float)x0;
        float dot = 0.f, kn2 = 0.f;
#pragma unroll
        for (int c = 0; c < CQ_; c++) {
            float g = ksh[c][x0] * (1.f - t) + ksh[c][x1] * t;
            dot += qv[c] * g;
            kn2 += g * g;
        }
        sp[(size_t)d * HW_] = dot / fmaxf(sqrtf(kn2), 1e-12f);
    }
}

// ---------------- fused 3x3x3 cost filtering + softmax over D ----------------
__global__ void __launch_bounds__(W_) k_costsoft(const float* __restrict__ cf_w,
                                                 float* __restrict__ out) {
    __shared__ float wsh[27];
    __shared__ float sh[2][3][PW_];
    int h = blockIdx.x, b = blockIdx.y, w = threadIdx.x;
    if (threadIdx.x < 27) wsh[threadIdx.x] = cf_w[threadIdx.x];
    if (threadIdx.x < 12) {
        int bu = threadIdx.x / 6, r = (threadIdx.x % 6) / 2, e = threadIdx.x & 1;
        sh[bu][r][e * (PW_ - 1)] = 0.f;
    }

    float c[D_];
#pragma unroll
    for (int d = 0; d < D_; d++) c[d] = 0.f;

#pragma unroll
    for (int dd = 0; dd < D_; dd++) {
        int bu = dd & 1;
#pragma unroll
        for (int r = 0; r < 3; r++) {
            int hh = h + r - 1;
            float v = 0.f;
            if (hh >= 0 && hh < H_) v = g_sim[((size_t)(b * D_ + dd) * H_ + hh) * W_ + w];
            sh[bu][r][w + 1] = v;
        }
        __syncthreads();
        float s0 = 0.f, s1 = 0.f, s2 = 0.f;
#pragma unroll
        for (int r = 0; r < 3; r++) {
            float v0 = sh[bu][r][w], v1 = sh[bu][r][w + 1], v2 = sh[bu][r][w + 2];
            s0 += wsh[r * 3 + 0] * v0 + wsh[r * 3 + 1] * v1 + wsh[r * 3 + 2] * v2;
            s1 += wsh[9 + r * 3 + 0] * v0 + wsh[9 + r * 3 + 1] * v1 + wsh[9 + r * 3 + 2] * v2;
            s2 += wsh[18 + r * 3 + 0] * v0 + wsh[18 + r * 3 + 1] * v1 + wsh[18 + r * 3 + 2] * v2;
        }
        if (dd + 1 < D_) c[dd + 1] += s0;
        c[dd] += s1;
        if (dd >= 1) c[dd - 1] += s2;
    }

    float m = -1e30f;
#pragma unroll
    for (int d = 0; d < D_; d++) m = fmaxf(m, c[d]);
    float sum = 0.f;
#pragma unroll
    for (int d = 0; d < D_; d++) { c[d] = expf(c[d] - m); sum += c[d]; }
    float invs = 1.f / sum;
    float* op = out + XEL_ + (size_t)b * D_ * HW_ + h * W_ + w;
#pragma unroll
    for (int d = 0; d < D_; d++) op[(size_t)d * HW_] = c[d] * invs;
}

// ---------------- groupnorms + cost embed + gated fusion -> padded NHWC fp16 ----------------
__global__ void __launch_bounds__(256) k_fuse(const float* __restrict__ out_base,
                                              const float* __restrict__ t_feat,
                                              const float* __restrict__ nt_w,
                                              const float* __restrict__ nt_b,
                                              const float* __restrict__ nc_w,
                                              const float* __restrict__ nc_b,
                                              const float* __restrict__ ce_w,
                                              const float* __restrict__ ce_b,
                                              const float* __restrict__ fa_w,
                                              const float* __restrict__ fa_b) {
    __shared__ u64 cep[D_][64];
    __shared__ u64 cebp[64];
    __shared__ float fw[C_], ntw[C_], ntb[C_];
    __shared__ float ncw[D_], ncb[D_], proj[40];

    for (int i = threadIdx.x; i < D_ * 64; i += 256) {
        int d = i >> 6, op = i & 63;
        u64 t; PACK2(t, ce_w[(2 * op) * D_ + d], ce_w[(2 * op + 1) * D_ + d]);
        cep[d][op] = t;
    }
    if (threadIdx.x < 64) {
        u64 t; PACK2(t, ce_b[2 * threadIdx.x], ce_b[2 * threadIdx.x + 1]);
        cebp[threadIdx.x] = t;
    }
    if (threadIdx.x < C_) {
        float f = fa_w[threadIdx.x];
        float w = nt_w[threadIdx.x];
        fw[threadIdx.x]  = f * w;
        ntw[threadIdx.x] = w;
        ntb[threadIdx.x] = nt_b[threadIdx.x];
    }
    if (threadIdx.x < D_) { ncw[threadIdx.x] = nc_w[threadIdx.x]; ncb[threadIdx.x] = nc_b[threadIdx.x]; }
    if (threadIdx.x >= 128 && threadIdx.x < 128 + 40) proj[threadIdx.x - 128] = g_faproj[threadIdx.x - 128];
    __syncthreads();

    int idx = blockIdx.x * 256 + threadIdx.x;
    int b = idx / HW_, pix = idx % HW_;
    int h = pix / W_, w = pix % W_;
    float mu_t = g_stats[b * 2 + 0], inv_t = g_stats[b * 2 + 1];
    float mu_c = g_stats[4 + b * 2 + 0], inv_c = g_stats[4 + b * 2 + 1];

    const float* ncp = out_base + XEL_ + (size_t)b * D_ * HW_ + pix;
    u64 cnp[D_];
    float alin = fa_b[0] + proj[32] + proj[33];
#pragma unroll
    for (int d = 0; d < D_; d++) {
        float v = (ncp[(size_t)d * HW_] - mu_c) * inv_c * ncw[d] + ncb[d];
        PACK2(cnp[d], v, v);
        alin += proj[d] * v;
    }
    const float* tp = t_feat + (size_t)b * C_ * HW_ + pix;
    float dotft = 0.f;
#pragma unroll 4
    for (int c = 0; c < C_; c++) dotft += fw[c] * tp[(size_t)c * HW_];
    alin += inv_t * (dotft - mu_t * proj[34]);

    float alpha = 1.f / (1.f + expf(-alin));
    float om = 1.f - alpha;

    size_t pbase = ((size_t)(b * PH_ + h + 1) * PW_ + (w + 1)) * C_;
    unsigned hq[4];
#pragma unroll 2
    for (int op = 0; op < 64; op++) {
        u64 a2 = cebp[op];
#pragma unroll
        for (int d = 0; d < D_; d++) FMA2(a2, cep[d][op], cnp[d], a2);
        float cf0, cf1; UNPK2(cf0, cf1, a2);
        int o0 = 2 * op, o1 = 2 * op + 1;
        float tv0 = (tp[(size_t)o0 * HW_] - mu_t) * inv_t * ntw[o0] + ntb[o0];
        float tv1 = (tp[(size_t)o1 * HW_] - mu_t) * inv_t * ntw[o1] + ntb[o1];
        float f0 = alpha * tv0 + om * cf0;
        float f1 = alpha * tv1 + om * cf1;
        int grp = op & 3;
        hq[grp] = (unsigned)__half_as_ushort(__float2half_rn(f0)) |
                  ((unsigned)__half_as_ushort(__float2half_rn(f1)) << 16);
        if (grp == 3) {
            int oc8 = 2 * (op - 3);
            *reinterpret_cast<uint4*>(&g_phi[pbase + oc8]) = make_uint4(hq[0], hq[1], hq[2], hq[3]);
        }
    }
}

// ---------------- reflect border fill ----------------
__global__ void k_border() {
    int i = blockIdx.x;
    int b = blockIdx.y;
    int hp, wp;
    if (i < PW_)            { hp = 0;           wp = i; }
    else if (i < 2 * PW_)   { hp = PH_ - 1;     wp = i - PW_; }
    else if (i < 2 * PW_ + H_) { hp = i - 2 * PW_ + 1; wp = 0; }
    else                    { hp = i - 2 * PW_ - H_ + 1; wp = PW_ - 1; }
    int rh = hp - 1, rw = wp - 1;
    rh = (rh < 0) ? -rh : ((rh >= H_) ? 2 * H_ - 2 - rh : rh);
    rw = (rw < 0) ? -rw : ((rw >= W_) ? 2 * W_ - 2 - rw : rw);
    size_t dst = ((size_t)(b * PH_ + hp) * PW_ + wp) * C_ + threadIdx.x;
    size_t src = ((size_t)(b * PH_ + rh + 1) * PW_ + (rw + 1)) * C_ + threadIdx.x;
    g_phi[dst] = g_phi[src];
}

// ---------------- mma.sync implicit-GEMM conv (fp16 single-term) ----------------
// smem: A [180 x 128B] @0; B double-buffered @23040 (16KB each)
#define A_HI  0
#define B_OFF 23040
#define CONV_SMEM 55808

__global__ void __launch_bounds__(256, 2) k_conv_mma(const float* __restrict__ rc_b,
                                                     float* __restrict__ out) {
    extern __shared__ __align__(128) char smem[];
    uint32_t sb = smem_u32(smem);
    int tid = threadIdx.x, lane = tid & 31, wid = tid >> 5;
    int warp_m = wid & 3, warp_n = wid >> 2;

    int bx = blockIdx.x % 20;
    int by = (blockIdx.x / 20) % 12;
    int b  = blockIdx.x / 240;
    int h0 = by * 8, w0 = bx * 16;
    size_t pbase = ((size_t)(b * PH_ + h0) * PW_ + w0) * C_;

    int m_loc = lane & 15, khalf_a = lane >> 4;
    int rA[2], cA[2];
#pragma unroll
    for (int mt = 0; mt < 2; mt++) {
        int m_abs = warp_m * 32 + mt * 16 + m_loc;
        rA[mt] = m_abs >> 4;
        cA[mt] = m_abs & 15;
    }
    int subB = lane >> 3;
    int nl = (lane & 7) + ((subB & 2) << 2);
    int khalf_b = subB & 1;
    uint32_t bRow[4]; int bSw[4];
#pragma unroll
    for (int nb4 = 0; nb4 < 4; nb4++) {
        int oc = warp_n * 64 + nb4 * 16 + nl;
        bRow[nb4] = (uint32_t)oc * 128;
        bSw[nb4]  = oc & 7;
    }

    float acc[2][8][4];
#pragma unroll
    for (int mt = 0; mt < 2; mt++)
#pragma unroll
        for (int n = 0; n < 8; n++)
#pragma unroll
            for (int e = 0; e < 4; e++) acc[mt][n][e] = 0.f;

    // prefetch B(it=0)
    {
        const uint4* s0 = reinterpret_cast<const uint4*>(g_wH[0]);
#pragma unroll
        for (int j = 0; j < 4; j++) {
            int idx = tid + j * 256;
            CP16(sb + B_OFF + idx * 16, s0 + idx);
        }
        CP_COMMIT();
    }

    for (int it = 0; it < 18; it++) {
        int chunk = it / 9, tap = it % 9, buf = it & 1;
        int dy = tap / 3, dx = tap % 3;
        __syncthreads();

        if (it + 1 < 18) {
            const uint4* s0 = reinterpret_cast<const uint4*>(g_wH[it + 1]);
            uint32_t d0 = sb + B_OFF + (buf ^ 1) * 16384;
#pragma unroll
            for (int j = 0; j < 4; j++) {
                int idx = tid + j * 256;
                CP16(d0 + idx * 16, s0 + idx);
            }
        }
        CP_COMMIT();

        if (tap == 0) {
            for (int i = tid; i < 1440; i += 256) {
                int row = i >> 3, ch = i & 7;
                int pr = row / 18, pc = row % 18;
                size_t g = pbase + ((size_t)pr * PW_ + pc) * C_ + chunk * 64 + ch * 8;
                uint32_t so = (uint32_t)row * 128 + ((ch ^ (row & 7)) << 4);
                *reinterpret_cast<uint4*>(smem + A_HI + so) = *reinterpret_cast<const uint4*>(&g_phi[g]);
            }
        }
        CP_WAIT(1);
        __syncthreads();

        uint32_t bbase = sb + B_OFF + buf * 16384;
        int rowA[2], swA[2];
#pragma unroll
        for (int mt = 0; mt < 2; mt++) {
            rowA[mt] = (rA[mt] + dy) * 18 + cA[mt] + dx;
            swA[mt]  = rowA[mt] & 7;
        }

#pragma unroll
        for (int k16 = 0; k16 < 4; k16++) {
            int chA = k16 * 2 + khalf_a;
            int chB = k16 * 2 + khalf_b;
            uint32_t ah[2][4];
#pragma unroll
            for (int mt = 0; mt < 2; mt++) {
                uint32_t off = (uint32_t)rowA[mt] * 128 + ((chA ^ swA[mt]) << 4);
                ldsm_x4(ah[mt], sb + A_HI + off);
            }
            uint32_t bh[4][4];
#pragma unroll
            for (int nb4 = 0; nb4 < 4; nb4++) {
                uint32_t off = bRow[nb4] + ((chB ^ bSw[nb4]) << 4);
                ldsm_x4(bh[nb4], bbase + off);
            }
#pragma unroll
            for (int mt = 0; mt < 2; mt++) {
#pragma unroll
                for (int nb4 = 0; nb4 < 4; nb4++) {
#pragma unroll
                    for (int half = 0; half < 2; half++) {
                        int n = nb4 * 2 + half;
                        mma16816h(acc[mt][n], ah[mt], bh[nb4][half * 2], bh[nb4][half * 2 + 1]);
                    }
                }
            }
        }
    }

    // ---------------- epilogue: transpose, store, per-CTA channel sums ----------------
    float* sf = reinterpret_cast<float*>(smem);
    int rbase = lane >> 2, cpair = (lane & 3) * 2;
#pragma unroll
    for (int p = 0; p < 2; p++) {
        __syncthreads();
        if (warp_n == p) {
#pragma unroll
            for (int mt = 0; mt < 2; mt++)
#pragma unroll
                for (int nbl = 0; nbl < 8; nbl++)
#pragma unroll
                    for (int e = 0; e < 4; e++) {
                        int m   = warp_m * 32 + mt * 16 + rbase + ((e >> 1) << 3);
                        int ocl = nbl * 8 + cpair + (e & 1);
                        sf[ocl * 132 + m] = acc[mt][nbl][e];
                    }
        }
        __syncthreads();
#pragma unroll
        for (int j = 0; j < 8; j++) {
            int idx = tid + j * 256;
            int ocl = idx >> 5, q = idx & 31;
            int r = q >> 2, cc = (q & 3) * 4;
            float4 v = *reinterpret_cast<const float4*>(&sf[ocl * 132 + r * 16 + cc]);
            int oc = p * 64 + ocl;
            float bias = rc_b[oc];
            v.x += bias; v.y += bias; v.z += bias; v.w += bias;
            *reinterpret_cast<float4*>(&out[(size_t)(b * C_ + oc) * HW_ + (h0 + r) * W_ + w0 + cc]) = v;
            float s = (v.x + v.y) + (v.z + v.w);
#pragma unroll
            for (int o = 16; o > 0; o >>= 1) s += __shfl_xor_sync(0xFFFFFFFFu, s, o);
            if (lane == 0) g_cpart[(size_t)blockIdx.x * 128 + oc] = s;
        }
    }
}

// ---------------- squeeze-excite (reduce conv partials + 2-layer MLP) ----------------
__global__ void __launch_bounds__(1024) k_se2(const float* __restrict__ se_w1,
                                              const float* __restrict__ se_w2) {
    __shared__ float part[4][256];
    __shared__ float mean_s[256];
    __shared__ float y1s[16];
    int tid = threadIdx.x;
    int q = tid >> 8, bc = tid & 255;
    int b = bc >> 7, c = bc & 127;
    float s = 0.f;
    for (int t = q * 60; t < q * 60 + 60; t++)
        s += g_cpart[(size_t)(b * 240 + t) * 128 + c];
    part[q][bc] = s;
    __syncthreads();
    if (tid < 256) {
        float m = part[0][tid] + part[1][tid] + part[2][tid] + part[3][tid];
        mean_s[tid] = m / (float)HW_;
    }
    __syncthreads();
    if (tid < 16) {
        int bb = tid / 8, j = tid % 8;
        float s2 = 0.f;
        for (int cc = 0; cc < C_; cc++) s2 += mean_s[bb * 128 + cc] * se_w1[j * C_ + cc];
        y1s[tid] = fmaxf(s2, 0.f);
    }
    __syncthreads();
    if (tid < 256) {
        int bb = tid >> 7, cc = tid & 127;
        float s3 = 0.f;
#pragma unroll
        for (int j = 0; j < 8; j++) s3 += y1s[bb * 8 + j] * se_w2[cc * 8 + j];
        g_yscale[tid] = 1.f / (1.f + expf(-s3));
    }
}

__global__ void __launch_bounds__(256) k_elu(float* __restrict__ out) {
    int idx = blockIdx.x * 256 + threadIdx.x;
    float v = out[idx] * g_yscale[idx / HW_];
    out[idx] = v > 0.f ? v : expm1f(v);
}

// ---------------- launch ----------------
extern "C" void kernel_launch(void* const* d_in, const int* in_sizes, int n_in,
                              void* d_out, int out_size) {
    const float* t_feat  = (const float*)d_in[0];
    const float* s_feat  = (const float*)d_in[1];
    const float* directs = (const float*)d_in[2];
    const float* disp    = (const float*)d_in[3];
    const float* q_w     = (const float*)d_in[4];
    const float* q_b     = (const float*)d_in[5];
    const float* k_w     = (const float*)d_in[6];
    const float* k_b     = (const float*)d_in[7];
    const float* cf_w    = (const float*)d_in[8];
    const float* nt_w    = (const float*)d_in[10];
    const float* nt_b    = (const float*)d_in[11];
    const float* nc_w    = (const float*)d_in[12];
    const float* nc_b    = (const float*)d_in[13];
    const float* ce_w    = (const float*)d_in[14];
    const float* ce_b    = (const float*)d_in[15];
    const float* fa_w    = (const float*)d_in[16];
    const float* fa_b    = (const float*)d_in[17];
    const float* rc_w    = (const float*)d_in[18];
    const float* rc_b    = (const float*)d_in[19];
    const float* se_w1   = (const float*)d_in[20];
    const float* se_w2   = (const float*)d_in[21];
    float* out = (float*)d_out;

    cudaFuncSetAttribute(k_conv_mma, cudaFuncAttributeMaxDynamicSharedMemorySize, CONV_SMEM);

    k_prep<<<1, 64>>>(fa_w, ce_w, ce_b, nt_w, nt_b);
    k_prepW<<<18, 256>>>(rc_w);
    k_qk<<<dim3(NPIX_ / 256, 2), 256>>>(t_feat, s_feat, q_w, q_b, k_w, k_b);
    k_stats_part<<<dim3(512, B_), 256>>>(t_feat, C_ * HW_ / 4);
    k_stats_final<<<B_, 512>>>(0, (double)(C_ * HW_), 1e-5);
    k_sim<<<dim3(H_, B_), W_>>>(disp, directs);
    k_costsoft<<<dim3(H_, B_), W_>>>(cf_w, out);
    k_stats_part<<<dim3(512, B_), 256>>>(out + XEL_, D_ * HW_ / 4);
    k_stats_final<<<B_, 512>>>(4, (double)(D_ * HW_), 1e-5);
    k_fuse<<<NPIX_ / 256, 256>>>(out, t_feat, nt_w, nt_b, nc_w, nc_b, ce_w, ce_b, fa_w, fa_b);
    k_border<<<dim3(2 * PW_ + 2 * H_, B_), C_>>>();
    k_conv_mma<<<480, 256, CONV_SMEM>>>(rc_b, out);
    k_se2<<<1, 1024>>>(se_w1, se_w2);
    k_elu<<<XEL_ / 256, 256>>>(out);
}

// round 7
// speedup vs baseline: 3.3479x; 1.0189x over previous
#include <cuda_runtime.h>
#include <cuda_fp16.h>
#include <math.h>
#include <stdint.h>

#define B_   2
#define C_   128
#define H_   96
#define W_   320
#define HW_  30720
#define CQ_  32
#define D_   32
#define NPIX_ (B_*HW_)        // 61440
#define XEL_  (B_*C_*HW_)     // 7864320
#define NCEL_ (B_*D_*HW_)     // 1966080
#define PH_  98
#define PW_  322

typedef unsigned long long u64;

#define FMA2(d,a,b,c) asm("fma.rn.f32x2 %0, %1, %2, %3;" : "=l"(d) : "l"(a), "l"(b), "l"(c))
#define PACK2(d,lo,hi) asm("mov.b64 %0, {%1, %2};" : "=l"(d) : "r"(__float_as_uint(lo)), "r"(__float_as_uint(hi)))
#define UNPK2(lo,hi,s) do { unsigned _a,_b; asm("mov.b64 {%0, %1}, %2;" : "=r"(_a), "=r"(_b) : "l"(s)); lo=__uint_as_float(_a); hi=__uint_as_float(_b); } while(0)

// ---------------- scratch ----------------
__device__ float  g_sim[NCEL_];
__device__ __align__(16) __half g_phi[(size_t)B_*PH_*PW_*C_];
__device__ __align__(16) unsigned short g_wH[18][8192];   // pre-swizzled fp16 weight smem-images
__device__ float  g_faproj[40];
__device__ float  g_partf[4*96*2];     // [which*2+b][hblock][s1,s2]
__device__ float  g_stats[8];
__device__ float  g_cpart[480*128];
__device__ float  g_yscale[B_*C_];

// ---------------- low-level helpers ----------------
__device__ __forceinline__ uint32_t smem_u32(const void* p) {
    uint32_t a;
    asm("{ .reg .u64 t; cvta.to.shared.u64 t, %1; cvt.u32.u64 %0, t; }" : "=r"(a) : "l"(p));
    return a;
}
#define CP16(sm, gp) asm volatile("cp.async.cg.shared.global [%0], [%1], 16;" :: "r"(sm), "l"(gp) : "memory")
#define CP_COMMIT()  asm volatile("cp.async.commit_group;" ::: "memory")
#define CP_WAIT(n)   asm volatile("cp.async.wait_group %0;" :: "n"(n) : "memory")

__device__ __forceinline__ void ldsm_x4(uint32_t* r, uint32_t addr) {
    asm volatile("ldmatrix.sync.aligned.m8n8.x4.shared.b16 {%0,%1,%2,%3}, [%4];"
        : "=r"(r[0]), "=r"(r[1]), "=r"(r[2]), "=r"(r[3]) : "r"(addr));
}
__device__ __forceinline__ void mma16816h(float* d, const uint32_t* a, uint32_t b0, uint32_t b1) {
    asm volatile("mma.sync.aligned.m16n8k16.row.col.f32.f16.f16.f32 "
        "{%0,%1,%2,%3}, {%4,%5,%6,%7}, {%8,%9}, {%0,%1,%2,%3};"
        : "+f"(d[0]), "+f"(d[1]), "+f"(d[2]), "+f"(d[3])
        : "r"(a[0]), "r"(a[1]), "r"(a[2]), "r"(a[3]), "r"(b0), "r"(b1));
}

// ---------------- tiny weight preprocessing ----------------
__global__ void k_prep(const float* __restrict__ fa_w,
                       const float* __restrict__ ce_w,
                       const float* __restrict__ ce_b,
                       const float* __restrict__ nt_w,
                       const float* __restrict__ nt_b) {
    int t = threadIdx.x;
    if (t < 32) {
        float s = 0.f;
        for (int o = 0; o < C_; o++) s += fa_w[C_ + o] * ce_w[o * D_ + t];
        g_faproj[t] = s;
    } else if (t == 32) {
        float s = 0.f;
        for (int o = 0; o < C_; o++) s += fa_w[C_ + o] * ce_b[o];
        g_faproj[32] = s;
    } else if (t == 33) {
        float s = 0.f;
        for (int c = 0; c < C_; c++) s += fa_w[c] * nt_b[c];
        g_faproj[33] = s;
    } else if (t == 34) {
        float s = 0.f;
        for (int c = 0; c < C_; c++) s += fa_w[c] * nt_w[c];
        g_faproj[34] = s;
    }
}

__global__ void k_prepW(const float* __restrict__ rc_w) {
    int it = blockIdx.x;      // chunk*9 + tap
    int tap = it % 9, chunk = it / 9;
    for (int idx = threadIdx.x; idx < 8192; idx += 256) {
        int oc = idx >> 6, icl = idx & 63;
        int ic = chunk * 64 + icl;
        float w = rc_w[(oc * C_ + ic) * 9 + tap];
        int pos = oc * 64 + (((icl >> 3) ^ (oc & 7)) << 3) + (icl & 7);
        g_wH[it][pos] = __half_as_ushort(__float2half_rn(w));
    }
}

// ---------------- fused q/k projection + warp + cosine sim + t-stats ----------------
// dyn smem layout:
#define SQ_KSH 0                       // float[32][320]  40960
#define SQ_WQ  40960                   // u64[128][16]    16384
#define SQ_WK  57344                   // u64[128][16]    16384
#define SQ_BQ  73728                   // float[32]
#define SQ_BK  73856                   // float[32]
#define SQ_R1  73984                   // float[10]
#define SQ_R2  74032                   // float[10]
#define SIMQK_SMEM 74112

__global__ void __launch_bounds__(W_) k_simqk(const float* __restrict__ t_feat,
                                              const float* __restrict__ s_feat,
                                              const float* __restrict__ q_w,
                                              const float* __restrict__ q_b,
                                              const float* __restrict__ k_w,
                                              const float* __restrict__ k_b,
                                              const float* __restrict__ disp,
                                              const float* __restrict__ directs) {
    extern __shared__ __align__(16) char sm[];
    float* ksh = reinterpret_cast<float*>(sm + SQ_KSH);     // [c][w] stride 320
    u64*   wq  = reinterpret_cast<u64*>(sm + SQ_WQ);
    u64*   wk  = reinterpret_cast<u64*>(sm + SQ_WK);
    float* bq  = reinterpret_cast<float*>(sm + SQ_BQ);
    float* bk  = reinterpret_cast<float*>(sm + SQ_BK);
    float* r1  = reinterpret_cast<float*>(sm + SQ_R1);
    float* r2  = reinterpret_cast<float*>(sm + SQ_R2);

    int h = blockIdx.x, b = blockIdx.y;
    int w = threadIdx.x, lane = w & 31, wrp = w >> 5;

    for (int i = threadIdx.x; i < C_ * 16; i += W_) {
        int c = i >> 4, op = i & 15;
        u64 t;
        PACK2(t, q_w[(2 * op) * C_ + c], q_w[(2 * op + 1) * C_ + c]);
        wq[i] = t;
        PACK2(t, k_w[(2 * op) * C_ + c], k_w[(2 * op + 1) * C_ + c]);
        wk[i] = t;
    }
    if (threadIdx.x < CQ_) { bq[threadIdx.x] = q_b[threadIdx.x]; bk[threadIdx.x] = k_b[threadIdx.x]; }
    __syncthreads();

    // ---- k projection for own pixel ----
    {
        const float* fp = s_feat + (size_t)b * C_ * HW_ + h * W_ + w;
        u64 acc[16];
#pragma unroll
        for (int o = 0; o < 16; o++) acc[o] = 0ULL;
#pragma unroll 4
        for (int c = 0; c < C_; c++) {
            float v = fp[(size_t)c * HW_];
            u64 v2; PACK2(v2, v, v);
#pragma unroll
            for (int op = 0; op < 16; op++) FMA2(acc[op], wk[c * 16 + op], v2, acc[op]);
        }
#pragma unroll
        for (int op = 0; op < 16; op++) {
            float lo, hi; UNPK2(lo, hi, acc[op]);
            ksh[(2 * op) * W_ + w]     = lo + bk[2 * op];
            ksh[(2 * op + 1) * W_ + w] = hi + bk[2 * op + 1];
        }
    }

    // ---- q projection + t_feat stats ----
    float qv[CQ_];
    float s1 = 0.f, s2 = 0.f;
    {
        const float* tp = t_feat + (size_t)b * C_ * HW_ + h * W_ + w;
        u64 acc[16];
#pragma unroll
        for (int o = 0; o < 16; o++) acc[o] = 0ULL;
#pragma unroll 4
        for (int c = 0; c < C_; c++) {
            float v = tp[(size_t)c * HW_];
            s1 += v; s2 += v * v;
            u64 v2; PACK2(v2, v, v);
#pragma unroll
            for (int op = 0; op < 16; op++) FMA2(acc[op], wq[c * 16 + op], v2, acc[op]);
        }
        float n2 = 0.f;
#pragma unroll
        for (int op = 0; op < 16; op++) {
            float lo, hi; UNPK2(lo, hi, acc[op]);
            lo += bq[2 * op]; hi += bq[2 * op + 1];
            qv[2 * op] = lo; qv[2 * op + 1] = hi;
            n2 += lo * lo + hi * hi;
        }
        float inv = 1.f / fmaxf(sqrtf(n2), 1e-12f);
#pragma unroll
        for (int c = 0; c < CQ_; c++) qv[c] *= inv;
    }
    __syncthreads();   // ksh complete

    // ---- warp + cosine sim ----
    float dir = directs[b];
    float* sp = g_sim + (size_t)b * D_ * HW_ + h * W_ + w;
    for (int d = 0; d < D_; d++) {
        float pos = (float)w + disp[d] * dir * (float)(W_ - 1);
        pos = fminf(fmaxf(pos, 0.f), (float)(W_ - 1));
        int x0 = (int)floorf(pos);
        x0 = min(max(x0, 0), W_ - 1);
        int x1 = min(x0 + 1, W_ - 1);
        float t = pos - (float)x0;
        float dot = 0.f, kn2 = 0.f;
#pragma unroll
        for (int c = 0; c < CQ_; c++) {
            float g = ksh[c * W_ + x0] * (1.f - t) + ksh[c * W_ + x1] * t;
            dot += qv[c] * g;
            kn2 += g * g;
        }
        sp[(size_t)d * HW_] = dot / fmaxf(sqrtf(kn2), 1e-12f);
    }

    // ---- t-stats block reduce (deterministic) ----
#pragma unroll
    for (int o = 16; o > 0; o >>= 1) {
        s1 += __shfl_xor_sync(0xFFFFFFFFu, s1, o);
        s2 += __shfl_xor_sync(0xFFFFFFFFu, s2, o);
    }
    if (lane == 0) { r1[wrp] = s1; r2[wrp] = s2; }
    __syncthreads();
    if (threadIdx.x == 0) {
        float t1 = 0.f, t2 = 0.f;
#pragma unroll
        for (int i = 0; i < 10; i++) { t1 += r1[i]; t2 += r2[i]; }
        g_partf[((0 * 2 + b) * 96 + h) * 2 + 0] = t1;
        g_partf[((0 * 2 + b) * 96 + h) * 2 + 1] = t2;
    }
}

// ---------------- fused 3x3x3 cost filter + softmax + c-stats (warp-shuffle) ----------------
__global__ void __launch_bounds__(W_) k_costsoft(const float* __restrict__ cf_w,
                                                 float* __restrict__ out) {
    __shared__ float wsh[27];
    __shared__ float r1[10], r2[10];
    int h = blockIdx.x, b = blockIdx.y, w = threadIdx.x;
    int lane = w & 31, wrp = w >> 5;
    if (threadIdx.x < 27) wsh[threadIdx.x] = cf_w[threadIdx.x];
    __syncthreads();

    float c[D_];
#pragma unroll
    for (int d = 0; d < D_; d++) c[d] = 0.f;

#pragma unroll
    for (int dd = 0; dd < D_; dd++) {
        float s0 = 0.f, s1 = 0.f, s2 = 0.f;
#pragma unroll
        for (int r = 0; r < 3; r++) {
            int hh = h + r - 1;
            bool ok = (hh >= 0) && (hh < H_);
            const float* row = g_sim + ((size_t)(b * D_ + dd) * H_ + hh) * W_;
            float v = ok ? row[w] : 0.f;
            float vm = __shfl_up_sync(0xFFFFFFFFu, v, 1);
            float vp = __shfl_down_sync(0xFFFFFFFFu, v, 1);
            if (lane == 0)  vm = (ok && w > 0)      ? row[w - 1] : 0.f;
            if (lane == 31) vp = (ok && w < W_ - 1) ? row[w + 1] : 0.f;
            s0 += wsh[r * 3 + 0] * vm + wsh[r * 3 + 1] * v + wsh[r * 3 + 2] * vp;
            s1 += wsh[9 + r * 3 + 0] * vm + wsh[9 + r * 3 + 1] * v + wsh[9 + r * 3 + 2] * vp;
            s2 += wsh[18 + r * 3 + 0] * vm + wsh[18 + r * 3 + 1] * v + wsh[18 + r * 3 + 2] * vp;
        }
        if (dd + 1 < D_) c[dd + 1] += s0;
        c[dd] += s1;
        if (dd >= 1) c[dd - 1] += s2;
    }

    float m = -1e30f;
#pragma unroll
    for (int d = 0; d < D_; d++) m = fmaxf(m, c[d]);
    float sum = 0.f;
#pragma unroll
    for (int d = 0; d < D_; d++) { c[d] = expf(c[d] - m); sum += c[d]; }
    float invs = 1.f / sum;
    float* op = out + XEL_ + (size_t)b * D_ * HW_ + h * W_ + w;
    float ss1 = 0.f, ss2 = 0.f;
#pragma unroll
    for (int d = 0; d < D_; d++) {
        float v = c[d] * invs;
        op[(size_t)d * HW_] = v;
        ss1 += v; ss2 += v * v;
    }
#pragma unroll
    for (int o = 16; o > 0; o >>= 1) {
        ss1 += __shfl_xor_sync(0xFFFFFFFFu, ss1, o);
        ss2 += __shfl_xor_sync(0xFFFFFFFFu, ss2, o);
    }
    if (lane == 0) { r1[wrp] = ss1; r2[wrp] = ss2; }
    __syncthreads();
    if (threadIdx.x == 0) {
        float t1 = 0.f, t2 = 0.f;
#pragma unroll
        for (int i = 0; i < 10; i++) { t1 += r1[i]; t2 += r2[i]; }
        g_partf[((1 * 2 + b) * 96 + h) * 2 + 0] = t1;
        g_partf[((1 * 2 + b) * 96 + h) * 2 + 1] = t2;
    }
}

// ---------------- combined stats finals (t and c) ----------------
__global__ void k_statsfinal() {
    __shared__ double sh1[128], sh2[128];
    int which = blockIdx.x >> 1, b = blockIdx.x & 1;
    int t = threadIdx.x;
    double s1 = 0.0, s2 = 0.0;
    if (t < 96) {
        s1 = (double)g_partf[((which * 2 + b) * 96 + t) * 2 + 0];
        s2 = (double)g_partf[((which * 2 + b) * 96 + t) * 2 + 1];
    }
    sh1[t] = s1; sh2[t] = s2;
    __syncthreads();
    for (int s = 64; s > 0; s >>= 1) {
        if (t < s) { sh1[t] += sh1[t + s]; sh2[t] += sh2[t + s]; }
        __syncthreads();
    }
    if (t == 0) {
        double N = which ? (double)(D_ * HW_) : (double)(C_ * HW_);
        double mu  = sh1[0] / N;
        double var = sh2[0] / N - mu * mu;
        g_stats[which * 4 + b * 2 + 0] = (float)mu;
        g_stats[which * 4 + b * 2 + 1] = (float)(1.0 / sqrt(var + 1e-5));
    }
}

// ---------------- groupnorms + cost embed + gated fusion -> padded NHWC fp16 (+borders) ----------------
__global__ void __launch_bounds__(256) k_fuse(const float* __restrict__ out_base,
                                              const float* __restrict__ t_feat,
                                              const float* __restrict__ nt_w,
                                              const float* __restrict__ nt_b,
                                              const float* __restrict__ nc_w,
                                              const float* __restrict__ nc_b,
                                              const float* __restrict__ ce_w,
                                              const float* __restrict__ ce_b,
                                              const float* __restrict__ fa_w,
                                              const float* __restrict__ fa_b) {
    __shared__ u64 cep[D_][64];
    __shared__ u64 cebp[64];
    __shared__ float fw[C_], ntw[C_], ntb[C_];
    __shared__ float ncw[D_], ncb[D_], proj[40];

    for (int i = threadIdx.x; i < D_ * 64; i += 256) {
        int d = i >> 6, op = i & 63;
        u64 t; PACK2(t, ce_w[(2 * op) * D_ + d], ce_w[(2 * op + 1) * D_ + d]);
        cep[d][op] = t;
    }
    if (threadIdx.x < 64) {
        u64 t; PACK2(t, ce_b[2 * threadIdx.x], ce_b[2 * threadIdx.x + 1]);
        cebp[threadIdx.x] = t;
    }
    if (threadIdx.x < C_) {
        float f = fa_w[threadIdx.x];
        float w = nt_w[threadIdx.x];
        fw[threadIdx.x]  = f * w;
        ntw[threadIdx.x] = w;
        ntb[threadIdx.x] = nt_b[threadIdx.x];
    }
    if (threadIdx.x < D_) { ncw[threadIdx.x] = nc_w[threadIdx.x]; ncb[threadIdx.x] = nc_b[threadIdx.x]; }
    if (threadIdx.x >= 128 && threadIdx.x < 128 + 40) proj[threadIdx.x - 128] = g_faproj[threadIdx.x - 128];
    __syncthreads();

    int idx = blockIdx.x * 256 + threadIdx.x;
    int b = idx / HW_, pix = idx % HW_;
    int h = pix / W_, w = pix % W_;
    float mu_t = g_stats[b * 2 + 0], inv_t = g_stats[b * 2 + 1];
    float mu_c = g_stats[4 + b * 2 + 0], inv_c = g_stats[4 + b * 2 + 1];

    const float* ncp = out_base + XEL_ + (size_t)b * D_ * HW_ + pix;
    u64 cnp[D_];
    float alin = fa_b[0] + proj[32] + proj[33];
#pragma unroll
    for (int d = 0; d < D_; d++) {
        float v = (ncp[(size_t)d * HW_] - mu_c) * inv_c * ncw[d] + ncb[d];
        PACK2(cnp[d], v, v);
        alin += proj[d] * v;
    }
    const float* tp = t_feat + (size_t)b * C_ * HW_ + pix;
    float dotft = 0.f;
#pragma unroll 4
    for (int c = 0; c < C_; c++) dotft += fw[c] * tp[(size_t)c * HW_];
    alin += inv_t * (dotft - mu_t * proj[34]);

    float alpha = 1.f / (1.f + expf(-alin));
    float om = 1.f - alpha;

    // main padded position + reflected border copies
    size_t pbase = ((size_t)(b * PH_ + h + 1) * PW_ + (w + 1)) * C_;
    size_t bases[4]; int nb = 0;
    bases[nb++] = pbase;
    bool top = (h == 1), bot = (h == H_ - 2);
    bool lef = (w == 1), rig = (w == W_ - 2);
    const size_t ROW2 = 2 * (size_t)PW_ * C_;
    if (top) bases[nb++] = pbase - ROW2;
    if (bot) bases[nb++] = pbase + ROW2;
    if (lef) bases[nb++] = pbase - 2 * C_;
    if (rig) bases[nb++] = pbase + 2 * C_;
    if (top && lef) bases[nb++] = pbase - ROW2 - 2 * C_;
    if (top && rig) bases[nb++] = pbase - ROW2 + 2 * C_;
    if (bot && lef) bases[nb++] = pbase + ROW2 - 2 * C_;
    if (bot && rig) bases[nb++] = pbase + ROW2 + 2 * C_;

    unsigned hq[4];
#pragma unroll 2
    for (int op = 0; op < 64; op++) {
        u64 a2 = cebp[op];
#pragma unroll
        for (int d = 0; d < D_; d++) FMA2(a2, cep[d][op], cnp[d], a2);
        float cf0, cf1; UNPK2(cf0, cf1, a2);
        int o0 = 2 * op, o1 = 2 * op + 1;
        float tv0 = (tp[(size_t)o0 * HW_] - mu_t) * inv_t * ntw[o0] + ntb[o0];
        float tv1 = (tp[(size_t)o1 * HW_] - mu_t) * inv_t * ntw[o1] + ntb[o1];
        float f0 = alpha * tv0 + om * cf0;
        float f1 = alpha * tv1 + om * cf1;
        int grp = op & 3;
        hq[grp] = (unsigned)__half_as_ushort(__float2half_rn(f0)) |
                  ((unsigned)__half_as_ushort(__float2half_rn(f1)) << 16);
        if (grp == 3) {
            int oc8 = 2 * (op - 3);
            uint4 val = make_uint4(hq[0], hq[1], hq[2], hq[3]);
            for (int t = 0; t < nb; t++)
                *reinterpret_cast<uint4*>(&g_phi[bases[t] + oc8]) = val;
        }
    }
}

// ---------------- mma.sync implicit-GEMM conv (fp16, cp.async staging) ----------------
#define A_HI  0
#define B_OFF 23040
#define CONV_SMEM 55808

__global__ void __launch_bounds__(256, 2) k_conv_mma(const float* __restrict__ rc_b,
                                                     float* __restrict__ out) {
    extern __shared__ __align__(128) char smem[];
    uint32_t sb = smem_u32(smem);
    int tid = threadIdx.x, lane = tid & 31, wid = tid >> 5;
    int warp_m = wid & 3, warp_n = wid >> 2;

    int bx = blockIdx.x % 20;
    int by = (blockIdx.x / 20) % 12;
    int b  = blockIdx.x / 240;
    int h0 = by * 8, w0 = bx * 16;
    size_t pbase = ((size_t)(b * PH_ + h0) * PW_ + w0) * C_;

    int m_loc = lane & 15, khalf_a = lane >> 4;
    int rA[2], cA[2];
#pragma unroll
    for (int mt = 0; mt < 2; mt++) {
        int m_abs = warp_m * 32 + mt * 16 + m_loc;
        rA[mt] = m_abs >> 4;
        cA[mt] = m_abs & 15;
    }
    int subB = lane >> 3;
    int nl = (lane & 7) + ((subB & 2) << 2);
    int khalf_b = subB & 1;
    uint32_t bRow[4]; int bSw[4];
#pragma unroll
    for (int nb4 = 0; nb4 < 4; nb4++) {
        int oc = warp_n * 64 + nb4 * 16 + nl;
        bRow[nb4] = (uint32_t)oc * 128;
        bSw[nb4]  = oc & 7;
    }

    float acc[2][8][4];
#pragma unroll
    for (int mt = 0; mt < 2; mt++)
#pragma unroll
        for (int n = 0; n < 8; n++)
#pragma unroll
            for (int e = 0; e < 4; e++) acc[mt][n][e] = 0.f;

    // prefetch B(it=0)
    {
        const uint4* s0 = reinterpret_cast<const uint4*>(g_wH[0]);
#pragma unroll
        for (int j = 0; j < 4; j++) {
            int idx = tid + j * 256;
            CP16(sb + B_OFF + idx * 16, s0 + idx);
        }
        CP_COMMIT();
    }

    for (int it = 0; it < 18; it++) {
        int chunk = it / 9, tap = it % 9, buf = it & 1;
        int dy = tap / 3, dx = tap % 3;
        __syncthreads();

        if (tap == 0) {
            // stage A patch via cp.async (own commit group, before B commit)
            for (int i = tid; i < 1440; i += 256) {
                int row = i >> 3, ch = i & 7;
                int pr = row / 18, pc = row % 18;
                size_t g = pbase + ((size_t)pr * PW_ + pc) * C_ + chunk * 64 + ch * 8;
                uint32_t so = (uint32_t)row * 128 + ((ch ^ (row & 7)) << 4);
                CP16(sb + A_HI + so, &g_phi[g]);
            }
            CP_COMMIT();
        }
        if (it + 1 < 18) {
            const uint4* s0 = reinterpret_cast<const uint4*>(g_wH[it + 1]);
            uint32_t d0 = sb + B_OFF + (buf ^ 1) * 16384;
#pragma unroll
            for (int j = 0; j < 4; j++) {
                int idx = tid + j * 256;
                CP16(d0 + idx * 16, s0 + idx);
            }
        }
        CP_COMMIT();
        CP_WAIT(1);   // B(it) + A(chunk) complete; B(it+1) in flight
        __syncthreads();

        uint32_t bbase = sb + B_OFF + buf * 16384;
        int rowA[2], swA[2];
#pragma unroll
        for (int mt = 0; mt < 2; mt++) {
            rowA[mt] = (rA[mt] + dy) * 18 + cA[mt] + dx;
            swA[mt]  = rowA[mt] & 7;
        }

#pragma unroll
        for (int k16 = 0; k16 < 4; k16++) {
            int chA = k16 * 2 + khalf_a;
            int chB = k16 * 2 + khalf_b;
            uint32_t ah[2][4];
#pragma unroll
            for (int mt = 0; mt < 2; mt++) {
                uint32_t off = (uint32_t)rowA[mt] * 128 + ((chA ^ swA[mt]) << 4);
                ldsm_x4(ah[mt], sb + A_HI + off);
            }
            uint32_t bh[4][4];
#pragma unroll
            for (int nb4 = 0; nb4 < 4; nb4++) {
                uint32_t off = bRow[nb4] + ((chB ^ bSw[nb4]) << 4);
                ldsm_x4(bh[nb4], bbase + off);
            }
#pragma unroll
            for (int mt = 0; mt < 2; mt++) {
#pragma unroll
                for (int nb4 = 0; nb4 < 4; nb4++) {
#pragma unroll
                    for (int half = 0; half < 2; half++) {
                        int n = nb4 * 2 + half;
                        mma16816h(acc[mt][n], ah[mt], bh[nb4][half * 2], bh[nb4][half * 2 + 1]);
                    }
                }
            }
        }
    }

    // epilogue: transpose, store, per-CTA channel sums
    float* sf = reinterpret_cast<float*>(smem);
    int rbase = lane >> 2, cpair = (lane & 3) * 2;
#pragma unroll
    for (int p = 0; p < 2; p++) {
        __syncthreads();
        if (warp_n == p) {
#pragma unroll
            for (int mt = 0; mt < 2; mt++)
#pragma unroll
                for (int nbl = 0; nbl < 8; nbl++)
#pragma unroll
                    for (int e = 0; e < 4; e++) {
                        int m   = warp_m * 32 + mt * 16 + rbase + ((e >> 1) << 3);
                        int ocl = nbl * 8 + cpair + (e & 1);
                        sf[ocl * 132 + m] = acc[mt][nbl][e];
                    }
        }
        __syncthreads();
#pragma unroll
        for (int j = 0; j < 8; j++) {
            int idx = tid + j * 256;
            int ocl = idx >> 5, q = idx & 31;
            int r = q >> 2, cc = (q & 3) * 4;
            float4 v = *reinterpret_cast<const float4*>(&sf[ocl * 132 + r * 16 + cc]);
            int oc = p * 64 + ocl;
            float bias = rc_b[oc];
            v.x += bias; v.y += bias; v.z += bias; v.w += bias;
            *reinterpret_cast<float4*>(&out[(size_t)(b * C_ + oc) * HW_ + (h0 + r) * W_ + w0 + cc]) = v;
            float s = (v.x + v.y) + (v.z + v.w);
#pragma unroll
            for (int o = 16; o > 0; o >>= 1) s += __shfl_xor_sync(0xFFFFFFFFu, s, o);
            if (lane == 0) g_cpart[(size_t)blockIdx.x * 128 + oc] = s;
        }
    }
}

// ---------------- squeeze-excite ----------------
__global__ void __launch_bounds__(1024) k_se2(const float* __restrict__ se_w1,
                                              const float* __restrict__ se_w2) {
    __shared__ float part[4][256];
    __shared__ float mean_s[256];
    __shared__ float y1s[16];
    int tid = threadIdx.x;
    int q = tid >> 8, bc = tid & 255;
    int b = bc >> 7, c = bc & 127;
    float s = 0.f;
    for (int t = q * 60; t < q * 60 + 60; t++)
        s += g_cpart[(size_t)(b * 240 + t) * 128 + c];
    part[q][bc] = s;
    __syncthreads();
    if (tid < 256) {
        float m = part[0][tid] + part[1][tid] + part[2][tid] + part[3][tid];
        mean_s[tid] = m / (float)HW_;
    }
    __syncthreads();
    if (tid < 16) {
        int bb = tid / 8, j = tid % 8;
        float s2 = 0.f;
        for (int cc = 0; cc < C_; cc++) s2 += mean_s[bb * 128 + cc] * se_w1[j * C_ + cc];
        y1s[tid] = fmaxf(s2, 0.f);
    }
    __syncthreads();
    if (tid < 256) {
        int bb = tid >> 7, cc = tid & 127;
        float s3 = 0.f;
#pragma unroll
        for (int j = 0; j < 8; j++) s3 += y1s[bb * 8 + j] * se_w2[cc * 8 + j];
        g_yscale[tid] = 1.f / (1.f + expf(-s3));
    }
}

__global__ void __launch_bounds__(256) k_elu(float* __restrict__ out) {
    int idx = blockIdx.x * 256 + threadIdx.x;
    float v = out[idx] * g_yscale[idx / HW_];
    out[idx] = v > 0.f ? v : expm1f(v);
}

// ---------------- launch ----------------
extern "C" void kernel_launch(void* const* d_in, const int* in_sizes, int n_in,
                              void* d_out, int out_size) {
    const float* t_feat  = (const float*)d_in[0];
    const float* s_feat  = (const float*)d_in[1];
    const float* directs = (const float*)d_in[2];
    const float* disp    = (const float*)d_in[3];
    const float* q_w     = (const float*)d_in[4];
    const float* q_b     = (const float*)d_in[5];
    const float* k_w     = (const float*)d_in[6];
    const float* k_b     = (const float*)d_in[7];
    const float* cf_w    = (const float*)d_in[8];
    const float* nt_w    = (const float*)d_in[10];
    const float* nt_b    = (const float*)d_in[11];
    const float* nc_w    = (const float*)d_in[12];
    const float* nc_b    = (const float*)d_in[13];
    const float* ce_w    = (const float*)d_in[14];
    const float* ce_b    = (const float*)d_in[15];
    const float* fa_w    = (const float*)d_in[16];
    const float* fa_b    = (const float*)d_in[17];
    const float* rc_w    = (const float*)d_in[18];
    const float* rc_b    = (const float*)d_in[19];
    const float* se_w1   = (const float*)d_in[20];
    const float* se_w2   = (const float*)d_in[21];
    float* out = (float*)d_out;

    cudaFuncSetAttribute(k_conv_mma, cudaFuncAttributeMaxDynamicSharedMemorySize, CONV_SMEM);
    cudaFuncSetAttribute(k_simqk, cudaFuncAttributeMaxDynamicSharedMemorySize, SIMQK_SMEM);

    k_prep<<<1, 64>>>(fa_w, ce_w, ce_b, nt_w, nt_b);
    k_prepW<<<18, 256>>>(rc_w);
    k_simqk<<<dim3(H_, B_), W_, SIMQK_SMEM>>>(t_feat, s_feat, q_w, q_b, k_w, k_b, disp, directs);
    k_costsoft<<<dim3(H_, B_), W_>>>(cf_w, out);
    k_statsfinal<<<4, 128>>>();
    k_fuse<<<NPIX_ / 256, 256>>>(out, t_feat, nt_w, nt_b, nc_w, nc_b, ce_w, ce_b, fa_w, fa_b);
    k_conv_mma<<<480, 256, CONV_SMEM>>>(rc_b, out);
    k_se2<<<1, 1024>>>(se_w1, se_w2);
    k_elu<<<XEL_ / 256, 256>>>(out);
}

// round 8
// speedup vs baseline: 3.5178x; 1.0508x over previous
#include <cuda_runtime.h>
#include <cuda_fp16.h>
#include <math.h>
#include <stdint.h>

#define B_   2
#define C_   128
#define H_   96
#define W_   320
#define HW_  30720
#define CQ_  32
#define D_   32
#define NPIX_ (B_*HW_)        // 61440
#define XEL_  (B_*C_*HW_)     // 7864320
#define NCEL_ (B_*D_*HW_)     // 1966080
#define PH_  98
#define PW_  322

typedef unsigned long long u64;

#define FMA2(d,a,b,c) asm("fma.rn.f32x2 %0, %1, %2, %3;" : "=l"(d) : "l"(a), "l"(b), "l"(c))
#define PACK2(d,lo,hi) asm("mov.b64 %0, {%1, %2};" : "=l"(d) : "r"(__float_as_uint(lo)), "r"(__float_as_uint(hi)))
#define UNPK2(lo,hi,s) do { unsigned _a,_b; asm("mov.b64 {%0, %1}, %2;" : "=r"(_a), "=r"(_b) : "l"(s)); lo=__uint_as_float(_a); hi=__uint_as_float(_b); } while(0)

// ---------------- scratch ----------------
__device__ float  g_sim[NCEL_];
__device__ __align__(16) __half g_phi[(size_t)B_*PH_*PW_*C_];
__device__ __align__(16) unsigned short g_wH[18][8192];
__device__ float  g_faproj[40];
__device__ float  g_partf[4*480*2];    // [which*2+b][blk<=480][s1,s2]
__device__ float  g_stats[8];
__device__ float  g_cpart[480*128];
__device__ float  g_yscale[B_*C_];

// ---------------- low-level helpers ----------------
__device__ __forceinline__ uint32_t smem_u32(const void* p) {
    uint32_t a;
    asm("{ .reg .u64 t; cvta.to.shared.u64 t, %1; cvt.u32.u64 %0, t; }" : "=r"(a) : "l"(p));
    return a;
}
#define CP16(sm, gp) asm volatile("cp.async.cg.shared.global [%0], [%1], 16;" :: "r"(sm), "l"(gp) : "memory")
#define CP_COMMIT()  asm volatile("cp.async.commit_group;" ::: "memory")
#define CP_WAIT(n)   asm volatile("cp.async.wait_group %0;" :: "n"(n) : "memory")

__device__ __forceinline__ void ldsm_x4(uint32_t* r, uint32_t addr) {
    asm volatile("ldmatrix.sync.aligned.m8n8.x4.shared.b16 {%0,%1,%2,%3}, [%4];"
        : "=r"(r[0]), "=r"(r[1]), "=r"(r[2]), "=r"(r[3]) : "r"(addr));
}
__device__ __forceinline__ void mma16816h(float* d, const uint32_t* a, uint32_t b0, uint32_t b1) {
    asm volatile("mma.sync.aligned.m16n8k16.row.col.f32.f16.f16.f32 "
        "{%0,%1,%2,%3}, {%4,%5,%6,%7}, {%8,%9}, {%0,%1,%2,%3};"
        : "+f"(d[0]), "+f"(d[1]), "+f"(d[2]), "+f"(d[3])
        : "r"(a[0]), "r"(a[1]), "r"(a[2]), "r"(a[3]), "r"(b0), "r"(b1));
}

// ---------------- tiny weight preprocessing ----------------
__global__ void k_prep(const float* __restrict__ fa_w,
                       const float* __restrict__ ce_w,
                       const float* __restrict__ ce_b,
                       const float* __restrict__ nt_w,
                       const float* __restrict__ nt_b) {
    int t = threadIdx.x;
    if (t < 32) {
        float s = 0.f;
        for (int o = 0; o < C_; o++) s += fa_w[C_ + o] * ce_w[o * D_ + t];
        g_faproj[t] = s;
    } else if (t == 32) {
        float s = 0.f;
        for (int o = 0; o < C_; o++) s += fa_w[C_ + o] * ce_b[o];
        g_faproj[32] = s;
    } else if (t == 33) {
        float s = 0.f;
        for (int c = 0; c < C_; c++) s += fa_w[c] * nt_b[c];
        g_faproj[33] = s;
    } else if (t == 34) {
        float s = 0.f;
        for (int c = 0; c < C_; c++) s += fa_w[c] * nt_w[c];
        g_faproj[34] = s;
    }
}

__global__ void k_prepW(const float* __restrict__ rc_w) {
    int it = blockIdx.x;
    int tap = it % 9, chunk = it / 9;
    for (int idx = threadIdx.x; idx < 8192; idx += 256) {
        int oc = idx >> 6, icl = idx & 63;
        int ic = chunk * 64 + icl;
        float w = rc_w[(oc * C_ + ic) * 9 + tap];
        int pos = oc * 64 + (((icl >> 3) ^ (oc & 7)) << 3) + (icl & 7);
        g_wH[it][pos] = __half_as_ushort(__float2half_rn(w));
    }
}

// ---------------- fused q/k projection + warp + cosine sim + t-stats ----------------
#define SQ_KSH 0
#define SQ_WQ  40960
#define SQ_WK  57344
#define SQ_BQ  73728
#define SQ_BK  73856
#define SQ_R1  73984
#define SQ_R2  74032
#define SIMQK_SMEM 74112

__global__ void __launch_bounds__(W_) k_simqk(const float* __restrict__ t_feat,
                                              const float* __restrict__ s_feat,
                                              const float* __restrict__ q_w,
                                              const float* __restrict__ q_b,
                                              const float* __restrict__ k_w,
                                              const float* __restrict__ k_b,
                                              const float* __restrict__ disp,
                                              const float* __restrict__ directs) {
    extern __shared__ __align__(16) char sm[];
    float* ksh = reinterpret_cast<float*>(sm + SQ_KSH);
    u64*   wq  = reinterpret_cast<u64*>(sm + SQ_WQ);
    u64*   wk  = reinterpret_cast<u64*>(sm + SQ_WK);
    float* bq  = reinterpret_cast<float*>(sm + SQ_BQ);
    float* bk  = reinterpret_cast<float*>(sm + SQ_BK);
    float* r1  = reinterpret_cast<float*>(sm + SQ_R1);
    float* r2  = reinterpret_cast<float*>(sm + SQ_R2);

    int h = blockIdx.x, b = blockIdx.y;
    int w = threadIdx.x, lane = w & 31, wrp = w >> 5;

    for (int i = threadIdx.x; i < C_ * 16; i += W_) {
        int c = i >> 4, op = i & 15;
        u64 t;
        PACK2(t, q_w[(2 * op) * C_ + c], q_w[(2 * op + 1) * C_ + c]);
        wq[i] = t;
        PACK2(t, k_w[(2 * op) * C_ + c], k_w[(2 * op + 1) * C_ + c]);
        wk[i] = t;
    }
    if (threadIdx.x < CQ_) { bq[threadIdx.x] = q_b[threadIdx.x]; bk[threadIdx.x] = k_b[threadIdx.x]; }
    __syncthreads();

    {
        const float* fp = s_feat + (size_t)b * C_ * HW_ + h * W_ + w;
        u64 acc[16];
#pragma unroll
        for (int o = 0; o < 16; o++) acc[o] = 0ULL;
#pragma unroll 4
        for (int c = 0; c < C_; c++) {
            float v = fp[(size_t)c * HW_];
            u64 v2; PACK2(v2, v, v);
#pragma unroll
            for (int op = 0; op < 16; op++) FMA2(acc[op], wk[c * 16 + op], v2, acc[op]);
        }
#pragma unroll
        for (int op = 0; op < 16; op++) {
            float lo, hi; UNPK2(lo, hi, acc[op]);
            ksh[(2 * op) * W_ + w]     = lo + bk[2 * op];
            ksh[(2 * op + 1) * W_ + w] = hi + bk[2 * op + 1];
        }
    }

    float qv[CQ_];
    float s1 = 0.f, s2 = 0.f;
    {
        const float* tp = t_feat + (size_t)b * C_ * HW_ + h * W_ + w;
        u64 acc[16];
#pragma unroll
        for (int o = 0; o < 16; o++) acc[o] = 0ULL;
#pragma unroll 4
        for (int c = 0; c < C_; c++) {
            float v = tp[(size_t)c * HW_];
            s1 += v; s2 += v * v;
            u64 v2; PACK2(v2, v, v);
#pragma unroll
            for (int op = 0; op < 16; op++) FMA2(acc[op], wq[c * 16 + op], v2, acc[op]);
        }
        float n2 = 0.f;
#pragma unroll
        for (int op = 0; op < 16; op++) {
            float lo, hi; UNPK2(lo, hi, acc[op]);
            lo += bq[2 * op]; hi += bq[2 * op + 1];
            qv[2 * op] = lo; qv[2 * op + 1] = hi;
            n2 += lo * lo + hi * hi;
        }
        float inv = 1.f / fmaxf(sqrtf(n2), 1e-12f);
#pragma unroll
        for (int c = 0; c < CQ_; c++) qv[c] *= inv;
    }
    __syncthreads();

    float dir = directs[b];
    float* sp = g_sim + (size_t)b * D_ * HW_ + h * W_ + w;
    for (int d = 0; d < D_; d++) {
        float pos = (float)w + disp[d] * dir * (float)(W_ - 1);
        pos = fminf(fmaxf(pos, 0.f), (float)(W_ - 1));
        int x0 = (int)floorf(pos);
        x0 = min(max(x0, 0), W_ - 1);
        int x1 = min(x0 + 1, W_ - 1);
        float t = pos - (float)x0;
        float dot = 0.f, kn2 = 0.f;
#pragma unroll
        for (int c = 0; c < CQ_; c++) {
            float g = ksh[c * W_ + x0] * (1.f - t) + ksh[c * W_ + x1] * t;
            dot += qv[c] * g;
            kn2 += g * g;
        }
        sp[(size_t)d * HW_] = dot / fmaxf(sqrtf(kn2), 1e-12f);
    }

#pragma unroll
    for (int o = 16; o > 0; o >>= 1) {
        s1 += __shfl_xor_sync(0xFFFFFFFFu, s1, o);
        s2 += __shfl_xor_sync(0xFFFFFFFFu, s2, o);
    }
    if (lane == 0) { r1[wrp] = s1; r2[wrp] = s2; }
    __syncthreads();
    if (threadIdx.x == 0) {
        float t1 = 0.f, t2 = 0.f;
#pragma unroll
        for (int i = 0; i < 10; i++) { t1 += r1[i]; t2 += r2[i]; }
        g_partf[((0 * 2 + b) * 480 + h) * 2 + 0] = t1;
        g_partf[((0 * 2 + b) * 480 + h) * 2 + 1] = t2;
    }
}

// ---------------- fused cost filter + softmax + c-stats (w-tiled, d-split) ----------------
template<int Y>
__device__ __forceinline__ void cost_half(float* cl, const float* __restrict__ base,
                                          const float* __restrict__ wsh,
                                          int h, int w, int lane) {
#pragma unroll
    for (int j = 0; j < 17; j++) {
        const int dd = Y ? (15 + j) : j;
        const int t  = Y ? (j - 1) : j;
        float s0 = 0.f, s1 = 0.f, s2 = 0.f;
#pragma unroll
        for (int r = 0; r < 3; r++) {
            int hh = h + r - 1;
            bool ok = (hh >= 0) && (hh < H_);
            const float* row = base + ((size_t)dd * H_ + hh) * W_;
            float v = ok ? row[w] : 0.f;
            float vm = __shfl_up_sync(0xFFFFFFFFu, v, 1);
            float vp = __shfl_down_sync(0xFFFFFFFFu, v, 1);
            if (lane == 0)  vm = (ok && w > 0)      ? row[w - 1] : 0.f;
            if (lane == 31) vp = (ok && w < W_ - 1) ? row[w + 1] : 0.f;
            s0 += wsh[r * 3 + 0] * vm + wsh[r * 3 + 1] * v + wsh[r * 3 + 2] * vp;
            s1 += wsh[9 + r * 3 + 0] * vm + wsh[9 + r * 3 + 1] * v + wsh[9 + r * 3 + 2] * vp;
            s2 += wsh[18 + r * 3 + 0] * vm + wsh[18 + r * 3 + 1] * v + wsh[18 + r * 3 + 2] * vp;
        }
        if (t + 1 >= 0 && t + 1 < 16 && dd + 1 < D_) cl[t + 1] += s0;
        if (t >= 0 && t < 16)                        cl[t]     += s1;
        if (t - 1 >= 0 && t - 1 < 16)                cl[t - 1] += s2;
    }
}

__global__ void __launch_bounds__(128) k_costsoft(const float* __restrict__ cf_w,
                                                  float* __restrict__ out) {
    __shared__ float wsh[27];
    __shared__ float mx[2][64], sms[2][64];
    __shared__ float r1s[4], r2s[4];
    int h = blockIdx.x / 5, tile = blockIdx.x % 5, b = blockIdx.y;
    int wl = threadIdx.x, y = threadIdx.y;
    int w = tile * 64 + wl;
    int tid = y * 64 + wl;
    int lane = wl & 31;
    if (tid < 27) wsh[tid] = cf_w[tid];
    __syncthreads();

    const float* base = g_sim + (size_t)b * D_ * HW_;
    float cl[16];
#pragma unroll
    for (int j = 0; j < 16; j++) cl[j] = 0.f;
    if (y == 0) cost_half<0>(cl, base, wsh, h, w, lane);
    else        cost_half<1>(cl, base, wsh, h, w, lane);

    float m = -1e30f;
#pragma unroll
    for (int j = 0; j < 16; j++) m = fmaxf(m, cl[j]);
    mx[y][wl] = m;
    __syncthreads();
    m = fmaxf(mx[0][wl], mx[1][wl]);
    float sum = 0.f;
#pragma unroll
    for (int j = 0; j < 16; j++) { cl[j] = expf(cl[j] - m); sum += cl[j]; }
    sms[y][wl] = sum;
    __syncthreads();
    float invs = 1.f / (sms[0][wl] + sms[1][wl]);

    int d0 = y * 16;
    float* op = out + XEL_ + (size_t)b * D_ * HW_ + (size_t)d0 * HW_ + h * W_ + w;
    float ss1 = 0.f, ss2 = 0.f;
#pragma unroll
    for (int j = 0; j < 16; j++) {
        float v = cl[j] * invs;
        op[(size_t)j * HW_] = v;
        ss1 += v; ss2 += v * v;
    }
#pragma unroll
    for (int o = 16; o > 0; o >>= 1) {
        ss1 += __shfl_xor_sync(0xFFFFFFFFu, ss1, o);
        ss2 += __shfl_xor_sync(0xFFFFFFFFu, ss2, o);
    }
    if (lane == 0) { r1s[tid >> 5] = ss1; r2s[tid >> 5] = ss2; }
    __syncthreads();
    if (tid == 0) {
        float t1 = r1s[0] + r1s[1] + r1s[2] + r1s[3];
        float t2 = r2s[0] + r2s[1] + r2s[2] + r2s[3];
        g_partf[((1 * 2 + b) * 480 + h * 5 + tile) * 2 + 0] = t1;
        g_partf[((1 * 2 + b) * 480 + h * 5 + tile) * 2 + 1] = t2;
    }
}

// ---------------- combined stats finals ----------------
__global__ void __launch_bounds__(512) k_statsfinal() {
    __shared__ double sh1[512], sh2[512];
    int which = blockIdx.x >> 1, b = blockIdx.x & 1;
    int n = which ? 480 : 96;
    int t = threadIdx.x;
    double s1 = 0.0, s2 = 0.0;
    if (t < n) {
        s1 = (double)g_partf[((which * 2 + b) * 480 + t) * 2 + 0];
        s2 = (double)g_partf[((which * 2 + b) * 480 + t) * 2 + 1];
    }
    sh1[t] = s1; sh2[t] = s2;
    __syncthreads();
    for (int s = 256; s > 0; s >>= 1) {
        if (t < s) { sh1[t] += sh1[t + s]; sh2[t] += sh2[t + s]; }
        __syncthreads();
    }
    if (t == 0) {
        double N = which ? (double)(D_ * HW_) : (double)(C_ * HW_);
        double mu  = sh1[0] / N;
        double var = sh2[0] / N - mu * mu;
        g_stats[which * 4 + b * 2 + 0] = (float)mu;
        g_stats[which * 4 + b * 2 + 1] = (float)(1.0 / sqrt(var + 1e-5));
    }
}

// ---------------- groupnorms + cost embed + gated fusion -> padded NHWC fp16 (+borders) ----------------
__global__ void __launch_bounds__(256) k_fuse(const float* __restrict__ out_base,
                                              const float* __restrict__ t_feat,
                                              const float* __restrict__ nt_w,
                                              const float* __restrict__ nt_b,
                                              const float* __restrict__ nc_w,
                                              const float* __restrict__ nc_b,
                                              const float* __restrict__ ce_w,
                                              const float* __restrict__ ce_b,
                                              const float* __restrict__ fa_w,
                                              const float* __restrict__ fa_b) {
    __shared__ u64 cep[D_][64];
    __shared__ u64 cebp[64];
    __shared__ float fw[C_], ntw[C_], ntb[C_];
    __shared__ float ncw[D_], ncb[D_], proj[40];

    for (int i = threadIdx.x; i < D_ * 64; i += 256) {
        int d = i >> 6, op = i & 63;
        u64 t; PACK2(t, ce_w[(2 * op) * D_ + d], ce_w[(2 * op + 1) * D_ + d]);
        cep[d][op] = t;
    }
    if (threadIdx.x < 64) {
        u64 t; PACK2(t, ce_b[2 * threadIdx.x], ce_b[2 * threadIdx.x + 1]);
        cebp[threadIdx.x] = t;
    }
    if (threadIdx.x < C_) {
        float f = fa_w[threadIdx.x];
        float w = nt_w[threadIdx.x];
        fw[threadIdx.x]  = f * w;
        ntw[threadIdx.x] = w;
        ntb[threadIdx.x] = nt_b[threadIdx.x];
    }
    if (threadIdx.x < D_) { ncw[threadIdx.x] = nc_w[threadIdx.x]; ncb[threadIdx.x] = nc_b[threadIdx.x]; }
    if (threadIdx.x >= 128 && threadIdx.x < 128 + 40) proj[threadIdx.x - 128] = g_faproj[threadIdx.x - 128];
    __syncthreads();

    int idx = blockIdx.x * 256 + threadIdx.x;
    int b = idx / HW_, pix = idx % HW_;
    int h = pix / W_, w = pix % W_;
    float mu_t = g_stats[b * 2 + 0], inv_t = g_stats[b * 2 + 1];
    float mu_c = g_stats[4 + b * 2 + 0], inv_c = g_stats[4 + b * 2 + 1];

    const float* ncp = out_base + XEL_ + (size_t)b * D_ * HW_ + pix;
    u64 cnp[D_];
    float alin = fa_b[0] + proj[32] + proj[33];
#pragma unroll
    for (int d = 0; d < D_; d++) {
        float v = (ncp[(size_t)d * HW_] - mu_c) * inv_c * ncw[d] + ncb[d];
        PACK2(cnp[d], v, v);
        alin += proj[d] * v;
    }
    const float* tp = t_feat + (size_t)b * C_ * HW_ + pix;
    float dotft = 0.f;
#pragma unroll 4
    for (int c = 0; c < C_; c++) dotft += fw[c] * tp[(size_t)c * HW_];
    alin += inv_t * (dotft - mu_t * proj[34]);

    float alpha = 1.f / (1.f + expf(-alin));
    float om = 1.f - alpha;

    size_t pbase = ((size_t)(b * PH_ + h + 1) * PW_ + (w + 1)) * C_;
    size_t bases[4]; int nb = 0;
    bases[nb++] = pbase;
    bool top = (h == 1), bot = (h == H_ - 2);
    bool lef = (w == 1), rig = (w == W_ - 2);
    const size_t ROW2 = 2 * (size_t)PW_ * C_;
    if (top) bases[nb++] = pbase - ROW2;
    if (bot) bases[nb++] = pbase + ROW2;
    if (lef) bases[nb++] = pbase - 2 * C_;
    if (rig) bases[nb++] = pbase + 2 * C_;
    if (top && lef) bases[nb++] = pbase - ROW2 - 2 * C_;
    if (top && rig) bases[nb++] = pbase - ROW2 + 2 * C_;
    if (bot && lef) bases[nb++] = pbase + ROW2 - 2 * C_;
    if (bot && rig) bases[nb++] = pbase + ROW2 + 2 * C_;

    unsigned hq[4];
#pragma unroll 2
    for (int op = 0; op < 64; op++) {
        u64 a2 = cebp[op];
#pragma unroll
        for (int d = 0; d < D_; d++) FMA2(a2, cep[d][op], cnp[d], a2);
        float cf0, cf1; UNPK2(cf0, cf1, a2);
        int o0 = 2 * op, o1 = 2 * op + 1;
        float tv0 = (tp[(size_t)o0 * HW_] - mu_t) * inv_t * ntw[o0] + ntb[o0];
        float tv1 = (tp[(size_t)o1 * HW_] - mu_t) * inv_t * ntw[o1] + ntb[o1];
        float f0 = alpha * tv0 + om * cf0;
        float f1 = alpha * tv1 + om * cf1;
        int grp = op & 3;
        hq[grp] = (unsigned)__half_as_ushort(__float2half_rn(f0)) |
                  ((unsigned)__half_as_ushort(__float2half_rn(f1)) << 16);
        if (grp == 3) {
            int oc8 = 2 * (op - 3);
            uint4 val = make_uint4(hq[0], hq[1], hq[2], hq[3]);
            for (int t = 0; t < nb; t++)
                *reinterpret_cast<uint4*>(&g_phi[bases[t] + oc8]) = val;
        }
    }
}

// ---------------- mma.sync implicit-GEMM conv (fp16, cp.async staging) ----------------
#define A_HI  0
#define B_OFF 23040
#define CONV_SMEM 55808

__global__ void __launch_bounds__(256, 2) k_conv_mma(const float* __restrict__ rc_b,
                                                     float* __restrict__ out) {
    extern __shared__ __align__(128) char smem[];
    uint32_t sb = smem_u32(smem);
    int tid = threadIdx.x, lane = tid & 31, wid = tid >> 5;
    int warp_m = wid & 3, warp_n = wid >> 2;

    int bx = blockIdx.x % 20;
    int by = (blockIdx.x / 20) % 12;
    int b  = blockIdx.x / 240;
    int h0 = by * 8, w0 = bx * 16;
    size_t pbase = ((size_t)(b * PH_ + h0) * PW_ + w0) * C_;

    int m_loc = lane & 15, khalf_a = lane >> 4;
    int rA[2], cA[2];
#pragma unroll
    for (int mt = 0; mt < 2; mt++) {
        int m_abs = warp_m * 32 + mt * 16 + m_loc;
        rA[mt] = m_abs >> 4;
        cA[mt] = m_abs & 15;
    }
    int subB = lane >> 3;
    int nl = (lane & 7) + ((subB & 2) << 2);
    int khalf_b = subB & 1;
    uint32_t bRow[4]; int bSw[4];
#pragma unroll
    for (int nb4 = 0; nb4 < 4; nb4++) {
        int oc = warp_n * 64 + nb4 * 16 + nl;
        bRow[nb4] = (uint32_t)oc * 128;
        bSw[nb4]  = oc & 7;
    }

    float acc[2][8][4];
#pragma unroll
    for (int mt = 0; mt < 2; mt++)
#pragma unroll
        for (int n = 0; n < 8; n++)
#pragma unroll
            for (int e = 0; e < 4; e++) acc[mt][n][e] = 0.f;

    {
        const uint4* s0 = reinterpret_cast<const uint4*>(g_wH[0]);
#pragma unroll
        for (int j = 0; j < 4; j++) {
            int idx = tid + j * 256;
            CP16(sb + B_OFF + idx * 16, s0 + idx);
        }
        CP_COMMIT();
    }

    for (int it = 0; it < 18; it++) {
        int chunk = it / 9, tap = it % 9, buf = it & 1;
        int dy = tap / 3, dx = tap % 3;
        __syncthreads();

        if (tap == 0) {
            for (int i = tid; i < 1440; i += 256) {
                int row = i >> 3, ch = i & 7;
                int pr = row / 18, pc = row % 18;
                size_t g = pbase + ((size_t)pr * PW_ + pc) * C_ + chunk * 64 + ch * 8;
                uint32_t so = (uint32_t)row * 128 + ((ch ^ (row & 7)) << 4);
                CP16(sb + A_HI + so, &g_phi[g]);
            }
            CP_COMMIT();
        }
        if (it + 1 < 18) {
            const uint4* s0 = reinterpret_cast<const uint4*>(g_wH[it + 1]);
            uint32_t d0 = sb + B_OFF + (buf ^ 1) * 16384;
#pragma unroll
            for (int j = 0; j < 4; j++) {
                int idx = tid + j * 256;
                CP16(d0 + idx * 16, s0 + idx);
            }
        }
        CP_COMMIT();
        CP_WAIT(1);
        __syncthreads();

        uint32_t bbase = sb + B_OFF + buf * 16384;
        int rowA[2], swA[2];
#pragma unroll
        for (int mt = 0; mt < 2; mt++) {
            rowA[mt] = (rA[mt] + dy) * 18 + cA[mt] + dx;
            swA[mt]  = rowA[mt] & 7;
        }

#pragma unroll
        for (int k16 = 0; k16 < 4; k16++) {
            int chA = k16 * 2 + khalf_a;
            int chB = k16 * 2 + khalf_b;
            uint32_t ah[2][4];
#pragma unroll
            for (int mt = 0; mt < 2; mt++) {
                uint32_t off = (uint32_t)rowA[mt] * 128 + ((chA ^ swA[mt]) << 4);
                ldsm_x4(ah[mt], sb + A_HI + off);
            }
            uint32_t bh[4][4];
#pragma unroll
            for (int nb4 = 0; nb4 < 4; nb4++) {
                uint32_t off = bRow[nb4] + ((chB ^ bSw[nb4]) << 4);
                ldsm_x4(bh[nb4], bbase + off);
            }
#pragma unroll
            for (int mt = 0; mt < 2; mt++) {
#pragma unroll
                for (int nb4 = 0; nb4 < 4; nb4++) {
#pragma unroll
                    for (int half = 0; half < 2; half++) {
                        int n = nb4 * 2 + half;
                        mma16816h(acc[mt][n], ah[mt], bh[nb4][half * 2], bh[nb4][half * 2 + 1]);
                    }
                }
            }
        }
    }

    float* sf = reinterpret_cast<float*>(smem);
    int rbase = lane >> 2, cpair = (lane & 3) * 2;
#pragma unroll
    for (int p = 0; p < 2; p++) {
        __syncthreads();
        if (warp_n == p) {
#pragma unroll
            for (int mt = 0; mt < 2; mt++)
#pragma unroll
                for (int nbl = 0; nbl < 8; nbl++)
#pragma unroll
                    for (int e = 0; e < 4; e++) {
                        int m   = warp_m * 32 + mt * 16 + rbase + ((e >> 1) << 3);
                        int ocl = nbl * 8 + cpair + (e & 1);
                        sf[ocl * 132 + m] = acc[mt][nbl][e];
                    }
        }
        __syncthreads();
#pragma unroll
        for (int j = 0; j < 8; j++) {
            int idx = tid + j * 256;
            int ocl = idx >> 5, q = idx & 31;
            int r = q >> 2, cc = (q & 3) * 4;
            float4 v = *reinterpret_cast<const float4*>(&sf[ocl * 132 + r * 16 + cc]);
            int oc = p * 64 + ocl;
            float bias = rc_b[oc];
            v.x += bias; v.y += bias; v.z += bias; v.w += bias;
            *reinterpret_cast<float4*>(&out[(size_t)(b * C_ + oc) * HW_ + (h0 + r) * W_ + w0 + cc]) = v;
            float s = (v.x + v.y) + (v.z + v.w);
#pragma unroll
            for (int o = 16; o > 0; o >>= 1) s += __shfl_xor_sync(0xFFFFFFFFu, s, o);
            if (lane == 0) g_cpart[(size_t)blockIdx.x * 128 + oc] = s;
        }
    }
}

// ---------------- squeeze-excite ----------------
__global__ void __launch_bounds__(1024) k_se2(const float* __restrict__ se_w1,
                                              const float* __restrict__ se_w2) {
    __shared__ float part[4][256];
    __shared__ float mean_s[256];
    __shared__ float y1s[16];
    int tid = threadIdx.x;
    int q = tid >> 8, bc = tid & 255;
    int b = bc >> 7, c = bc & 127;
    float s = 0.f;
    for (int t = q * 60; t < q * 60 + 60; t++)
        s += g_cpart[(size_t)(b * 240 + t) * 128 + c];
    part[q][bc] = s;
    __syncthreads();
    if (tid < 256) {
        float m = part[0][tid] + part[1][tid] + part[2][tid] + part[3][tid];
        mean_s[tid] = m / (float)HW_;
    }
    __syncthreads();
    if (tid < 16) {
        int bb = tid / 8, j = tid % 8;
        float s2 = 0.f;
        for (int cc = 0; cc < C_; cc++) s2 += mean_s[bb * 128 + cc] * se_w1[j * C_ + cc];
        y1s[tid] = fmaxf(s2, 0.f);
    }
    __syncthreads();
    if (tid < 256) {
        int bb = tid >> 7, cc = tid & 127;
        float s3 = 0.f;
#pragma unroll
        for (int j = 0; j < 8; j++) s3 += y1s[bb * 8 + j] * se_w2[cc * 8 + j];
        g_yscale[tid] = 1.f / (1.f + expf(-s3));
    }
}

__global__ void __launch_bounds__(256) k_elu(float* __restrict__ out) {
    int idx4 = blockIdx.x * 256 + threadIdx.x;
    float ysc = g_yscale[(idx4 * 4) / HW_];
    float4 v = reinterpret_cast<float4*>(out)[idx4];
    v.x *= ysc; v.y *= ysc; v.z *= ysc; v.w *= ysc;
    v.x = v.x > 0.f ? v.x : expm1f(v.x);
    v.y = v.y > 0.f ? v.y : expm1f(v.y);
    v.z = v.z > 0.f ? v.z : expm1f(v.z);
    v.w = v.w > 0.f ? v.w : expm1f(v.w);
    reinterpret_cast<float4*>(out)[idx4] = v;
}

// ---------------- launch ----------------
extern "C" void kernel_launch(void* const* d_in, const int* in_sizes, int n_in,
                              void* d_out, int out_size) {
    const float* t_feat  = (const float*)d_in[0];
    const float* s_feat  = (const float*)d_in[1];
    const float* directs = (const float*)d_in[2];
    const float* disp    = (const float*)d_in[3];
    const float* q_w     = (const float*)d_in[4];
    const float* q_b     = (const float*)d_in[5];
    const float* k_w     = (const float*)d_in[6];
    const float* k_b     = (const float*)d_in[7];
    const float* cf_w    = (const float*)d_in[8];
    const float* nt_w    = (const float*)d_in[10];
    const float* nt_b    = (const float*)d_in[11];
    const float* nc_w    = (const float*)d_in[12];
    const float* nc_b    = (const float*)d_in[13];
    const float* ce_w    = (const float*)d_in[14];
    const float* ce_b    = (const float*)d_in[15];
    const float* fa_w    = (const float*)d_in[16];
    const float* fa_b    = (const float*)d_in[17];
    const float* rc_w    = (const float*)d_in[18];
    const float* rc_b    = (const float*)d_in[19];
    const float* se_w1   = (const float*)d_in[20];
    const float* se_w2   = (const float*)d_in[21];
    float* out = (float*)d_out;

    cudaFuncSetAttribute(k_conv_mma, cudaFuncAttributeMaxDynamicSharedMemorySize, CONV_SMEM);
    cudaFuncSetAttribute(k_simqk, cudaFuncAttributeMaxDynamicSharedMemorySize, SIMQK_SMEM);

    k_prep<<<1, 64>>>(fa_w, ce_w, ce_b, nt_w, nt_b);
    k_prepW<<<18, 256>>>(rc_w);
    k_simqk<<<dim3(H_, B_), W_, SIMQK_SMEM>>>(t_feat, s_feat, q_w, q_b, k_w, k_b, disp, directs);
    k_costsoft<<<dim3(H_ * 5, B_), dim3(64, 2)>>>(cf_w, out);
    k_statsfinal<<<4, 512>>>();
    k_fuse<<<NPIX_ / 256, 256>>>(out, t_feat, nt_w, nt_b, nc_w, nc_b, ce_w, ce_b, fa_w, fa_b);
    k_conv_mma<<<480, 256, CONV_SMEM>>>(rc_b, out);
    k_se2<<<1, 1024>>>(se_w1, se_w2);
    k_elu<<<XEL_ / 1024, 256>>>(out);
}